// round 6
// baseline (speedup 1.0000x reference)
#include <cuda_runtime.h>
#include <cuda_bf16.h>
#include <cstdint>

// ---------------------------------------------------------------------------
// GPUManifoldFeatureEncoder — round 6:
//   * occupancy: 224 thr/block, 3 blocks/SM (smem 69.3KB via buffer aliasing,
//     1024-entry gelu LUT), __launch_bounds__(224,3)
//   * bias folded into MMA accumulator init
//   * tf32 2-term MMA, packed gather, BN fold, float4 RED scatter (unchanged)
// ---------------------------------------------------------------------------

#define MAX_N 131072
typedef uint32_t u32;

__device__ float  g_nodepack[MAX_N * 8];    // x,y,z,nx | ny,nz,c0,c1
__device__ float  g_node_acc[MAX_N * 16];
__device__ float  g_degree[MAX_N];
__device__ double g_esum[16], g_esq[16];
__device__ double g_nsum[16], g_nsq[16];
__device__ float  g_es[16], g_et[16];
__device__ float  g_ns[16], g_nt[16];

__device__ __forceinline__ float gelu_exact(float x) {
    return 0.5f * x * (1.0f + erff(x * 0.70710678118654752440f));
}
__device__ __forceinline__ u32 tf32_of(float x) {
    u32 r; asm("cvt.rna.tf32.f32 %0, %1;" : "=r"(r) : "f"(x)); return r;
}
__device__ __forceinline__ void split_tf32(float x, u32& hi, u32& lo) {
    asm("cvt.rna.tf32.f32 %0, %1;" : "=r"(hi) : "f"(x));
    float rem = x - __uint_as_float(hi);
    asm("cvt.rna.tf32.f32 %0, %1;" : "=r"(lo) : "f"(rem));
}
__device__ __forceinline__ void mma_tf32(float& d0, float& d1, float& d2, float& d3,
                                         u32 a0, u32 a1, u32 a2, u32 a3,
                                         u32 b0, u32 b1) {
    asm("mma.sync.aligned.m16n8k8.row.col.f32.tf32.tf32.f32 "
        "{%0,%1,%2,%3}, {%4,%5,%6,%7}, {%8,%9}, {%0,%1,%2,%3};"
        : "+f"(d0), "+f"(d1), "+f"(d2), "+f"(d3)
        : "r"(a0), "r"(a1), "r"(a2), "r"(a3), "r"(b0), "r"(b1));
}

// ---------------------------------------------------------------------------
__global__ void k_zero(int N) {
    int i = blockIdx.x * blockDim.x + threadIdx.x;
    int tot = N * 16;
    if (i < tot) g_node_acc[i] = 0.0f;
    if (i < N)   g_degree[i]   = 0.0f;
    if (i < 16) {
        g_esum[i] = 0.0; g_esq[i] = 0.0;
        g_nsum[i] = 0.0; g_nsq[i] = 0.0;
    }
}

__global__ void k_pack(const float* __restrict__ coords,
                       const float* __restrict__ normals,
                       const float* __restrict__ curv, int N)
{
    int n = blockIdx.x * blockDim.x + threadIdx.x;
    if (n < N) {
        float4 a = make_float4(coords[3*n+0], coords[3*n+1], coords[3*n+2],
                               normals[3*n+0]);
        float4 b = make_float4(normals[3*n+1], normals[3*n+2],
                               curv[4*n+0], curv[4*n+1]);
        *reinterpret_cast<float4*>(&g_nodepack[8*n])     = a;
        *reinterpret_cast<float4*>(&g_nodepack[8*n + 4]) = b;
    }
}

// ---------------------------------------------------------------------------
// smem (floats): W1f[1024] W2f[4096] W3f[1024] biases[128] lut[2048]
//   per-warp: efs[256], hbuf[1088]  (h1 = hbuf; h2 aliases hbuf[0..576);
//   outs aliases hbuf[576..896))
// ---------------------------------------------------------------------------
#define OFF_W1   0
#define OFF_W2   1024
#define OFF_W3   5120
#define OFF_B1   6144
#define OFF_B2   6208
#define OFF_B3   6240
#define OFF_LUT  6272
#define OFF_WARP 8320
#define WARP_FLOATS 1344
#define H1_PAD 68
#define H2_PAD 36
#define OUT_PAD 20
#define NWARP 7
#define NTHR  224

__global__ __launch_bounds__(NTHR, 3)
void k_edge(const int* __restrict__ rowi,
            const int* __restrict__ coli,
            const float* __restrict__ W1, const float* __restrict__ b1,
            const float* __restrict__ W2, const float* __restrict__ b2,
            const float* __restrict__ W3, const float* __restrict__ b3,
            int E, int N)
{
    extern __shared__ float sm[];
    float4* sW1f = reinterpret_cast<float4*>(sm + OFF_W1);
    float4* sW2f = reinterpret_cast<float4*>(sm + OFF_W2);
    float4* sW3f = reinterpret_cast<float4*>(sm + OFF_W3);
    float*  sb1  = sm + OFF_B1;
    float*  sb2  = sm + OFF_B2;
    float*  sb3  = sm + OFF_B3;
    float2* slut = reinterpret_cast<float2*>(sm + OFF_LUT);

    const int tid  = threadIdx.x;
    const int lane = tid & 31;
    const int wid  = tid >> 5;
    const int g    = lane >> 2;
    const int j    = lane & 3;

    // ---- preamble ----
    for (int idx = tid; idx < 8 * 32; idx += NTHR) {       // W1
        int nt = idx >> 5, t = idx & 31;
        int kk = t & 3, nn = nt * 8 + (t >> 2);
        float w0 = W1[kk * 64 + nn], w1 = W1[(kk + 4) * 64 + nn];
        u32 h0, l0, h1_, l1; split_tf32(w0, h0, l0); split_tf32(w1, h1_, l1);
        sW1f[idx] = make_float4(__uint_as_float(h0), __uint_as_float(h1_),
                                __uint_as_float(l0), __uint_as_float(l1));
    }
    for (int idx = tid; idx < 32 * 32; idx += NTHR) {      // W2
        int combo = idx >> 5, t = idx & 31;
        int ks = combo >> 2, nt = combo & 3;
        int kk = ks * 8 + (t & 3), nn = nt * 8 + (t >> 2);
        float w0 = W2[kk * 32 + nn], w1 = W2[(kk + 4) * 32 + nn];
        u32 h0, l0, h1_, l1; split_tf32(w0, h0, l0); split_tf32(w1, h1_, l1);
        sW2f[idx] = make_float4(__uint_as_float(h0), __uint_as_float(h1_),
                                __uint_as_float(l0), __uint_as_float(l1));
    }
    for (int idx = tid; idx < 8 * 32; idx += NTHR) {       // W3
        int combo = idx >> 5, t = idx & 31;
        int ks = combo >> 1, nt = combo & 1;
        int kk = ks * 8 + (t & 3), nn = nt * 8 + (t >> 2);
        float w0 = W3[kk * 16 + nn], w1 = W3[(kk + 4) * 16 + nn];
        u32 h0, l0, h1_, l1; split_tf32(w0, h0, l0); split_tf32(w1, h1_, l1);
        sW3f[idx] = make_float4(__uint_as_float(h0), __uint_as_float(h1_),
                                __uint_as_float(l0), __uint_as_float(l1));
    }
    if (tid < 64) sb1[tid] = b1[tid];
    if (tid < 32) sb2[tid] = b2[tid];
    if (tid < 16) sb3[tid] = b3[tid];
    // gelu LUT: 1024 entries over [-8,8), step 1/64
    for (int i = tid; i < 1024; i += NTHR) {
        float x0 = (float)(i - 512) * 0.015625f;
        float g0 = gelu_exact(x0);
        slut[i] = make_float2(g0, gelu_exact(x0 + 0.015625f) - g0);
    }
    __syncthreads();

    float* efs  = sm + OFF_WARP + wid * WARP_FLOATS;  // [32][8]
    float* h1s  = efs + 256;                          // [16][68]
    float* h2s  = h1s;                                // alias [16][36]
    float* outs = h1s + 576;                          // alias [16][20]
    float4* outs4 = reinterpret_cast<float4*>(outs);

    float lsum4[4] = {0, 0, 0, 0}, lsq4[4] = {0, 0, 0, 0};

    const int tiles32 = (E + 31) >> 5;
    const int warpsTotal = gridDim.x * NWARP;
    const int warpGlobal = blockIdx.x * NWARP + wid;

    for (int tb32 = warpGlobal; tb32 < tiles32; tb32 += warpsTotal) {
        const int ebase = tb32 << 5;
        const int e = ebase + lane;
        const bool ev = (e < E);

        int r = ev ? rowi[e] : 0;
        int c = ev ? coli[e] : 0;
        if ((unsigned)r >= (unsigned)N) r = 0;
        if ((unsigned)c >= (unsigned)N) c = 0;

        {   // gather: 2x LDG.128 per endpoint
            const float4 ra = *reinterpret_cast<const float4*>(&g_nodepack[8*r]);
            const float4 rb = *reinterpret_cast<const float4*>(&g_nodepack[8*r+4]);
            const float4 ca = *reinterpret_cast<const float4*>(&g_nodepack[8*c]);
            const float4 cb = *reinterpret_cast<const float4*>(&g_nodepack[8*c+4]);

            const float dx = ca.x - ra.x, dy = ca.y - ra.y, dz = ca.z - ra.z;
            const float nrx = ra.w, nry = rb.x, nrz = rb.y;
            const float ncx = ca.w, ncy = cb.x, ncz = cb.y;
            const float ndot = nrx*ncx + nry*ncy + nrz*ncz;
            const float dn = sqrtf(dx*dx + dy*dy + dz*dz) + 1e-8f;
            const float inv = 1.0f / dn;
            float cr = fminf(1.0f, fmaxf(-1.0f, (nrx*dx+nry*dy+nrz*dz)*inv));
            float cc = fminf(1.0f, fmaxf(-1.0f, (ncx*dx+ncy*dy+ncz*dz)*inv));
            float* er = efs + lane * 8;
            er[0] = dx; er[1] = dy; er[2] = dz; er[3] = ndot;
            er[4] = cr; er[5] = cc;
            er[6] = cb.z - rb.z;
            er[7] = cb.w - rb.w;
        }
        __syncwarp();

#pragma unroll
        for (int t = 0; t < 2; t++) {
            const int tb = ebase + t * 16;

            // Layer 1: [16,8] @ [8,64], bias in accumulator init
            u32 a4[4];
            {
                const float* base = efs + t * 128;
                a4[0] = tf32_of(base[(g    )*8 + j    ]);
                a4[1] = tf32_of(base[(g + 8)*8 + j    ]);
                a4[2] = tf32_of(base[(g    )*8 + j + 4]);
                a4[3] = tf32_of(base[(g + 8)*8 + j + 4]);
            }
            float d1v[8][4];
#pragma unroll
            for (int nt = 0; nt < 8; nt++) {
                const float2 bb = *reinterpret_cast<const float2*>(
                    sb1 + nt * 8 + 2 * j);
                d1v[nt][0] = bb.x; d1v[nt][1] = bb.y;
                d1v[nt][2] = bb.x; d1v[nt][3] = bb.y;
                float4 bw = sW1f[nt * 32 + lane];
                mma_tf32(d1v[nt][0], d1v[nt][1], d1v[nt][2], d1v[nt][3],
                         a4[0], a4[1], a4[2], a4[3],
                         __float_as_uint(bw.x), __float_as_uint(bw.y));
                mma_tf32(d1v[nt][0], d1v[nt][1], d1v[nt][2], d1v[nt][3],
                         a4[0], a4[1], a4[2], a4[3],
                         __float_as_uint(bw.z), __float_as_uint(bw.w));
            }
#pragma unroll
            for (int nt = 0; nt < 8; nt++) {
                const int cb = nt * 8 + 2 * j;
#pragma unroll
                for (int hrow = 0; hrow < 2; hrow++) {
                    float v0 = d1v[nt][2*hrow];
                    float v1 = d1v[nt][2*hrow + 1];
                    float t0 = fminf(fmaxf(fmaf(v0, 64.0f, 512.0f), 0.0f), 1022.999f);
                    float t1 = fminf(fmaxf(fmaf(v1, 64.0f, 512.0f), 0.0f), 1022.999f);
                    int i0 = (int)t0, i1 = (int)t1;
                    float2 e0 = slut[i0], e1 = slut[i1];
                    float y0 = fmaf(t0 - (float)i0, e0.y, e0.x);
                    float y1 = fmaf(t1 - (float)i1, e1.y, e1.x);
                    if (v0 > 8.0f) y0 = v0;
                    if (v1 > 8.0f) y1 = v1;
                    const int rr = g + 8 * hrow;
                    *reinterpret_cast<float2*>(h1s + rr * H1_PAD + cb) =
                        make_float2(y0, y1);
                }
            }
            __syncwarp();

            // Layer 2: [16,64] @ [64,32]
            float d2v[4][4];
#pragma unroll
            for (int nt = 0; nt < 4; nt++) {
                const float2 bb = *reinterpret_cast<const float2*>(
                    sb2 + nt * 8 + 2 * j);
                d2v[nt][0] = bb.x; d2v[nt][1] = bb.y;
                d2v[nt][2] = bb.x; d2v[nt][3] = bb.y;
            }
#pragma unroll
            for (int ks = 0; ks < 8; ks++) {
                const int cbk = ks * 8;
                a4[0] = tf32_of(h1s[(g    )*H1_PAD + cbk + j    ]);
                a4[1] = tf32_of(h1s[(g + 8)*H1_PAD + cbk + j    ]);
                a4[2] = tf32_of(h1s[(g    )*H1_PAD + cbk + j + 4]);
                a4[3] = tf32_of(h1s[(g + 8)*H1_PAD + cbk + j + 4]);
#pragma unroll
                for (int nt = 0; nt < 4; nt++) {
                    float4 bw = sW2f[(ks * 4 + nt) * 32 + lane];
                    mma_tf32(d2v[nt][0], d2v[nt][1], d2v[nt][2], d2v[nt][3],
                             a4[0], a4[1], a4[2], a4[3],
                             __float_as_uint(bw.x), __float_as_uint(bw.y));
                    mma_tf32(d2v[nt][0], d2v[nt][1], d2v[nt][2], d2v[nt][3],
                             a4[0], a4[1], a4[2], a4[3],
                             __float_as_uint(bw.z), __float_as_uint(bw.w));
                }
            }
            __syncwarp();   // all h1s reads done before h2s (aliased) writes
#pragma unroll
            for (int nt = 0; nt < 4; nt++) {
                const int cb = nt * 8 + 2 * j;
#pragma unroll
                for (int hrow = 0; hrow < 2; hrow++) {
                    float v0 = d2v[nt][2*hrow];
                    float v1 = d2v[nt][2*hrow + 1];
                    float t0 = fminf(fmaxf(fmaf(v0, 64.0f, 512.0f), 0.0f), 1022.999f);
                    float t1 = fminf(fmaxf(fmaf(v1, 64.0f, 512.0f), 0.0f), 1022.999f);
                    int i0 = (int)t0, i1 = (int)t1;
                    float2 e0 = slut[i0], e1 = slut[i1];
                    float y0 = fmaf(t0 - (float)i0, e0.y, e0.x);
                    float y1 = fmaf(t1 - (float)i1, e1.y, e1.x);
                    if (v0 > 8.0f) y0 = v0;
                    if (v1 > 8.0f) y1 = v1;
                    const int rr = g + 8 * hrow;
                    *reinterpret_cast<float2*>(h2s + rr * H2_PAD + cb) =
                        make_float2(y0, y1);
                }
            }
            __syncwarp();

            // Layer 3: [16,32] @ [32,16]
            float d3v[2][4];
#pragma unroll
            for (int nt = 0; nt < 2; nt++) {
                const float2 bb = *reinterpret_cast<const float2*>(
                    sb3 + nt * 8 + 2 * j);
                d3v[nt][0] = bb.x; d3v[nt][1] = bb.y;
                d3v[nt][2] = bb.x; d3v[nt][3] = bb.y;
            }
#pragma unroll
            for (int ks = 0; ks < 4; ks++) {
                const int cbk = ks * 8;
                a4[0] = tf32_of(h2s[(g    )*H2_PAD + cbk + j    ]);
                a4[1] = tf32_of(h2s[(g + 8)*H2_PAD + cbk + j    ]);
                a4[2] = tf32_of(h2s[(g    )*H2_PAD + cbk + j + 4]);
                a4[3] = tf32_of(h2s[(g + 8)*H2_PAD + cbk + j + 4]);
#pragma unroll
                for (int nt = 0; nt < 2; nt++) {
                    float4 bw = sW3f[(ks * 2 + nt) * 32 + lane];
                    mma_tf32(d3v[nt][0], d3v[nt][1], d3v[nt][2], d3v[nt][3],
                             a4[0], a4[1], a4[2], a4[3],
                             __float_as_uint(bw.x), __float_as_uint(bw.y));
                    mma_tf32(d3v[nt][0], d3v[nt][1], d3v[nt][2], d3v[nt][3],
                             a4[0], a4[1], a4[2], a4[3],
                             __float_as_uint(bw.z), __float_as_uint(bw.w));
                }
            }
            __syncwarp();

            const bool fullTile = (tb + 16 <= E);
#pragma unroll
            for (int nt = 0; nt < 2; nt++) {
                const int cb = nt * 8 + 2 * j;
#pragma unroll
                for (int hrow = 0; hrow < 2; hrow++) {
                    float v0 = d3v[nt][2*hrow];
                    float v1 = d3v[nt][2*hrow + 1];
                    const int rr = g + 8 * hrow;
                    if (fullTile || (tb + rr < E)) {
                        lsum4[nt*2+0] += v0;
                        lsum4[nt*2+1] += v1;
                        lsq4[nt*2+0]   = fmaf(v0, v0, lsq4[nt*2+0]);
                        lsq4[nt*2+1]   = fmaf(v1, v1, lsq4[nt*2+1]);
                    }
                    *reinterpret_cast<float2*>(outs + rr * OUT_PAD + cb) =
                        make_float2(v0, v1);
                }
            }
            __syncwarp();

            {   // scatter: lanes 0-15 -> row endpoint, 16-31 -> col endpoint
                const int le = lane & 15;
                const int src = t * 16 + le;
                const int rr = __shfl_sync(0xffffffffu, r, src);
                const int cc = __shfl_sync(0xffffffffu, c, src);
                if (tb + le < E) {
                    const int node = (lane < 16) ? rr : cc;
                    float4* dst = reinterpret_cast<float4*>(
                        &g_node_acc[(size_t)node * 16]);
#pragma unroll
                    for (int q = 0; q < 4; q++)
                        atomicAdd(dst + q, outs4[le * 5 + q]);
                    atomicAdd(&g_degree[node], 1.0f);
                }
            }
            __syncwarp();
        }
    }

    // ---- BN-stat reduction ----
#pragma unroll
    for (int i = 0; i < 4; i++) {
#pragma unroll
        for (int o = 4; o < 32; o <<= 1) {
            lsum4[i] += __shfl_xor_sync(0xffffffffu, lsum4[i], o);
            lsq4[i]  += __shfl_xor_sync(0xffffffffu, lsq4[i],  o);
        }
    }
    if (lane < 4) {
#pragma unroll
        for (int i = 0; i < 4; i++) {
            const int col = (i >> 1) * 8 + 2 * lane + (i & 1);
            atomicAdd(&g_esum[col], (double)lsum4[i]);
            atomicAdd(&g_esq[col],  (double)lsq4[i]);
        }
    }
}

// ---------------------------------------------------------------------------
__global__ void k_ecoef(const float* __restrict__ g, const float* __restrict__ b,
                        int E)
{
    int j = threadIdx.x;
    if (j < 16) {
        double invE = 1.0 / (double)E;
        double m = g_esum[j] * invE;
        double v = g_esq[j] * invE - m * m;
        double s = (double)g[j] / sqrt(v + 1e-5);
        g_es[j] = (float)s;
        g_et[j] = (float)((double)b[j] - m * s);
    }
}

// ---------------------------------------------------------------------------
__global__ __launch_bounds__(256)
void k_node(const float* __restrict__ Wp, const float* __restrict__ bp,
            int N, float* __restrict__ out)
{
    __shared__ float sWp[256], sbp[16], ses[16], set_[16];
    __shared__ float redS[8][16], redQ[8][16];
    if (threadIdx.x < 256) sWp[threadIdx.x] = Wp[threadIdx.x];
    if (threadIdx.x < 16) {
        sbp[threadIdx.x]  = bp[threadIdx.x];
        ses[threadIdx.x]  = g_es[threadIdx.x];
        set_[threadIdx.x] = g_et[threadIdx.x];
    }
    __syncthreads();

    float lsum[16], lsq[16];
#pragma unroll
    for (int k = 0; k < 16; k++) { lsum[k] = 0.0f; lsq[k] = 0.0f; }

    const int n = blockIdx.x * blockDim.x + threadIdx.x;
    if (n < N) {
        const float deg  = g_degree[n];
        const float invd = 1.0f / fmaxf(deg, 1.0f);
        float pre[16];
#pragma unroll
        for (int j = 0; j < 16; j++) {
            const float a = g_node_acc[n * 16 + j];
            pre[j] = (ses[j] * a + set_[j] * deg) * invd;
        }
        float y[16];
#pragma unroll
        for (int k = 0; k < 16; k++) y[k] = sbp[k];
#pragma unroll
        for (int j = 0; j < 16; j++)
#pragma unroll
            for (int k = 0; k < 16; k++) y[k] = fmaf(pre[j], sWp[j*16 + k], y[k]);
#pragma unroll
        for (int k = 0; k < 16; k++) {
            out[n * 16 + k] = y[k];
            lsum[k] = y[k];
            lsq[k]  = y[k] * y[k];
        }
    }

#pragma unroll
    for (int k = 0; k < 16; k++) {
        float s = lsum[k], q = lsq[k];
#pragma unroll
        for (int o = 16; o > 0; o >>= 1) {
            s += __shfl_xor_sync(0xffffffffu, s, o);
            q += __shfl_xor_sync(0xffffffffu, q, o);
        }
        if ((threadIdx.x & 31) == 0) {
            redS[threadIdx.x >> 5][k] = s;
            redQ[threadIdx.x >> 5][k] = q;
        }
    }
    __syncthreads();
    if (threadIdx.x < 16) {
        double s = 0.0, q = 0.0;
#pragma unroll
        for (int w = 0; w < 8; w++) { s += (double)redS[w][threadIdx.x];
                                      q += (double)redQ[w][threadIdx.x]; }
        atomicAdd(&g_nsum[threadIdx.x], s);
        atomicAdd(&g_nsq[threadIdx.x],  q);
    }
}

// ---------------------------------------------------------------------------
__global__ void k_ncoef(const float* __restrict__ g, const float* __restrict__ b,
                        int N)
{
    int j = threadIdx.x;
    if (j < 16) {
        double invN = 1.0 / (double)N;
        double m = g_nsum[j] * invN;
        double v = g_nsq[j] * invN - m * m;
        double s = (double)g[j] / sqrt(v + 1e-5);
        g_ns[j] = (float)s;
        g_nt[j] = (float)((double)b[j] - m * s);
    }
}

// ---------------------------------------------------------------------------
__global__ void k_norm(float* __restrict__ out, int total)
{
    int i = blockIdx.x * blockDim.x + threadIdx.x;
    if (i < total) {
        int j = i & 15;
        out[i] = fmaf(out[i], g_ns[j], g_nt[j]);
    }
}

// ---------------------------------------------------------------------------
extern "C" void kernel_launch(void* const* d_in, const int* in_sizes, int n_in,
                              void* d_out, int out_size)
{
    const float* coords  = (const float*)d_in[0];
    const float* normals = (const float*)d_in[1];
    const float* curv    = (const float*)d_in[2];
    const int*   ei      = (const int*)d_in[3];
    const float* W1 = (const float*)d_in[4];
    const float* b1 = (const float*)d_in[5];
    const float* W2 = (const float*)d_in[6];
    const float* b2 = (const float*)d_in[7];
    const float* W3 = (const float*)d_in[8];
    const float* b3 = (const float*)d_in[9];
    const float* Wp = (const float*)d_in[10];
    const float* bp = (const float*)d_in[11];
    const float* beg = (const float*)d_in[12];
    const float* beb = (const float*)d_in[13];
    const float* bng = (const float*)d_in[14];
    const float* bnb = (const float*)d_in[15];

    const int N = in_sizes[0] / 3;
    const int E = in_sizes[3] / 2;
    const int* row = ei;
    const int* col = ei + E;
    float* out = (float*)d_out;

    const int smemBytes = (OFF_WARP + NWARP * WARP_FLOATS) * 4;  // ~69.3 KB
    static bool attrSet = false;
    if (!attrSet) {
        cudaFuncSetAttribute(k_edge, cudaFuncAttributeMaxDynamicSharedMemorySize,
                             smemBytes);
        attrSet = true;
    }

    k_zero<<<(N * 16 + 255) / 256, 256>>>(N);
    k_pack<<<(N + 255) / 256, 256>>>(coords, normals, curv, N);
    k_edge<<<444, NTHR, smemBytes>>>(row, col, W1, b1, W2, b2, W3, b3, E, N);
    k_ecoef<<<1, 32>>>(beg, beb, E);
    k_node<<<(N + 255) / 256, 256>>>(Wp, bp, N, out);
    k_ncoef<<<1, 32>>>(bng, bnb, N);
    k_norm<<<(N * 16 + 255) / 256, 256>>>(out, N * 16);
}

// round 7
// speedup vs baseline: 1.0696x; 1.0696x over previous
#include <cuda_runtime.h>
#include <cuda_bf16.h>
#include <cstdint>

// ---------------------------------------------------------------------------
// GPUManifoldFeatureEncoder — round 7:
//   * revert to 256thr/8warp/2blk (R5 shape) + R6 bias-fold + small LUT
//   * software-pipelined gather: next tile's indices + node records
//     prefetched into registers during current tile's MMA phases
//   * dummy kernel at launch position 3 so ncu captures k_edge (position 4)
// ---------------------------------------------------------------------------

#define MAX_N 131072
typedef uint32_t u32;

__device__ float  g_nodepack[MAX_N * 8];    // x,y,z,nx | ny,nz,c0,c1
__device__ float  g_node_acc[MAX_N * 16];
__device__ float  g_degree[MAX_N];
__device__ double g_esum[16], g_esq[16];
__device__ double g_nsum[16], g_nsq[16];
__device__ float  g_es[16], g_et[16];
__device__ float  g_ns[16], g_nt[16];

__device__ __forceinline__ float gelu_exact(float x) {
    return 0.5f * x * (1.0f + erff(x * 0.70710678118654752440f));
}
__device__ __forceinline__ u32 tf32_of(float x) {
    u32 r; asm("cvt.rna.tf32.f32 %0, %1;" : "=r"(r) : "f"(x)); return r;
}
__device__ __forceinline__ void split_tf32(float x, u32& hi, u32& lo) {
    asm("cvt.rna.tf32.f32 %0, %1;" : "=r"(hi) : "f"(x));
    float rem = x - __uint_as_float(hi);
    asm("cvt.rna.tf32.f32 %0, %1;" : "=r"(lo) : "f"(rem));
}
__device__ __forceinline__ void mma_tf32(float& d0, float& d1, float& d2, float& d3,
                                         u32 a0, u32 a1, u32 a2, u32 a3,
                                         u32 b0, u32 b1) {
    asm("mma.sync.aligned.m16n8k8.row.col.f32.tf32.tf32.f32 "
        "{%0,%1,%2,%3}, {%4,%5,%6,%7}, {%8,%9}, {%0,%1,%2,%3};"
        : "+f"(d0), "+f"(d1), "+f"(d2), "+f"(d3)
        : "r"(a0), "r"(a1), "r"(a2), "r"(a3), "r"(b0), "r"(b1));
}

// ---------------------------------------------------------------------------
__global__ void k_zero(int N) {
    int i = blockIdx.x * blockDim.x + threadIdx.x;
    int tot = N * 16;
    if (i < tot) g_node_acc[i] = 0.0f;
    if (i < N)   g_degree[i]   = 0.0f;
    if (i < 16) {
        g_esum[i] = 0.0; g_esq[i] = 0.0;
        g_nsum[i] = 0.0; g_nsq[i] = 0.0;
    }
}

__global__ void k_pack(const float* __restrict__ coords,
                       const float* __restrict__ normals,
                       const float* __restrict__ curv, int N)
{
    int n = blockIdx.x * blockDim.x + threadIdx.x;
    if (n < N) {
        float4 a = make_float4(coords[3*n+0], coords[3*n+1], coords[3*n+2],
                               normals[3*n+0]);
        float4 b = make_float4(normals[3*n+1], normals[3*n+2],
                               curv[4*n+0], curv[4*n+1]);
        *reinterpret_cast<float4*>(&g_nodepack[8*n])     = a;
        *reinterpret_cast<float4*>(&g_nodepack[8*n + 4]) = b;
    }
}

// dummy: occupies launch slot 3 so ncu's captured launch (#4) is k_edge
__global__ void k_dummy() {}

// ---------------------------------------------------------------------------
#define OFF_W1   0
#define OFF_W2   1024
#define OFF_W3   5120
#define OFF_B1   6144
#define OFF_B2   6208
#define OFF_B3   6240
#define OFF_LUT  6272
#define OFF_WARP 8320
#define WARP_FLOATS 1344
#define H1_PAD 68
#define H2_PAD 36
#define OUT_PAD 20
#define NWARP 8
#define NTHR  256

__global__ __launch_bounds__(NTHR, 2)
void k_edge(const int* __restrict__ rowi,
            const int* __restrict__ coli,
            const float* __restrict__ W1, const float* __restrict__ b1,
            const float* __restrict__ W2, const float* __restrict__ b2,
            const float* __restrict__ W3, const float* __restrict__ b3,
            int E, int N)
{
    extern __shared__ float sm[];
    float4* sW1f = reinterpret_cast<float4*>(sm + OFF_W1);
    float4* sW2f = reinterpret_cast<float4*>(sm + OFF_W2);
    float4* sW3f = reinterpret_cast<float4*>(sm + OFF_W3);
    float*  sb1  = sm + OFF_B1;
    float*  sb2  = sm + OFF_B2;
    float*  sb3  = sm + OFF_B3;
    float2* slut = reinterpret_cast<float2*>(sm + OFF_LUT);

    const int tid  = threadIdx.x;
    const int lane = tid & 31;
    const int wid  = tid >> 5;
    const int g    = lane >> 2;
    const int j    = lane & 3;

    // ---- preamble ----
    for (int idx = tid; idx < 8 * 32; idx += NTHR) {       // W1
        int nt = idx >> 5, t = idx & 31;
        int kk = t & 3, nn = nt * 8 + (t >> 2);
        float w0 = W1[kk * 64 + nn], w1 = W1[(kk + 4) * 64 + nn];
        u32 h0, l0, h1_, l1; split_tf32(w0, h0, l0); split_tf32(w1, h1_, l1);
        sW1f[idx] = make_float4(__uint_as_float(h0), __uint_as_float(h1_),
                                __uint_as_float(l0), __uint_as_float(l1));
    }
    for (int idx = tid; idx < 32 * 32; idx += NTHR) {      // W2
        int combo = idx >> 5, t = idx & 31;
        int ks = combo >> 2, nt = combo & 3;
        int kk = ks * 8 + (t & 3), nn = nt * 8 + (t >> 2);
        float w0 = W2[kk * 32 + nn], w1 = W2[(kk + 4) * 32 + nn];
        u32 h0, l0, h1_, l1; split_tf32(w0, h0, l0); split_tf32(w1, h1_, l1);
        sW2f[idx] = make_float4(__uint_as_float(h0), __uint_as_float(h1_),
                                __uint_as_float(l0), __uint_as_float(l1));
    }
    for (int idx = tid; idx < 8 * 32; idx += NTHR) {       // W3
        int combo = idx >> 5, t = idx & 31;
        int ks = combo >> 1, nt = combo & 1;
        int kk = ks * 8 + (t & 3), nn = nt * 8 + (t >> 2);
        float w0 = W3[kk * 16 + nn], w1 = W3[(kk + 4) * 16 + nn];
        u32 h0, l0, h1_, l1; split_tf32(w0, h0, l0); split_tf32(w1, h1_, l1);
        sW3f[idx] = make_float4(__uint_as_float(h0), __uint_as_float(h1_),
                                __uint_as_float(l0), __uint_as_float(l1));
    }
    if (tid < 64) sb1[tid] = b1[tid];
    if (tid < 32) sb2[tid] = b2[tid];
    if (tid < 16) sb3[tid] = b3[tid];
    for (int i = tid; i < 1024; i += NTHR) {    // gelu LUT, step 1/64
        float x0 = (float)(i - 512) * 0.015625f;
        float g0 = gelu_exact(x0);
        slut[i] = make_float2(g0, gelu_exact(x0 + 0.015625f) - g0);
    }
    __syncthreads();

    float* efs  = sm + OFF_WARP + wid * WARP_FLOATS;  // [32][8]
    float* h1s  = efs + 256;                          // [16][68]
    float* h2s  = h1s;                                // alias [16][36]
    float* outs = h1s + 576;                          // alias [16][20]
    float4* outs4 = reinterpret_cast<float4*>(outs);

    float lsum4[4] = {0, 0, 0, 0}, lsq4[4] = {0, 0, 0, 0};

    const int tiles32 = (E + 31) >> 5;
    const int warpsTotal = gridDim.x * NWARP;
    const int warpGlobal = blockIdx.x * NWARP + wid;

    // ---- software pipeline: preload first iteration's gather ----
    int   pr = 0, pc = 0;
    float4 pra, prb, pca, pcb;
    {
        const int tb32 = warpGlobal;
        if (tb32 < tiles32) {
            const int e = (tb32 << 5) + lane;
            const bool ev = (e < E);
            int r0 = ev ? rowi[e] : 0;
            int c0 = ev ? coli[e] : 0;
            if ((unsigned)r0 >= (unsigned)N) r0 = 0;
            if ((unsigned)c0 >= (unsigned)N) c0 = 0;
            pr = r0; pc = c0;
            pra = *reinterpret_cast<const float4*>(&g_nodepack[8*r0]);
            prb = *reinterpret_cast<const float4*>(&g_nodepack[8*r0+4]);
            pca = *reinterpret_cast<const float4*>(&g_nodepack[8*c0]);
            pcb = *reinterpret_cast<const float4*>(&g_nodepack[8*c0+4]);
        }
    }

    for (int tb32 = warpGlobal; tb32 < tiles32; tb32 += warpsTotal) {
        const int ebase = tb32 << 5;
        const int r = pr, c = pc;
        const float4 ra = pra, rb = prb, ca = pca, cb = pcb;

        {   // geometry from prefetched registers -> stage to smem
            const float dx = ca.x - ra.x, dy = ca.y - ra.y, dz = ca.z - ra.z;
            const float nrx = ra.w, nry = rb.x, nrz = rb.y;
            const float ncx = ca.w, ncy = cb.x, ncz = cb.y;
            const float ndot = nrx*ncx + nry*ncy + nrz*ncz;
            const float dn = sqrtf(dx*dx + dy*dy + dz*dz) + 1e-8f;
            const float inv = 1.0f / dn;
            float cr = fminf(1.0f, fmaxf(-1.0f, (nrx*dx+nry*dy+nrz*dz)*inv));
            float cc = fminf(1.0f, fmaxf(-1.0f, (ncx*dx+ncy*dy+ncz*dz)*inv));
            float* er = efs + lane * 8;
            er[0] = dx; er[1] = dy; er[2] = dz; er[3] = ndot;
            er[4] = cr; er[5] = cc;
            er[6] = cb.z - rb.z;
            er[7] = cb.w - rb.w;
        }

        // ---- issue next iteration's gather now (overlaps MMA phases) ----
        {
            const int nt32 = tb32 + warpsTotal;
            if (nt32 < tiles32) {
                const int e = (nt32 << 5) + lane;
                const bool ev = (e < E);
                int r0 = ev ? rowi[e] : 0;
                int c0 = ev ? coli[e] : 0;
                if ((unsigned)r0 >= (unsigned)N) r0 = 0;
                if ((unsigned)c0 >= (unsigned)N) c0 = 0;
                pr = r0; pc = c0;
                pra = *reinterpret_cast<const float4*>(&g_nodepack[8*r0]);
                prb = *reinterpret_cast<const float4*>(&g_nodepack[8*r0+4]);
                pca = *reinterpret_cast<const float4*>(&g_nodepack[8*c0]);
                pcb = *reinterpret_cast<const float4*>(&g_nodepack[8*c0+4]);
            }
        }
        __syncwarp();

#pragma unroll
        for (int t = 0; t < 2; t++) {
            const int tb = ebase + t * 16;

            // Layer 1: [16,8] @ [8,64], bias in accumulator init
            u32 a4[4];
            {
                const float* base = efs + t * 128;
                a4[0] = tf32_of(base[(g    )*8 + j    ]);
                a4[1] = tf32_of(base[(g + 8)*8 + j    ]);
                a4[2] = tf32_of(base[(g    )*8 + j + 4]);
                a4[3] = tf32_of(base[(g + 8)*8 + j + 4]);
            }
            float d1v[8][4];
#pragma unroll
            for (int nt = 0; nt < 8; nt++) {
                const float2 bb = *reinterpret_cast<const float2*>(
                    sb1 + nt * 8 + 2 * j);
                d1v[nt][0] = bb.x; d1v[nt][1] = bb.y;
                d1v[nt][2] = bb.x; d1v[nt][3] = bb.y;
                float4 bw = sW1f[nt * 32 + lane];
                mma_tf32(d1v[nt][0], d1v[nt][1], d1v[nt][2], d1v[nt][3],
                         a4[0], a4[1], a4[2], a4[3],
                         __float_as_uint(bw.x), __float_as_uint(bw.y));
                mma_tf32(d1v[nt][0], d1v[nt][1], d1v[nt][2], d1v[nt][3],
                         a4[0], a4[1], a4[2], a4[3],
                         __float_as_uint(bw.z), __float_as_uint(bw.w));
            }
#pragma unroll
            for (int nt = 0; nt < 8; nt++) {
                const int cb2 = nt * 8 + 2 * j;
#pragma unroll
                for (int hrow = 0; hrow < 2; hrow++) {
                    float v0 = d1v[nt][2*hrow];
                    float v1 = d1v[nt][2*hrow + 1];
                    float t0 = fminf(fmaxf(fmaf(v0, 64.0f, 512.0f), 0.0f), 1022.999f);
                    float t1 = fminf(fmaxf(fmaf(v1, 64.0f, 512.0f), 0.0f), 1022.999f);
                    int i0 = (int)t0, i1 = (int)t1;
                    float2 e0 = slut[i0], e1 = slut[i1];
                    float y0 = fmaf(t0 - (float)i0, e0.y, e0.x);
                    float y1 = fmaf(t1 - (float)i1, e1.y, e1.x);
                    if (v0 > 8.0f) y0 = v0;
                    if (v1 > 8.0f) y1 = v1;
                    const int rr = g + 8 * hrow;
                    *reinterpret_cast<float2*>(h1s + rr * H1_PAD + cb2) =
                        make_float2(y0, y1);
                }
            }
            __syncwarp();

            // Layer 2: [16,64] @ [64,32]
            float d2v[4][4];
#pragma unroll
            for (int nt = 0; nt < 4; nt++) {
                const float2 bb = *reinterpret_cast<const float2*>(
                    sb2 + nt * 8 + 2 * j);
                d2v[nt][0] = bb.x; d2v[nt][1] = bb.y;
                d2v[nt][2] = bb.x; d2v[nt][3] = bb.y;
            }
#pragma unroll
            for (int ks = 0; ks < 8; ks++) {
                const int cbk = ks * 8;
                a4[0] = tf32_of(h1s[(g    )*H1_PAD + cbk + j    ]);
                a4[1] = tf32_of(h1s[(g + 8)*H1_PAD + cbk + j    ]);
                a4[2] = tf32_of(h1s[(g    )*H1_PAD + cbk + j + 4]);
                a4[3] = tf32_of(h1s[(g + 8)*H1_PAD + cbk + j + 4]);
#pragma unroll
                for (int nt = 0; nt < 4; nt++) {
                    float4 bw = sW2f[(ks * 4 + nt) * 32 + lane];
                    mma_tf32(d2v[nt][0], d2v[nt][1], d2v[nt][2], d2v[nt][3],
                             a4[0], a4[1], a4[2], a4[3],
                             __float_as_uint(bw.x), __float_as_uint(bw.y));
                    mma_tf32(d2v[nt][0], d2v[nt][1], d2v[nt][2], d2v[nt][3],
                             a4[0], a4[1], a4[2], a4[3],
                             __float_as_uint(bw.z), __float_as_uint(bw.w));
                }
            }
            __syncwarp();   // h1s reads done before h2s (aliased) writes
#pragma unroll
            for (int nt = 0; nt < 4; nt++) {
                const int cb2 = nt * 8 + 2 * j;
#pragma unroll
                for (int hrow = 0; hrow < 2; hrow++) {
                    float v0 = d2v[nt][2*hrow];
                    float v1 = d2v[nt][2*hrow + 1];
                    float t0 = fminf(fmaxf(fmaf(v0, 64.0f, 512.0f), 0.0f), 1022.999f);
                    float t1 = fminf(fmaxf(fmaf(v1, 64.0f, 512.0f), 0.0f), 1022.999f);
                    int i0 = (int)t0, i1 = (int)t1;
                    float2 e0 = slut[i0], e1 = slut[i1];
                    float y0 = fmaf(t0 - (float)i0, e0.y, e0.x);
                    float y1 = fmaf(t1 - (float)i1, e1.y, e1.x);
                    if (v0 > 8.0f) y0 = v0;
                    if (v1 > 8.0f) y1 = v1;
                    const int rr = g + 8 * hrow;
                    *reinterpret_cast<float2*>(h2s + rr * H2_PAD + cb2) =
                        make_float2(y0, y1);
                }
            }
            __syncwarp();

            // Layer 3: [16,32] @ [32,16]
            float d3v[2][4];
#pragma unroll
            for (int nt = 0; nt < 2; nt++) {
                const float2 bb = *reinterpret_cast<const float2*>(
                    sb3 + nt * 8 + 2 * j);
                d3v[nt][0] = bb.x; d3v[nt][1] = bb.y;
                d3v[nt][2] = bb.x; d3v[nt][3] = bb.y;
            }
#pragma unroll
            for (int ks = 0; ks < 4; ks++) {
                const int cbk = ks * 8;
                a4[0] = tf32_of(h2s[(g    )*H2_PAD + cbk + j    ]);
                a4[1] = tf32_of(h2s[(g + 8)*H2_PAD + cbk + j    ]);
                a4[2] = tf32_of(h2s[(g    )*H2_PAD + cbk + j + 4]);
                a4[3] = tf32_of(h2s[(g + 8)*H2_PAD + cbk + j + 4]);
#pragma unroll
                for (int nt = 0; nt < 2; nt++) {
                    float4 bw = sW3f[(ks * 2 + nt) * 32 + lane];
                    mma_tf32(d3v[nt][0], d3v[nt][1], d3v[nt][2], d3v[nt][3],
                             a4[0], a4[1], a4[2], a4[3],
                             __float_as_uint(bw.x), __float_as_uint(bw.y));
                    mma_tf32(d3v[nt][0], d3v[nt][1], d3v[nt][2], d3v[nt][3],
                             a4[0], a4[1], a4[2], a4[3],
                             __float_as_uint(bw.z), __float_as_uint(bw.w));
                }
            }
            __syncwarp();

            const bool fullTile = (tb + 16 <= E);
#pragma unroll
            for (int nt = 0; nt < 2; nt++) {
                const int cb2 = nt * 8 + 2 * j;
#pragma unroll
                for (int hrow = 0; hrow < 2; hrow++) {
                    float v0 = d3v[nt][2*hrow];
                    float v1 = d3v[nt][2*hrow + 1];
                    const int rr = g + 8 * hrow;
                    if (fullTile || (tb + rr < E)) {
                        lsum4[nt*2+0] += v0;
                        lsum4[nt*2+1] += v1;
                        lsq4[nt*2+0]   = fmaf(v0, v0, lsq4[nt*2+0]);
                        lsq4[nt*2+1]   = fmaf(v1, v1, lsq4[nt*2+1]);
                    }
                    *reinterpret_cast<float2*>(outs + rr * OUT_PAD + cb2) =
                        make_float2(v0, v1);
                }
            }
            __syncwarp();

            {   // scatter: lanes 0-15 -> row endpoint, 16-31 -> col endpoint
                const int le = lane & 15;
                const int src = t * 16 + le;
                const int rr = __shfl_sync(0xffffffffu, r, src);
                const int cc = __shfl_sync(0xffffffffu, c, src);
                if (tb + le < E) {
                    const int node = (lane < 16) ? rr : cc;
                    float4* dst = reinterpret_cast<float4*>(
                        &g_node_acc[(size_t)node * 16]);
#pragma unroll
                    for (int q = 0; q < 4; q++)
                        atomicAdd(dst + q, outs4[le * 5 + q]);
                    atomicAdd(&g_degree[node], 1.0f);
                }
            }
            __syncwarp();
        }
    }

    // ---- BN-stat reduction ----
#pragma unroll
    for (int i = 0; i < 4; i++) {
#pragma unroll
        for (int o = 4; o < 32; o <<= 1) {
            lsum4[i] += __shfl_xor_sync(0xffffffffu, lsum4[i], o);
            lsq4[i]  += __shfl_xor_sync(0xffffffffu, lsq4[i],  o);
        }
    }
    if (lane < 4) {
#pragma unroll
        for (int i = 0; i < 4; i++) {
            const int col = (i >> 1) * 8 + 2 * lane + (i & 1);
            atomicAdd(&g_esum[col], (double)lsum4[i]);
            atomicAdd(&g_esq[col],  (double)lsq4[i]);
        }
    }
}

// ---------------------------------------------------------------------------
__global__ void k_ecoef(const float* __restrict__ g, const float* __restrict__ b,
                        int E)
{
    int j = threadIdx.x;
    if (j < 16) {
        double invE = 1.0 / (double)E;
        double m = g_esum[j] * invE;
        double v = g_esq[j] * invE - m * m;
        double s = (double)g[j] / sqrt(v + 1e-5);
        g_es[j] = (float)s;
        g_et[j] = (float)((double)b[j] - m * s);
    }
}

// ---------------------------------------------------------------------------
__global__ __launch_bounds__(256)
void k_node(const float* __restrict__ Wp, const float* __restrict__ bp,
            int N, float* __restrict__ out)
{
    __shared__ float sWp[256], sbp[16], ses[16], set_[16];
    __shared__ float redS[8][16], redQ[8][16];
    if (threadIdx.x < 256) sWp[threadIdx.x] = Wp[threadIdx.x];
    if (threadIdx.x < 16) {
        sbp[threadIdx.x]  = bp[threadIdx.x];
        ses[threadIdx.x]  = g_es[threadIdx.x];
        set_[threadIdx.x] = g_et[threadIdx.x];
    }
    __syncthreads();

    float lsum[16], lsq[16];
#pragma unroll
    for (int k = 0; k < 16; k++) { lsum[k] = 0.0f; lsq[k] = 0.0f; }

    const int n = blockIdx.x * blockDim.x + threadIdx.x;
    if (n < N) {
        const float deg  = g_degree[n];
        const float invd = 1.0f / fmaxf(deg, 1.0f);
        float pre[16];
#pragma unroll
        for (int j = 0; j < 16; j++) {
            const float a = g_node_acc[n * 16 + j];
            pre[j] = (ses[j] * a + set_[j] * deg) * invd;
        }
        float y[16];
#pragma unroll
        for (int k = 0; k < 16; k++) y[k] = sbp[k];
#pragma unroll
        for (int j = 0; j < 16; j++)
#pragma unroll
            for (int k = 0; k < 16; k++) y[k] = fmaf(pre[j], sWp[j*16 + k], y[k]);
#pragma unroll
        for (int k = 0; k < 16; k++) {
            out[n * 16 + k] = y[k];
            lsum[k] = y[k];
            lsq[k]  = y[k] * y[k];
        }
    }

#pragma unroll
    for (int k = 0; k < 16; k++) {
        float s = lsum[k], q = lsq[k];
#pragma unroll
        for (int o = 16; o > 0; o >>= 1) {
            s += __shfl_xor_sync(0xffffffffu, s, o);
            q += __shfl_xor_sync(0xffffffffu, q, o);
        }
        if ((threadIdx.x & 31) == 0) {
            redS[threadIdx.x >> 5][k] = s;
            redQ[threadIdx.x >> 5][k] = q;
        }
    }
    __syncthreads();
    if (threadIdx.x < 16) {
        double s = 0.0, q = 0.0;
#pragma unroll
        for (int w = 0; w < 8; w++) { s += (double)redS[w][threadIdx.x];
                                      q += (double)redQ[w][threadIdx.x]; }
        atomicAdd(&g_nsum[threadIdx.x], s);
        atomicAdd(&g_nsq[threadIdx.x],  q);
    }
}

// ---------------------------------------------------------------------------
__global__ void k_ncoef(const float* __restrict__ g, const float* __restrict__ b,
                        int N)
{
    int j = threadIdx.x;
    if (j < 16) {
        double invN = 1.0 / (double)N;
        double m = g_nsum[j] * invN;
        double v = g_nsq[j] * invN - m * m;
        double s = (double)g[j] / sqrt(v + 1e-5);
        g_ns[j] = (float)s;
        g_nt[j] = (float)((double)b[j] - m * s);
    }
}

// ---------------------------------------------------------------------------
__global__ void k_norm(float* __restrict__ out, int total)
{
    int i = blockIdx.x * blockDim.x + threadIdx.x;
    if (i < total) {
        int j = i & 15;
        out[i] = fmaf(out[i], g_ns[j], g_nt[j]);
    }
}

// ---------------------------------------------------------------------------
extern "C" void kernel_launch(void* const* d_in, const int* in_sizes, int n_in,
                              void* d_out, int out_size)
{
    const float* coords  = (const float*)d_in[0];
    const float* normals = (const float*)d_in[1];
    const float* curv    = (const float*)d_in[2];
    const int*   ei      = (const int*)d_in[3];
    const float* W1 = (const float*)d_in[4];
    const float* b1 = (const float*)d_in[5];
    const float* W2 = (const float*)d_in[6];
    const float* b2 = (const float*)d_in[7];
    const float* W3 = (const float*)d_in[8];
    const float* b3 = (const float*)d_in[9];
    const float* Wp = (const float*)d_in[10];
    const float* bp = (const float*)d_in[11];
    const float* beg = (const float*)d_in[12];
    const float* beb = (const float*)d_in[13];
    const float* bng = (const float*)d_in[14];
    const float* bnb = (const float*)d_in[15];

    const int N = in_sizes[0] / 3;
    const int E = in_sizes[3] / 2;
    const int* row = ei;
    const int* col = ei + E;
    float* out = (float*)d_out;

    const int smemBytes = (OFF_WARP + NWARP * WARP_FLOATS) * 4;  // ~76.3 KB
    static bool attrSet = false;
    if (!attrSet) {
        cudaFuncSetAttribute(k_edge, cudaFuncAttributeMaxDynamicSharedMemorySize,
                             smemBytes);
        attrSet = true;
    }

    k_zero<<<(N * 16 + 255) / 256, 256>>>(N);                       // launch 1
    k_pack<<<(N + 255) / 256, 256>>>(coords, normals, curv, N);     // launch 2
    k_dummy<<<1, 32>>>();                                           // launch 3
    k_edge<<<296, NTHR, smemBytes>>>(row, col, W1, b1, W2, b2,      // launch 4
                                     W3, b3, E, N);
    k_ecoef<<<1, 32>>>(beg, beb, E);
    k_node<<<(N + 255) / 256, 256>>>(Wp, bp, N, out);
    k_ncoef<<<1, 32>>>(bng, bnb, N);
    k_norm<<<(N * 16 + 255) / 256, 256>>>(out, N * 16);
}

// round 8
// speedup vs baseline: 1.5041x; 1.4061x over previous
#include <cuda_runtime.h>
#include <cuda_bf16.h>
#include <cstdint>

// ---------------------------------------------------------------------------
// GPUManifoldFeatureEncoder — round 8:
//   * layers 2-3: bf16 m16n8k16 3-term MMAs; accumulator fragment == next
//     A fragment => gelu + bf16 hi/lo pack stays in REGISTERS (no smem
//     staging between layers at all)
//   * layer 1: tf32 k8 3-term (act hi+lo) -> rel_err ~2e-5
//   * weight fragment bytes halved (bf16 hi+lo = 16B/k16)
//   * transposed scatter: 4 lanes per node => 8 lines per RED.128 (was 32)
//   * smem 41.5KB; prefetch pipeline kept; dummy launch keeps ncu on k_edge
// ---------------------------------------------------------------------------

#define MAX_N 131072
typedef uint32_t u32;

__device__ float  g_nodepack[MAX_N * 8];    // x,y,z,nx | ny,nz,c0,c1
__device__ float  g_node_acc[MAX_N * 16];
__device__ float  g_degree[MAX_N];
__device__ double g_esum[16], g_esq[16];
__device__ double g_nsum[16], g_nsq[16];
__device__ float  g_es[16], g_et[16];
__device__ float  g_ns[16], g_nt[16];

__device__ __forceinline__ float gelu_exact(float x) {
    return 0.5f * x * (1.0f + erff(x * 0.70710678118654752440f));
}
__device__ __forceinline__ void split_tf32(float x, u32& hi, u32& lo) {
    asm("cvt.rna.tf32.f32 %0, %1;" : "=r"(hi) : "f"(x));
    float rem = x - __uint_as_float(hi);
    asm("cvt.rna.tf32.f32 %0, %1;" : "=r"(lo) : "f"(rem));
}
// pack (y0 -> lower bf16, y1 -> upper bf16) + residual pair
__device__ __forceinline__ void bfpair(float y0, float y1, u32& hp, u32& lp) {
    u32 h; asm("cvt.rn.bf16x2.f32 %0, %1, %2;" : "=r"(h) : "f"(y1), "f"(y0));
    float h0 = __uint_as_float(h << 16);
    float h1 = __uint_as_float(h & 0xFFFF0000u);
    u32 l; asm("cvt.rn.bf16x2.f32 %0, %1, %2;" : "=r"(l) : "f"(y1 - h1), "f"(y0 - h0));
    hp = h; lp = l;
}
__device__ __forceinline__ void mma_tf32(float& d0, float& d1, float& d2, float& d3,
                                         u32 a0, u32 a1, u32 a2, u32 a3,
                                         u32 b0, u32 b1) {
    asm("mma.sync.aligned.m16n8k8.row.col.f32.tf32.tf32.f32 "
        "{%0,%1,%2,%3}, {%4,%5,%6,%7}, {%8,%9}, {%0,%1,%2,%3};"
        : "+f"(d0), "+f"(d1), "+f"(d2), "+f"(d3)
        : "r"(a0), "r"(a1), "r"(a2), "r"(a3), "r"(b0), "r"(b1));
}
__device__ __forceinline__ void mma_bf16(float& d0, float& d1, float& d2, float& d3,
                                         u32 a0, u32 a1, u32 a2, u32 a3,
                                         u32 b0, u32 b1) {
    asm("mma.sync.aligned.m16n8k16.row.col.f32.bf16.bf16.f32 "
        "{%0,%1,%2,%3}, {%4,%5,%6,%7}, {%8,%9}, {%0,%1,%2,%3};"
        : "+f"(d0), "+f"(d1), "+f"(d2), "+f"(d3)
        : "r"(a0), "r"(a1), "r"(a2), "r"(a3), "r"(b0), "r"(b1));
}

// ---------------------------------------------------------------------------
__global__ void k_zero(int N) {
    int i = blockIdx.x * blockDim.x + threadIdx.x;
    int tot = N * 16;
    if (i < tot) g_node_acc[i] = 0.0f;
    if (i < N)   g_degree[i]   = 0.0f;
    if (i < 16) {
        g_esum[i] = 0.0; g_esq[i] = 0.0;
        g_nsum[i] = 0.0; g_nsq[i] = 0.0;
    }
}

__global__ void k_pack(const float* __restrict__ coords,
                       const float* __restrict__ normals,
                       const float* __restrict__ curv, int N)
{
    int n = blockIdx.x * blockDim.x + threadIdx.x;
    if (n < N) {
        float4 a = make_float4(coords[3*n+0], coords[3*n+1], coords[3*n+2],
                               normals[3*n+0]);
        float4 b = make_float4(normals[3*n+1], normals[3*n+2],
                               curv[4*n+0], curv[4*n+1]);
        *reinterpret_cast<float4*>(&g_nodepack[8*n])     = a;
        *reinterpret_cast<float4*>(&g_nodepack[8*n + 4]) = b;
    }
}

__global__ void k_dummy() {}

// ---------------------------------------------------------------------------
// smem (floats): W1f[1024] W2b[2048] W3b[512] b1[64] b2[32] b3[16]+pad
//                lut[2048]; per-warp: efs[256] + outs[320]
// ---------------------------------------------------------------------------
#define OFF_W1   0
#define OFF_W2   1024
#define OFF_W3   3072
#define OFF_B1   3584
#define OFF_B2   3648
#define OFF_B3   3680
#define OFF_LUT  3712
#define OFF_WARP 5760
#define WARP_FLOATS 576
#define OUT_PAD 20
#define NWARP 8
#define NTHR  256

__global__ __launch_bounds__(NTHR, 2)
void k_edge(const int* __restrict__ rowi,
            const int* __restrict__ coli,
            const float* __restrict__ W1, const float* __restrict__ b1,
            const float* __restrict__ W2, const float* __restrict__ b2,
            const float* __restrict__ W3, const float* __restrict__ b3,
            int E, int N)
{
    extern __shared__ float sm[];
    float4* sW1f = reinterpret_cast<float4*>(sm + OFF_W1);
    uint4*  sW2b = reinterpret_cast<uint4*>(sm + OFF_W2);
    uint4*  sW3b = reinterpret_cast<uint4*>(sm + OFF_W3);
    float*  sb1  = sm + OFF_B1;
    float*  sb2  = sm + OFF_B2;
    float*  sb3  = sm + OFF_B3;
    float2* slut = reinterpret_cast<float2*>(sm + OFF_LUT);

    const int tid  = threadIdx.x;
    const int lane = tid & 31;
    const int wid  = tid >> 5;
    const int g    = lane >> 2;
    const int j    = lane & 3;

    // ---- preamble ----
    for (int idx = tid; idx < 8 * 32; idx += NTHR) {       // W1 tf32 hi/lo
        int nt = idx >> 5, t = idx & 31;
        int kk = t & 3, nn = nt * 8 + (t >> 2);
        float w0 = W1[kk * 64 + nn], w1 = W1[(kk + 4) * 64 + nn];
        u32 h0, l0, h1_, l1; split_tf32(w0, h0, l0); split_tf32(w1, h1_, l1);
        sW1f[idx] = make_float4(__uint_as_float(h0), __uint_as_float(h1_),
                                __uint_as_float(l0), __uint_as_float(l1));
    }
    for (int idx = tid; idx < 16 * 32; idx += NTHR) {      // W2 bf16 hi/lo pairs
        int combo = idx >> 5, t = idx & 31;
        int s = combo >> 2, nt = combo & 3;
        int g2 = t >> 2, j2 = t & 3;
        int nn = nt * 8 + g2;
        int k0 = s * 16 + 2 * j2;
        float w00 = W2[(k0    ) * 32 + nn], w01 = W2[(k0 + 1) * 32 + nn];
        float w10 = W2[(k0 + 8) * 32 + nn], w11 = W2[(k0 + 9) * 32 + nn];
        u32 h0p, l0p, h1p, l1p;
        bfpair(w00, w01, h0p, l0p);
        bfpair(w10, w11, h1p, l1p);
        sW2b[idx] = make_uint4(h0p, h1p, l0p, l1p);
    }
    for (int idx = tid; idx < 4 * 32; idx += NTHR) {       // W3 bf16 hi/lo pairs
        int combo = idx >> 5, t = idx & 31;
        int s = combo >> 1, nt = combo & 1;
        int g2 = t >> 2, j2 = t & 3;
        int nn = nt * 8 + g2;
        int k0 = s * 16 + 2 * j2;
        float w00 = W3[(k0    ) * 16 + nn], w01 = W3[(k0 + 1) * 16 + nn];
        float w10 = W3[(k0 + 8) * 16 + nn], w11 = W3[(k0 + 9) * 16 + nn];
        u32 h0p, l0p, h1p, l1p;
        bfpair(w00, w01, h0p, l0p);
        bfpair(w10, w11, h1p, l1p);
        sW3b[idx] = make_uint4(h0p, h1p, l0p, l1p);
    }
    if (tid < 64) sb1[tid] = b1[tid];
    if (tid < 32) sb2[tid] = b2[tid];
    if (tid < 16) sb3[tid] = b3[tid];
    for (int i = tid; i < 1024; i += NTHR) {    // gelu LUT, step 1/64
        float x0 = (float)(i - 512) * 0.015625f;
        float g0 = gelu_exact(x0);
        slut[i] = make_float2(g0, gelu_exact(x0 + 0.015625f) - g0);
    }
    __syncthreads();

    float* efs  = sm + OFF_WARP + wid * WARP_FLOATS;  // [32][8]
    float* outs = efs + 256;                          // [16][20]
    float4* outs4 = reinterpret_cast<float4*>(outs);

    float lsum4[4] = {0, 0, 0, 0}, lsq4[4] = {0, 0, 0, 0};

    const int tiles32 = (E + 31) >> 5;
    const int warpsTotal = gridDim.x * NWARP;
    const int warpGlobal = blockIdx.x * NWARP + wid;

    // ---- software pipeline: preload first iteration's gather ----
    int   pr = 0, pc = 0;
    float4 pra, prb, pca, pcb;
    if (warpGlobal < tiles32) {
        const int e = (warpGlobal << 5) + lane;
        const bool ev = (e < E);
        int r0 = ev ? rowi[e] : 0;
        int c0 = ev ? coli[e] : 0;
        if ((unsigned)r0 >= (unsigned)N) r0 = 0;
        if ((unsigned)c0 >= (unsigned)N) c0 = 0;
        pr = r0; pc = c0;
        pra = *reinterpret_cast<const float4*>(&g_nodepack[8*r0]);
        prb = *reinterpret_cast<const float4*>(&g_nodepack[8*r0+4]);
        pca = *reinterpret_cast<const float4*>(&g_nodepack[8*c0]);
        pcb = *reinterpret_cast<const float4*>(&g_nodepack[8*c0+4]);
    }

    for (int tb32 = warpGlobal; tb32 < tiles32; tb32 += warpsTotal) {
        const int ebase = tb32 << 5;
        const int r = pr, c = pc;
        const float4 ra = pra, rb = prb, ca = pca, cb = pcb;

        {   // geometry from prefetched registers -> stage ef to smem
            const float dx = ca.x - ra.x, dy = ca.y - ra.y, dz = ca.z - ra.z;
            const float nrx = ra.w, nry = rb.x, nrz = rb.y;
            const float ncx = ca.w, ncy = cb.x, ncz = cb.y;
            const float ndot = nrx*ncx + nry*ncy + nrz*ncz;
            const float dn = sqrtf(dx*dx + dy*dy + dz*dz) + 1e-8f;
            const float inv = 1.0f / dn;
            float cr = fminf(1.0f, fmaxf(-1.0f, (nrx*dx+nry*dy+nrz*dz)*inv));
            float cc = fminf(1.0f, fmaxf(-1.0f, (ncx*dx+ncy*dy+ncz*dz)*inv));
            float4* er = reinterpret_cast<float4*>(efs + lane * 8);
            er[0] = make_float4(dx, dy, dz, ndot);
            er[1] = make_float4(cr, cc, cb.z - rb.z, cb.w - rb.w);
        }

        // issue next iteration's gather now (overlaps MMA phases)
        {
            const int nt32 = tb32 + warpsTotal;
            if (nt32 < tiles32) {
                const int e = (nt32 << 5) + lane;
                const bool ev = (e < E);
                int r0 = ev ? rowi[e] : 0;
                int c0 = ev ? coli[e] : 0;
                if ((unsigned)r0 >= (unsigned)N) r0 = 0;
                if ((unsigned)c0 >= (unsigned)N) c0 = 0;
                pr = r0; pc = c0;
                pra = *reinterpret_cast<const float4*>(&g_nodepack[8*r0]);
                prb = *reinterpret_cast<const float4*>(&g_nodepack[8*r0+4]);
                pca = *reinterpret_cast<const float4*>(&g_nodepack[8*c0]);
                pcb = *reinterpret_cast<const float4*>(&g_nodepack[8*c0+4]);
            }
        }
        __syncwarp();

#pragma unroll
        for (int t = 0; t < 2; t++) {
            const int tb = ebase + t * 16;

            // ---- Layer 1: tf32 k8, 3-term (act hi+lo, weight hi+lo) ----
            u32 ah[4], al[4];
            {
                const float* base = efs + t * 128;
                split_tf32(base[(g    )*8 + j    ], ah[0], al[0]);
                split_tf32(base[(g + 8)*8 + j    ], ah[1], al[1]);
                split_tf32(base[(g    )*8 + j + 4], ah[2], al[2]);
                split_tf32(base[(g + 8)*8 + j + 4], ah[3], al[3]);
            }
            float d1v[8][4];
#pragma unroll
            for (int nt = 0; nt < 8; nt++) {
                const float2 bb = *reinterpret_cast<const float2*>(
                    sb1 + nt * 8 + 2 * j);
                d1v[nt][0] = bb.x; d1v[nt][1] = bb.y;
                d1v[nt][2] = bb.x; d1v[nt][3] = bb.y;
                float4 bw = sW1f[nt * 32 + lane];
                u32 bh0 = __float_as_uint(bw.x), bh1 = __float_as_uint(bw.y);
                u32 bl0 = __float_as_uint(bw.z), bl1 = __float_as_uint(bw.w);
                mma_tf32(d1v[nt][0], d1v[nt][1], d1v[nt][2], d1v[nt][3],
                         ah[0], ah[1], ah[2], ah[3], bh0, bh1);
                mma_tf32(d1v[nt][0], d1v[nt][1], d1v[nt][2], d1v[nt][3],
                         al[0], al[1], al[2], al[3], bh0, bh1);
                mma_tf32(d1v[nt][0], d1v[nt][1], d1v[nt][2], d1v[nt][3],
                         ah[0], ah[1], ah[2], ah[3], bl0, bl1);
            }
            // gelu + pack as bf16 hi/lo A-fragments for layer 2 (in regs!)
            u32 A2h[4][4], A2l[4][4];
#pragma unroll
            for (int nt = 0; nt < 8; nt++) {
                float y0, y1, y2, y3;
                {
                    float v0 = d1v[nt][0], v1 = d1v[nt][1];
                    float v2 = d1v[nt][2], v3 = d1v[nt][3];
                    float t0 = fminf(fmaxf(fmaf(v0, 64.0f, 512.0f), 0.0f), 1022.999f);
                    float t1 = fminf(fmaxf(fmaf(v1, 64.0f, 512.0f), 0.0f), 1022.999f);
                    float t2 = fminf(fmaxf(fmaf(v2, 64.0f, 512.0f), 0.0f), 1022.999f);
                    float t3 = fminf(fmaxf(fmaf(v3, 64.0f, 512.0f), 0.0f), 1022.999f);
                    int i0 = (int)t0, i1 = (int)t1, i2 = (int)t2, i3 = (int)t3;
                    float2 e0 = slut[i0], e1 = slut[i1], e2 = slut[i2], e3 = slut[i3];
                    y0 = fmaf(t0 - (float)i0, e0.y, e0.x);
                    y1 = fmaf(t1 - (float)i1, e1.y, e1.x);
                    y2 = fmaf(t2 - (float)i2, e2.y, e2.x);
                    y3 = fmaf(t3 - (float)i3, e3.y, e3.x);
                    if (v0 > 8.0f) y0 = v0;
                    if (v1 > 8.0f) y1 = v1;
                    if (v2 > 8.0f) y2 = v2;
                    if (v3 > 8.0f) y3 = v3;
                }
                const int s = nt >> 1, half = nt & 1;
                u32 hp, lp;
                bfpair(y0, y1, hp, lp);              // row g pair
                A2h[s][half * 2 + 0] = hp; A2l[s][half * 2 + 0] = lp;
                bfpair(y2, y3, hp, lp);              // row g+8 pair
                A2h[s][half * 2 + 1] = hp; A2l[s][half * 2 + 1] = lp;
            }

            // ---- Layer 2: bf16 m16n8k16, 3-term ----
            float d2v[4][4];
#pragma unroll
            for (int n2 = 0; n2 < 4; n2++) {
                const float2 bb = *reinterpret_cast<const float2*>(
                    sb2 + n2 * 8 + 2 * j);
                d2v[n2][0] = bb.x; d2v[n2][1] = bb.y;
                d2v[n2][2] = bb.x; d2v[n2][3] = bb.y;
            }
#pragma unroll
            for (int s = 0; s < 4; s++) {
#pragma unroll
                for (int n2 = 0; n2 < 4; n2++) {
                    uint4 bw = sW2b[(s * 4 + n2) * 32 + lane];
                    mma_bf16(d2v[n2][0], d2v[n2][1], d2v[n2][2], d2v[n2][3],
                             A2h[s][0], A2h[s][1], A2h[s][2], A2h[s][3],
                             bw.x, bw.y);
                    mma_bf16(d2v[n2][0], d2v[n2][1], d2v[n2][2], d2v[n2][3],
                             A2h[s][0], A2h[s][1], A2h[s][2], A2h[s][3],
                             bw.z, bw.w);
                    mma_bf16(d2v[n2][0], d2v[n2][1], d2v[n2][2], d2v[n2][3],
                             A2l[s][0], A2l[s][1], A2l[s][2], A2l[s][3],
                             bw.x, bw.y);
                }
            }
            // gelu + pack for layer 3
            u32 A3h[2][4], A3l[2][4];
#pragma unroll
            for (int n2 = 0; n2 < 4; n2++) {
                float y0, y1, y2, y3;
                {
                    float v0 = d2v[n2][0], v1 = d2v[n2][1];
                    float v2 = d2v[n2][2], v3 = d2v[n2][3];
                    float t0 = fminf(fmaxf(fmaf(v0, 64.0f, 512.0f), 0.0f), 1022.999f);
                    float t1 = fminf(fmaxf(fmaf(v1, 64.0f, 512.0f), 0.0f), 1022.999f);
                    float t2 = fminf(fmaxf(fmaf(v2, 64.0f, 512.0f), 0.0f), 1022.999f);
                    float t3 = fminf(fmaxf(fmaf(v3, 64.0f, 512.0f), 0.0f), 1022.999f);
                    int i0 = (int)t0, i1 = (int)t1, i2 = (int)t2, i3 = (int)t3;
                    float2 e0 = slut[i0], e1 = slut[i1], e2 = slut[i2], e3 = slut[i3];
                    y0 = fmaf(t0 - (float)i0, e0.y, e0.x);
                    y1 = fmaf(t1 - (float)i1, e1.y, e1.x);
                    y2 = fmaf(t2 - (float)i2, e2.y, e2.x);
                    y3 = fmaf(t3 - (float)i3, e3.y, e3.x);
                    if (v0 > 8.0f) y0 = v0;
                    if (v1 > 8.0f) y1 = v1;
                    if (v2 > 8.0f) y2 = v2;
                    if (v3 > 8.0f) y3 = v3;
                }
                const int s = n2 >> 1, half = n2 & 1;
                u32 hp, lp;
                bfpair(y0, y1, hp, lp);
                A3h[s][half * 2 + 0] = hp; A3l[s][half * 2 + 0] = lp;
                bfpair(y2, y3, hp, lp);
                A3h[s][half * 2 + 1] = hp; A3l[s][half * 2 + 1] = lp;
            }

            // ---- Layer 3: bf16 m16n8k16, 3-term ----
            float d3v[2][4];
#pragma unroll
            for (int n3 = 0; n3 < 2; n3++) {
                const float2 bb = *reinterpret_cast<const float2*>(
                    sb3 + n3 * 8 + 2 * j);
                d3v[n3][0] = bb.x; d3v[n3][1] = bb.y;
                d3v[n3][2] = bb.x; d3v[n3][3] = bb.y;
            }
#pragma unroll
            for (int s = 0; s < 2; s++) {
#pragma unroll
                for (int n3 = 0; n3 < 2; n3++) {
                    uint4 bw = sW3b[(s * 2 + n3) * 32 + lane];
                    mma_bf16(d3v[n3][0], d3v[n3][1], d3v[n3][2], d3v[n3][3],
                             A3h[s][0], A3h[s][1], A3h[s][2], A3h[s][3],
                             bw.x, bw.y);
                    mma_bf16(d3v[n3][0], d3v[n3][1], d3v[n3][2], d3v[n3][3],
                             A3h[s][0], A3h[s][1], A3h[s][2], A3h[s][3],
                             bw.z, bw.w);
                    mma_bf16(d3v[n3][0], d3v[n3][1], d3v[n3][2], d3v[n3][3],
                             A3l[s][0], A3l[s][1], A3l[s][2], A3l[s][3],
                             bw.x, bw.y);
                }
            }

            // ---- stats + stage out ----
            const bool fullTile = (tb + 16 <= E);
#pragma unroll
            for (int n3 = 0; n3 < 2; n3++) {
                const int cb2 = n3 * 8 + 2 * j;
#pragma unroll
                for (int hrow = 0; hrow < 2; hrow++) {
                    float v0 = d3v[n3][2*hrow];
                    float v1 = d3v[n3][2*hrow + 1];
                    const int rr = g + 8 * hrow;
                    if (fullTile || (tb + rr < E)) {
                        lsum4[n3*2+0] += v0;
                        lsum4[n3*2+1] += v1;
                        lsq4[n3*2+0]   = fmaf(v0, v0, lsq4[n3*2+0]);
                        lsq4[n3*2+1]   = fmaf(v1, v1, lsq4[n3*2+1]);
                    }
                    *reinterpret_cast<float2*>(outs + rr * OUT_PAD + cb2) =
                        make_float2(v0, v1);
                }
            }
            __syncwarp();

            // ---- transposed scatter: 4 lanes cover one node's 64B ----
            {
                const int slot = lane >> 2;           // 0..7
                const int q    = lane & 3;
#pragma unroll
                for (int it = 0; it < 4; it++) {
                    const int rec  = it * 8 + slot;   // 0..31
                    const int le   = rec & 15;
                    const int side = rec >> 4;
                    const int src  = t * 16 + le;
                    const int nr = __shfl_sync(0xffffffffu, r, src);
                    const int nc = __shfl_sync(0xffffffffu, c, src);
                    const int node = side ? nc : nr;
                    if (tb + le < E) {
                        float4 v = outs4[le * 5 + q];
                        atomicAdd(reinterpret_cast<float4*>(
                            &g_node_acc[(size_t)node * 16]) + q, v);
                    }
                }
                // degree
                const int le = lane & 15;
                const int src = t * 16 + le;
                const int nr = __shfl_sync(0xffffffffu, r, src);
                const int nc = __shfl_sync(0xffffffffu, c, src);
                const int node = (lane < 16) ? nr : nc;
                if (tb + le < E) atomicAdd(&g_degree[node], 1.0f);
            }
            __syncwarp();
        }
    }

    // ---- BN-stat reduction ----
#pragma unroll
    for (int i = 0; i < 4; i++) {
#pragma unroll
        for (int o = 4; o < 32; o <<= 1) {
            lsum4[i] += __shfl_xor_sync(0xffffffffu, lsum4[i], o);
            lsq4[i]  += __shfl_xor_sync(0xffffffffu, lsq4[i],  o);
        }
    }
    if (lane < 4) {
#pragma unroll
        for (int i = 0; i < 4; i++) {
            const int col = (i >> 1) * 8 + 2 * lane + (i & 1);
            atomicAdd(&g_esum[col], (double)lsum4[i]);
            atomicAdd(&g_esq[col],  (double)lsq4[i]);
        }
    }
}

// ---------------------------------------------------------------------------
__global__ void k_ecoef(const float* __restrict__ g, const float* __restrict__ b,
                        int E)
{
    int j = threadIdx.x;
    if (j < 16) {
        double invE = 1.0 / (double)E;
        double m = g_esum[j] * invE;
        double v = g_esq[j] * invE - m * m;
        double s = (double)g[j] / sqrt(v + 1e-5);
        g_es[j] = (float)s;
        g_et[j] = (float)((double)b[j] - m * s);
    }
}

// ---------------------------------------------------------------------------
__global__ __launch_bounds__(256)
void k_node(const float* __restrict__ Wp, const float* __restrict__ bp,
            int N, float* __restrict__ out)
{
    __shared__ float sWp[256], sbp[16], ses[16], set_[16];
    __shared__ float redS[8][16], redQ[8][16];
    if (threadIdx.x < 256) sWp[threadIdx.x] = Wp[threadIdx.x];
    if (threadIdx.x < 16) {
        sbp[threadIdx.x]  = bp[threadIdx.x];
        ses[threadIdx.x]  = g_es[threadIdx.x];
        set_[threadIdx.x] = g_et[threadIdx.x];
    }
    __syncthreads();

    float lsum[16], lsq[16];
#pragma unroll
    for (int k = 0; k < 16; k++) { lsum[k] = 0.0f; lsq[k] = 0.0f; }

    const int n = blockIdx.x * blockDim.x + threadIdx.x;
    if (n < N) {
        const float deg  = g_degree[n];
        const float invd = 1.0f / fmaxf(deg, 1.0f);
        float pre[16];
#pragma unroll
        for (int j = 0; j < 16; j++) {
            const float a = g_node_acc[n * 16 + j];
            pre[j] = (ses[j] * a + set_[j] * deg) * invd;
        }
        float y[16];
#pragma unroll
        for (int k = 0; k < 16; k++) y[k] = sbp[k];
#pragma unroll
        for (int j = 0; j < 16; j++)
#pragma unroll
            for (int k = 0; k < 16; k++) y[k] = fmaf(pre[j], sWp[j*16 + k], y[k]);
#pragma unroll
        for (int k = 0; k < 16; k++) {
            out[n * 16 + k] = y[k];
            lsum[k] = y[k];
            lsq[k]  = y[k] * y[k];
        }
    }

#pragma unroll
    for (int k = 0; k < 16; k++) {
        float s = lsum[k], q = lsq[k];
#pragma unroll
        for (int o = 16; o > 0; o >>= 1) {
            s += __shfl_xor_sync(0xffffffffu, s, o);
            q += __shfl_xor_sync(0xffffffffu, q, o);
        }
        if ((threadIdx.x & 31) == 0) {
            redS[threadIdx.x >> 5][k] = s;
            redQ[threadIdx.x >> 5][k] = q;
        }
    }
    __syncthreads();
    if (threadIdx.x < 16) {
        double s = 0.0, q = 0.0;
#pragma unroll
        for (int w = 0; w < 8; w++) { s += (double)redS[w][threadIdx.x];
                                      q += (double)redQ[w][threadIdx.x]; }
        atomicAdd(&g_nsum[threadIdx.x], s);
        atomicAdd(&g_nsq[threadIdx.x],  q);
    }
}

// ---------------------------------------------------------------------------
__global__ void k_ncoef(const float* __restrict__ g, const float* __restrict__ b,
                        int N)
{
    int j = threadIdx.x;
    if (j < 16) {
        double invN = 1.0 / (double)N;
        double m = g_nsum[j] * invN;
        double v = g_nsq[j] * invN - m * m;
        double s = (double)g[j] / sqrt(v + 1e-5);
        g_ns[j] = (float)s;
        g_nt[j] = (float)((double)b[j] - m * s);
    }
}

// ---------------------------------------------------------------------------
__global__ void k_norm(float* __restrict__ out, int total)
{
    int i = blockIdx.x * blockDim.x + threadIdx.x;
    if (i < total) {
        int j = i & 15;
        out[i] = fmaf(out[i], g_ns[j], g_nt[j]);
    }
}

// ---------------------------------------------------------------------------
extern "C" void kernel_launch(void* const* d_in, const int* in_sizes, int n_in,
                              void* d_out, int out_size)
{
    const float* coords  = (const float*)d_in[0];
    const float* normals = (const float*)d_in[1];
    const float* curv    = (const float*)d_in[2];
    const int*   ei      = (const int*)d_in[3];
    const float* W1 = (const float*)d_in[4];
    const float* b1 = (const float*)d_in[5];
    const float* W2 = (const float*)d_in[6];
    const float* b2 = (const float*)d_in[7];
    const float* W3 = (const float*)d_in[8];
    const float* b3 = (const float*)d_in[9];
    const float* Wp = (const float*)d_in[10];
    const float* bp = (const float*)d_in[11];
    const float* beg = (const float*)d_in[12];
    const float* beb = (const float*)d_in[13];
    const float* bng = (const float*)d_in[14];
    const float* bnb = (const float*)d_in[15];

    const int N = in_sizes[0] / 3;
    const int E = in_sizes[3] / 2;
    const int* row = ei;
    const int* col = ei + E;
    float* out = (float*)d_out;

    const int smemBytes = (OFF_WARP + NWARP * WARP_FLOATS) * 4;  // ~41.5 KB

    k_zero<<<(N * 16 + 255) / 256, 256>>>(N);                       // launch 1
    k_pack<<<(N + 255) / 256, 256>>>(coords, normals, curv, N);     // launch 2
    k_dummy<<<1, 32>>>();                                           // launch 3
    k_edge<<<296, NTHR, smemBytes>>>(row, col, W1, b1, W2, b2,      // launch 4
                                     W3, b3, E, N);
    k_ecoef<<<1, 32>>>(beg, beb, E);
    k_node<<<(N + 255) / 256, 256>>>(Wp, bp, N, out);
    k_ncoef<<<1, 32>>>(bng, bnb, N);
    k_norm<<<(N * 16 + 255) / 256, 256>>>(out, N * 16);
}

// round 9
// speedup vs baseline: 1.8412x; 1.2242x over previous
#include <cuda_runtime.h>
#include <cuda_bf16.h>
#include <cuda_fp16.h>
#include <cstdint>

// ---------------------------------------------------------------------------
// GPUManifoldFeatureEncoder — round 9:
//   * full layer fusion across both 16-edge tiles: every weight fragment
//     LDS serves 32 edges (halves weight L1 wavefronts)
//   * gelu LUT compacted to f16x2 (delta = gelu - relu, + slope) -> LDS.32,
//     tail selects eliminated (delta->0 at both ends)
//   * 192-thr blocks, launch_bounds(192,2): 12 warps/SM @ <=170 regs
// ---------------------------------------------------------------------------

#define MAX_N 131072
typedef uint32_t u32;

__device__ float  g_nodepack[MAX_N * 8];    // x,y,z,nx | ny,nz,c0,c1
__device__ float  g_node_acc[MAX_N * 16];
__device__ float  g_degree[MAX_N];
__device__ double g_esum[16], g_esq[16];
__device__ double g_nsum[16], g_nsq[16];
__device__ float  g_es[16], g_et[16];
__device__ float  g_ns[16], g_nt[16];

__device__ __forceinline__ float gelu_exact(float x) {
    return 0.5f * x * (1.0f + erff(x * 0.70710678118654752440f));
}
__device__ __forceinline__ void split_tf32(float x, u32& hi, u32& lo) {
    asm("cvt.rna.tf32.f32 %0, %1;" : "=r"(hi) : "f"(x));
    float rem = x - __uint_as_float(hi);
    asm("cvt.rna.tf32.f32 %0, %1;" : "=r"(lo) : "f"(rem));
}
__device__ __forceinline__ void bfpair(float y0, float y1, u32& hp, u32& lp) {
    u32 h; asm("cvt.rn.bf16x2.f32 %0, %1, %2;" : "=r"(h) : "f"(y1), "f"(y0));
    float h0 = __uint_as_float(h << 16);
    float h1 = __uint_as_float(h & 0xFFFF0000u);
    u32 l; asm("cvt.rn.bf16x2.f32 %0, %1, %2;" : "=r"(l) : "f"(y1 - h1), "f"(y0 - h0));
    hp = h; lp = l;
}
__device__ __forceinline__ void mma_tf32(float& d0, float& d1, float& d2, float& d3,
                                         u32 a0, u32 a1, u32 a2, u32 a3,
                                         u32 b0, u32 b1) {
    asm("mma.sync.aligned.m16n8k8.row.col.f32.tf32.tf32.f32 "
        "{%0,%1,%2,%3}, {%4,%5,%6,%7}, {%8,%9}, {%0,%1,%2,%3};"
        : "+f"(d0), "+f"(d1), "+f"(d2), "+f"(d3)
        : "r"(a0), "r"(a1), "r"(a2), "r"(a3), "r"(b0), "r"(b1));
}
__device__ __forceinline__ void mma_bf16(float& d0, float& d1, float& d2, float& d3,
                                         u32 a0, u32 a1, u32 a2, u32 a3,
                                         u32 b0, u32 b1) {
    asm("mma.sync.aligned.m16n8k16.row.col.f32.bf16.bf16.f32 "
        "{%0,%1,%2,%3}, {%4,%5,%6,%7}, {%8,%9}, {%0,%1,%2,%3};"
        : "+f"(d0), "+f"(d1), "+f"(d2), "+f"(d3)
        : "r"(a0), "r"(a1), "r"(a2), "r"(a3), "r"(b0), "r"(b1));
}
// gelu via f16x2 delta-LUT: y = relu(x) + lerp(delta)
__device__ __forceinline__ float gelu_lut(float x, const u32* __restrict__ slut) {
    float tt = fminf(fmaxf(fmaf(x, 64.0f, 512.0f), 0.0f), 1022.999f);
    int i = (int)tt;
    float fr = tt - (float)i;
    u32 e = slut[i];
    __half2 h2 = *reinterpret_cast<const __half2*>(&e);
    float2 bs = __half22float2(h2);   // .x = delta base, .y = delta slope
    return fmaxf(x, 0.0f) + fmaf(fr, bs.y, bs.x);
}

// ---------------------------------------------------------------------------
__global__ void k_zero(int N) {
    int i = blockIdx.x * blockDim.x + threadIdx.x;
    int tot = N * 16;
    if (i < tot) g_node_acc[i] = 0.0f;
    if (i < N)   g_degree[i]   = 0.0f;
    if (i < 16) {
        g_esum[i] = 0.0; g_esq[i] = 0.0;
        g_nsum[i] = 0.0; g_nsq[i] = 0.0;
    }
}

__global__ void k_pack(const float* __restrict__ coords,
                       const float* __restrict__ normals,
                       const float* __restrict__ curv, int N)
{
    int n = blockIdx.x * blockDim.x + threadIdx.x;
    if (n < N) {
        float4 a = make_float4(coords[3*n+0], coords[3*n+1], coords[3*n+2],
                               normals[3*n+0]);
        float4 b = make_float4(normals[3*n+1], normals[3*n+2],
                               curv[4*n+0], curv[4*n+1]);
        *reinterpret_cast<float4*>(&g_nodepack[8*n])     = a;
        *reinterpret_cast<float4*>(&g_nodepack[8*n + 4]) = b;
    }
}

__global__ void k_dummy() {}

// ---------------------------------------------------------------------------
#define OFF_W1   0
#define OFF_W2   1024
#define OFF_W3   3072
#define OFF_B1   3584
#define OFF_B2   3648
#define OFF_B3   3680
#define OFF_LUT  3712
#define OFF_WARP 4736
#define WARP_FLOATS 576
#define OUT_PAD 20
#define NWARP 6
#define NTHR  192

__global__ __launch_bounds__(NTHR, 2)
void k_edge(const int* __restrict__ rowi,
            const int* __restrict__ coli,
            const float* __restrict__ W1, const float* __restrict__ b1,
            const float* __restrict__ W2, const float* __restrict__ b2,
            const float* __restrict__ W3, const float* __restrict__ b3,
            int E, int N)
{
    extern __shared__ float sm[];
    float4* sW1f = reinterpret_cast<float4*>(sm + OFF_W1);
    uint4*  sW2b = reinterpret_cast<uint4*>(sm + OFF_W2);
    uint4*  sW3b = reinterpret_cast<uint4*>(sm + OFF_W3);
    float*  sb1  = sm + OFF_B1;
    float*  sb2  = sm + OFF_B2;
    float*  sb3  = sm + OFF_B3;
    u32*    slut = reinterpret_cast<u32*>(sm + OFF_LUT);

    const int tid  = threadIdx.x;
    const int lane = tid & 31;
    const int wid  = tid >> 5;
    const int g    = lane >> 2;
    const int j    = lane & 3;

    // ---- preamble ----
    for (int idx = tid; idx < 8 * 32; idx += NTHR) {       // W1 tf32 hi/lo
        int nt = idx >> 5, t = idx & 31;
        int kk = t & 3, nn = nt * 8 + (t >> 2);
        float w0 = W1[kk * 64 + nn], w1 = W1[(kk + 4) * 64 + nn];
        u32 h0, l0, h1_, l1; split_tf32(w0, h0, l0); split_tf32(w1, h1_, l1);
        sW1f[idx] = make_float4(__uint_as_float(h0), __uint_as_float(h1_),
                                __uint_as_float(l0), __uint_as_float(l1));
    }
    for (int idx = tid; idx < 16 * 32; idx += NTHR) {      // W2 bf16 hi/lo pairs
        int combo = idx >> 5, t = idx & 31;
        int s = combo >> 2, nt = combo & 3;
        int g2 = t >> 2, j2 = t & 3;
        int nn = nt * 8 + g2;
        int k0 = s * 16 + 2 * j2;
        float w00 = W2[(k0    ) * 32 + nn], w01 = W2[(k0 + 1) * 32 + nn];
        float w10 = W2[(k0 + 8) * 32 + nn], w11 = W2[(k0 + 9) * 32 + nn];
        u32 h0p, l0p, h1p, l1p;
        bfpair(w00, w01, h0p, l0p);
        bfpair(w10, w11, h1p, l1p);
        sW2b[idx] = make_uint4(h0p, h1p, l0p, l1p);
    }
    for (int idx = tid; idx < 4 * 32; idx += NTHR) {       // W3 bf16 hi/lo pairs
        int combo = idx >> 5, t = idx & 31;
        int s = combo >> 1, nt = combo & 1;
        int g2 = t >> 2, j2 = t & 3;
        int nn = nt * 8 + g2;
        int k0 = s * 16 + 2 * j2;
        float w00 = W3[(k0    ) * 16 + nn], w01 = W3[(k0 + 1) * 16 + nn];
        float w10 = W3[(k0 + 8) * 16 + nn], w11 = W3[(k0 + 9) * 16 + nn];
        u32 h0p, l0p, h1p, l1p;
        bfpair(w00, w01, h0p, l0p);
        bfpair(w10, w11, h1p, l1p);
        sW3b[idx] = make_uint4(h0p, h1p, l0p, l1p);
    }
    if (tid < 64) sb1[tid] = b1[tid];
    if (tid < 32) sb2[tid] = b2[tid];
    if (tid < 16) sb3[tid] = b3[tid];
    for (int i = tid; i < 1024; i += NTHR) {    // delta-gelu LUT (f16x2)
        float x0 = (float)(i - 512) * 0.015625f;
        float x1 = x0 + 0.015625f;
        float d0 = gelu_exact(x0) - fmaxf(x0, 0.0f);
        float d1 = gelu_exact(x1) - fmaxf(x1, 0.0f);
        float sl = d1 - d0;
        u32 packed;
        asm("cvt.rn.f16x2.f32 %0, %1, %2;" : "=r"(packed) : "f"(sl), "f"(d0));
        slut[i] = packed;
    }
    __syncthreads();

    float* efs  = sm + OFF_WARP + wid * WARP_FLOATS;  // [32][8]
    float* outs = efs + 256;                          // [16][20]
    float4* outs4 = reinterpret_cast<float4*>(outs);

    float lsum4[4] = {0, 0, 0, 0}, lsq4[4] = {0, 0, 0, 0};

    const int tiles32 = (E + 31) >> 5;
    const int warpsTotal = gridDim.x * NWARP;
    const int warpGlobal = blockIdx.x * NWARP + wid;

    // ---- software pipeline: preload first iteration's gather ----
    int   pr = 0, pc = 0;
    float4 pra, prb, pca, pcb;
    if (warpGlobal < tiles32) {
        const int e = (warpGlobal << 5) + lane;
        const bool ev = (e < E);
        int r0 = ev ? rowi[e] : 0;
        int c0 = ev ? coli[e] : 0;
        if ((unsigned)r0 >= (unsigned)N) r0 = 0;
        if ((unsigned)c0 >= (unsigned)N) c0 = 0;
        pr = r0; pc = c0;
        pra = *reinterpret_cast<const float4*>(&g_nodepack[8*r0]);
        prb = *reinterpret_cast<const float4*>(&g_nodepack[8*r0+4]);
        pca = *reinterpret_cast<const float4*>(&g_nodepack[8*c0]);
        pcb = *reinterpret_cast<const float4*>(&g_nodepack[8*c0+4]);
    }

    for (int tb32 = warpGlobal; tb32 < tiles32; tb32 += warpsTotal) {
        const int ebase = tb32 << 5;
        const int r = pr, c = pc;
        const float4 ra = pra, rb = prb, ca = pca, cb = pcb;

        {   // geometry from prefetched registers -> stage ef to smem
            const float dx = ca.x - ra.x, dy = ca.y - ra.y, dz = ca.z - ra.z;
            const float nrx = ra.w, nry = rb.x, nrz = rb.y;
            const float ncx = ca.w, ncy = cb.x, ncz = cb.y;
            const float ndot = nrx*ncx + nry*ncy + nrz*ncz;
            const float dn = sqrtf(dx*dx + dy*dy + dz*dz) + 1e-8f;
            const float inv = 1.0f / dn;
            float cr = fminf(1.0f, fmaxf(-1.0f, (nrx*dx+nry*dy+nrz*dz)*inv));
            float cc = fminf(1.0f, fmaxf(-1.0f, (ncx*dx+ncy*dy+ncz*dz)*inv));
            float4* er = reinterpret_cast<float4*>(efs + lane * 8);
            er[0] = make_float4(dx, dy, dz, ndot);
            er[1] = make_float4(cr, cc, cb.z - rb.z, cb.w - rb.w);
        }

        // issue next iteration's gather now (overlaps MMA phases)
        {
            const int nt32 = tb32 + warpsTotal;
            if (nt32 < tiles32) {
                const int e = (nt32 << 5) + lane;
                const bool ev = (e < E);
                int r0 = ev ? rowi[e] : 0;
                int c0 = ev ? coli[e] : 0;
                if ((unsigned)r0 >= (unsigned)N) r0 = 0;
                if ((unsigned)c0 >= (unsigned)N) c0 = 0;
                pr = r0; pc = c0;
                pra = *reinterpret_cast<const float4*>(&g_nodepack[8*r0]);
                prb = *reinterpret_cast<const float4*>(&g_nodepack[8*r0+4]);
                pca = *reinterpret_cast<const float4*>(&g_nodepack[8*c0]);
                pcb = *reinterpret_cast<const float4*>(&g_nodepack[8*c0+4]);
            }
        }
        __syncwarp();

        // ---- Layer 1 (both tiles share each W1 fragment load) ----
        u32 ahA[4], alA[4], ahB[4], alB[4];
        {
            const float* b0 = efs;
            split_tf32(b0[(g    )*8 + j    ], ahA[0], alA[0]);
            split_tf32(b0[(g + 8)*8 + j    ], ahA[1], alA[1]);
            split_tf32(b0[(g    )*8 + j + 4], ahA[2], alA[2]);
            split_tf32(b0[(g + 8)*8 + j + 4], ahA[3], alA[3]);
            const float* b1f = efs + 128;
            split_tf32(b1f[(g    )*8 + j    ], ahB[0], alB[0]);
            split_tf32(b1f[(g + 8)*8 + j    ], ahB[1], alB[1]);
            split_tf32(b1f[(g    )*8 + j + 4], ahB[2], alB[2]);
            split_tf32(b1f[(g + 8)*8 + j + 4], ahB[3], alB[3]);
        }
        u32 A2h[2][4][4], A2l[2][4][4];
#pragma unroll
        for (int nt = 0; nt < 8; nt++) {
            const float2 bb = *reinterpret_cast<const float2*>(sb1 + nt * 8 + 2 * j);
            float4 bw = sW1f[nt * 32 + lane];
            u32 bh0 = __float_as_uint(bw.x), bh1 = __float_as_uint(bw.y);
            u32 bl0 = __float_as_uint(bw.z), bl1 = __float_as_uint(bw.w);
            const int s = nt >> 1, half = nt & 1;
#pragma unroll
            for (int t = 0; t < 2; t++) {
                float d0 = bb.x, d1 = bb.y, d2 = bb.x, d3 = bb.y;
                const u32* ah = t ? ahB : ahA;
                const u32* al = t ? alB : alA;
                mma_tf32(d0, d1, d2, d3, ah[0], ah[1], ah[2], ah[3], bh0, bh1);
                mma_tf32(d0, d1, d2, d3, al[0], al[1], al[2], al[3], bh0, bh1);
                mma_tf32(d0, d1, d2, d3, ah[0], ah[1], ah[2], ah[3], bl0, bl1);
                float y0 = gelu_lut(d0, slut);
                float y1 = gelu_lut(d1, slut);
                float y2 = gelu_lut(d2, slut);
                float y3 = gelu_lut(d3, slut);
                u32 hp, lp;
                bfpair(y0, y1, hp, lp);
                A2h[t][s][half * 2 + 0] = hp; A2l[t][s][half * 2 + 0] = lp;
                bfpair(y2, y3, hp, lp);
                A2h[t][s][half * 2 + 1] = hp; A2l[t][s][half * 2 + 1] = lp;
            }
        }

        // ---- Layer 2 (shared W2 fragment loads) ----
        float d2v[2][4][4];
#pragma unroll
        for (int n2 = 0; n2 < 4; n2++) {
            const float2 bb = *reinterpret_cast<const float2*>(sb2 + n2 * 8 + 2 * j);
#pragma unroll
            for (int t = 0; t < 2; t++) {
                d2v[t][n2][0] = bb.x; d2v[t][n2][1] = bb.y;
                d2v[t][n2][2] = bb.x; d2v[t][n2][3] = bb.y;
            }
        }
#pragma unroll
        for (int s = 0; s < 4; s++) {
#pragma unroll
            for (int n2 = 0; n2 < 4; n2++) {
                uint4 bw = sW2b[(s * 4 + n2) * 32 + lane];
#pragma unroll
                for (int t = 0; t < 2; t++) {
                    mma_bf16(d2v[t][n2][0], d2v[t][n2][1], d2v[t][n2][2], d2v[t][n2][3],
                             A2h[t][s][0], A2h[t][s][1], A2h[t][s][2], A2h[t][s][3],
                             bw.x, bw.y);
                    mma_bf16(d2v[t][n2][0], d2v[t][n2][1], d2v[t][n2][2], d2v[t][n2][3],
                             A2h[t][s][0], A2h[t][s][1], A2h[t][s][2], A2h[t][s][3],
                             bw.z, bw.w);
                    mma_bf16(d2v[t][n2][0], d2v[t][n2][1], d2v[t][n2][2], d2v[t][n2][3],
                             A2l[t][s][0], A2l[t][s][1], A2l[t][s][2], A2l[t][s][3],
                             bw.x, bw.y);
                }
            }
        }
        u32 A3h[2][2][4], A3l[2][2][4];
#pragma unroll
        for (int t = 0; t < 2; t++) {
#pragma unroll
            for (int n2 = 0; n2 < 4; n2++) {
                float y0 = gelu_lut(d2v[t][n2][0], slut);
                float y1 = gelu_lut(d2v[t][n2][1], slut);
                float y2 = gelu_lut(d2v[t][n2][2], slut);
                float y3 = gelu_lut(d2v[t][n2][3], slut);
                const int s = n2 >> 1, half = n2 & 1;
                u32 hp, lp;
                bfpair(y0, y1, hp, lp);
                A3h[t][s][half * 2 + 0] = hp; A3l[t][s][half * 2 + 0] = lp;
                bfpair(y2, y3, hp, lp);
                A3h[t][s][half * 2 + 1] = hp; A3l[t][s][half * 2 + 1] = lp;
            }
        }

        // ---- Layer 3 (shared W3 fragment loads) ----
        float d3v[2][2][4];
#pragma unroll
        for (int n3 = 0; n3 < 2; n3++) {
            const float2 bb = *reinterpret_cast<const float2*>(sb3 + n3 * 8 + 2 * j);
#pragma unroll
            for (int t = 0; t < 2; t++) {
                d3v[t][n3][0] = bb.x; d3v[t][n3][1] = bb.y;
                d3v[t][n3][2] = bb.x; d3v[t][n3][3] = bb.y;
            }
        }
#pragma unroll
        for (int s = 0; s < 2; s++) {
#pragma unroll
            for (int n3 = 0; n3 < 2; n3++) {
                uint4 bw = sW3b[(s * 2 + n3) * 32 + lane];
#pragma unroll
                for (int t = 0; t < 2; t++) {
                    mma_bf16(d3v[t][n3][0], d3v[t][n3][1], d3v[t][n3][2], d3v[t][n3][3],
                             A3h[t][s][0], A3h[t][s][1], A3h[t][s][2], A3h[t][s][3],
                             bw.x, bw.y);
                    mma_bf16(d3v[t][n3][0], d3v[t][n3][1], d3v[t][n3][2], d3v[t][n3][3],
                             A3h[t][s][0], A3h[t][s][1], A3h[t][s][2], A3h[t][s][3],
                             bw.z, bw.w);
                    mma_bf16(d3v[t][n3][0], d3v[t][n3][1], d3v[t][n3][2], d3v[t][n3][3],
                             A3l[t][s][0], A3l[t][s][1], A3l[t][s][2], A3l[t][s][3],
                             bw.x, bw.y);
                }
            }
        }

        // ---- per-tile epilogue: stats + stage + scatter ----
#pragma unroll
        for (int t = 0; t < 2; t++) {
            const int tb = ebase + t * 16;
            const bool fullTile = (tb + 16 <= E);
#pragma unroll
            for (int n3 = 0; n3 < 2; n3++) {
                const int cb2 = n3 * 8 + 2 * j;
#pragma unroll
                for (int hrow = 0; hrow < 2; hrow++) {
                    float v0 = d3v[t][n3][2*hrow];
                    float v1 = d3v[t][n3][2*hrow + 1];
                    const int rr = g + 8 * hrow;
                    if (fullTile || (tb + rr < E)) {
                        lsum4[n3*2+0] += v0;
                        lsum4[n3*2+1] += v1;
                        lsq4[n3*2+0]   = fmaf(v0, v0, lsq4[n3*2+0]);
                        lsq4[n3*2+1]   = fmaf(v1, v1, lsq4[n3*2+1]);
                    }
                    *reinterpret_cast<float2*>(outs + rr * OUT_PAD + cb2) =
                        make_float2(v0, v1);
                }
            }
            __syncwarp();

            {   // transposed scatter: 4 lanes cover one node's 64B
                const int slot = lane >> 2;
                const int q    = lane & 3;
#pragma unroll
                for (int it = 0; it < 4; it++) {
                    const int rec  = it * 8 + slot;
                    const int le   = rec & 15;
                    const int side = rec >> 4;
                    const int src  = t * 16 + le;
                    const int nr = __shfl_sync(0xffffffffu, r, src);
                    const int nc = __shfl_sync(0xffffffffu, c, src);
                    const int node = side ? nc : nr;
                    if (tb + le < E) {
                        float4 v = outs4[le * 5 + q];
                        atomicAdd(reinterpret_cast<float4*>(
                            &g_node_acc[(size_t)node * 16]) + q, v);
                    }
                }
                const int le = lane & 15;
                const int src = t * 16 + le;
                const int nr = __shfl_sync(0xffffffffu, r, src);
                const int nc = __shfl_sync(0xffffffffu, c, src);
                const int node = (lane < 16) ? nr : nc;
                if (tb + le < E) atomicAdd(&g_degree[node], 1.0f);
            }
            __syncwarp();
        }
    }

    // ---- BN-stat reduction ----
#pragma unroll
    for (int i = 0; i < 4; i++) {
#pragma unroll
        for (int o = 4; o < 32; o <<= 1) {
            lsum4[i] += __shfl_xor_sync(0xffffffffu, lsum4[i], o);
            lsq4[i]  += __shfl_xor_sync(0xffffffffu, lsq4[i],  o);
        }
    }
    if (lane < 4) {
#pragma unroll
        for (int i = 0; i < 4; i++) {
            const int col = (i >> 1) * 8 + 2 * lane + (i & 1);
            atomicAdd(&g_esum[col], (double)lsum4[i]);
            atomicAdd(&g_esq[col],  (double)lsq4[i]);
        }
    }
}

// ---------------------------------------------------------------------------
__global__ void k_ecoef(const float* __restrict__ g, const float* __restrict__ b,
                        int E)
{
    int j = threadIdx.x;
    if (j < 16) {
        double invE = 1.0 / (double)E;
        double m = g_esum[j] * invE;
        double v = g_esq[j] * invE - m * m;
        double s = (double)g[j] / sqrt(v + 1e-5);
        g_es[j] = (float)s;
        g_et[j] = (float)((double)b[j] - m * s);
    }
}

// ---------------------------------------------------------------------------
__global__ __launch_bounds__(256)
void k_node(const float* __restrict__ Wp, const float* __restrict__ bp,
            int N, float* __restrict__ out)
{
    __shared__ float sWp[256], sbp[16], ses[16], set_[16];
    __shared__ float redS[8][16], redQ[8][16];
    if (threadIdx.x < 256) sWp[threadIdx.x] = Wp[threadIdx.x];
    if (threadIdx.x < 16) {
        sbp[threadIdx.x]  = bp[threadIdx.x];
        ses[threadIdx.x]  = g_es[threadIdx.x];
        set_[threadIdx.x] = g_et[threadIdx.x];
    }
    __syncthreads();

    float lsum[16], lsq[16];
#pragma unroll
    for (int k = 0; k < 16; k++) { lsum[k] = 0.0f; lsq[k] = 0.0f; }

    const int n = blockIdx.x * blockDim.x + threadIdx.x;
    if (n < N) {
        const float deg  = g_degree[n];
        const float invd = 1.0f / fmaxf(deg, 1.0f);
        float pre[16];
#pragma unroll
        for (int j = 0; j < 16; j++) {
            const float a = g_node_acc[n * 16 + j];
            pre[j] = (ses[j] * a + set_[j] * deg) * invd;
        }
        float y[16];
#pragma unroll
        for (int k = 0; k < 16; k++) y[k] = sbp[k];
#pragma unroll
        for (int j = 0; j < 16; j++)
#pragma unroll
            for (int k = 0; k < 16; k++) y[k] = fmaf(pre[j], sWp[j*16 + k], y[k]);
#pragma unroll
        for (int k = 0; k < 16; k++) {
            out[n * 16 + k] = y[k];
            lsum[k] = y[k];
            lsq[k]  = y[k] * y[k];
        }
    }

#pragma unroll
    for (int k = 0; k < 16; k++) {
        float s = lsum[k], q = lsq[k];
#pragma unroll
        for (int o = 16; o > 0; o >>= 1) {
            s += __shfl_xor_sync(0xffffffffu, s, o);
            q += __shfl_xor_sync(0xffffffffu, q, o);
        }
        if ((threadIdx.x & 31) == 0) {
            redS[threadIdx.x >> 5][k] = s;
            redQ[threadIdx.x >> 5][k] = q;
        }
    }
    __syncthreads();
    if (threadIdx.x < 16) {
        double s = 0.0, q = 0.0;
#pragma unroll
        for (int w = 0; w < 8; w++) { s += (double)redS[w][threadIdx.x];
                                      q += (double)redQ[w][threadIdx.x]; }
        atomicAdd(&g_nsum[threadIdx.x], s);
        atomicAdd(&g_nsq[threadIdx.x],  q);
    }
}

// ---------------------------------------------------------------------------
__global__ void k_ncoef(const float* __restrict__ g, const float* __restrict__ b,
                        int N)
{
    int j = threadIdx.x;
    if (j < 16) {
        double invN = 1.0 / (double)N;
        double m = g_nsum[j] * invN;
        double v = g_nsq[j] * invN - m * m;
        double s = (double)g[j] / sqrt(v + 1e-5);
        g_ns[j] = (float)s;
        g_nt[j] = (float)((double)b[j] - m * s);
    }
}

// ---------------------------------------------------------------------------
__global__ void k_norm(float* __restrict__ out, int total)
{
    int i = blockIdx.x * blockDim.x + threadIdx.x;
    if (i < total) {
        int j = i & 15;
        out[i] = fmaf(out[i], g_ns[j], g_nt[j]);
    }
}

// ---------------------------------------------------------------------------
extern "C" void kernel_launch(void* const* d_in, const int* in_sizes, int n_in,
                              void* d_out, int out_size)
{
    const float* coords  = (const float*)d_in[0];
    const float* normals = (const float*)d_in[1];
    const float* curv    = (const float*)d_in[2];
    const int*   ei      = (const int*)d_in[3];
    const float* W1 = (const float*)d_in[4];
    const float* b1 = (const float*)d_in[5];
    const float* W2 = (const float*)d_in[6];
    const float* b2 = (const float*)d_in[7];
    const float* W3 = (const float*)d_in[8];
    const float* b3 = (const float*)d_in[9];
    const float* Wp = (const float*)d_in[10];
    const float* bp = (const float*)d_in[11];
    const float* beg = (const float*)d_in[12];
    const float* beb = (const float*)d_in[13];
    const float* bng = (const float*)d_in[14];
    const float* bnb = (const float*)d_in[15];

    const int N = in_sizes[0] / 3;
    const int E = in_sizes[3] / 2;
    const int* row = ei;
    const int* col = ei + E;
    float* out = (float*)d_out;

    const int smemBytes = (OFF_WARP + NWARP * WARP_FLOATS) * 4;  // 32 KB

    k_zero<<<(N * 16 + 255) / 256, 256>>>(N);                       // launch 1
    k_pack<<<(N + 255) / 256, 256>>>(coords, normals, curv, N);     // launch 2
    k_dummy<<<1, 32>>>();                                           // launch 3
    k_edge<<<296, NTHR, smemBytes>>>(row, col, W1, b1, W2, b2,      // launch 4
                                     W3, b3, E, N);
    k_ecoef<<<1, 32>>>(beg, beb, E);
    k_node<<<(N + 255) / 256, 256>>>(Wp, bp, N, out);
    k_ncoef<<<1, 32>>>(bng, bnb, N);
    k_norm<<<(N * 16 + 255) / 256, 256>>>(out, N * 16);
}

// round 10
// speedup vs baseline: 1.8577x; 1.0089x over previous
#include <cuda_runtime.h>
#include <cuda_bf16.h>
#include <cuda_fp16.h>
#include <cstdint>

// ---------------------------------------------------------------------------
// GPUManifoldFeatureEncoder — round 10:
//   * bank-replicated gelu delta-LUT: 512 entries x 32 copies, layout
//     lut[idx*32+lane] -> every LDS.32 conflict-free (was ~3.5 wf each)
//   * two-phase LUT init (compute once, broadcast-replicate)
//   * everything else as round 9 (fused 32-edge layers, bf16 3-term MMA,
//     transposed scatter, prefetch pipeline)
// ---------------------------------------------------------------------------

#define MAX_N 131072
typedef uint32_t u32;

__device__ float  g_nodepack[MAX_N * 8];    // x,y,z,nx | ny,nz,c0,c1
__device__ float  g_node_acc[MAX_N * 16];
__device__ float  g_degree[MAX_N];
__device__ double g_esum[16], g_esq[16];
__device__ double g_nsum[16], g_nsq[16];
__device__ float  g_es[16], g_et[16];
__device__ float  g_ns[16], g_nt[16];

__device__ __forceinline__ float gelu_exact(float x) {
    return 0.5f * x * (1.0f + erff(x * 0.70710678118654752440f));
}
__device__ __forceinline__ void split_tf32(float x, u32& hi, u32& lo) {
    asm("cvt.rna.tf32.f32 %0, %1;" : "=r"(hi) : "f"(x));
    float rem = x - __uint_as_float(hi);
    asm("cvt.rna.tf32.f32 %0, %1;" : "=r"(lo) : "f"(rem));
}
__device__ __forceinline__ void bfpair(float y0, float y1, u32& hp, u32& lp) {
    u32 h; asm("cvt.rn.bf16x2.f32 %0, %1, %2;" : "=r"(h) : "f"(y1), "f"(y0));
    float h0 = __uint_as_float(h << 16);
    float h1 = __uint_as_float(h & 0xFFFF0000u);
    u32 l; asm("cvt.rn.bf16x2.f32 %0, %1, %2;" : "=r"(l) : "f"(y1 - h1), "f"(y0 - h0));
    hp = h; lp = l;
}
__device__ __forceinline__ void mma_tf32(float& d0, float& d1, float& d2, float& d3,
                                         u32 a0, u32 a1, u32 a2, u32 a3,
                                         u32 b0, u32 b1) {
    asm("mma.sync.aligned.m16n8k8.row.col.f32.tf32.tf32.f32 "
        "{%0,%1,%2,%3}, {%4,%5,%6,%7}, {%8,%9}, {%0,%1,%2,%3};"
        : "+f"(d0), "+f"(d1), "+f"(d2), "+f"(d3)
        : "r"(a0), "r"(a1), "r"(a2), "r"(a3), "r"(b0), "r"(b1));
}
__device__ __forceinline__ void mma_bf16(float& d0, float& d1, float& d2, float& d3,
                                         u32 a0, u32 a1, u32 a2, u32 a3,
                                         u32 b0, u32 b1) {
    asm("mma.sync.aligned.m16n8k16.row.col.f32.bf16.bf16.f32 "
        "{%0,%1,%2,%3}, {%4,%5,%6,%7}, {%8,%9}, {%0,%1,%2,%3};"
        : "+f"(d0), "+f"(d1), "+f"(d2), "+f"(d3)
        : "r"(a0), "r"(a1), "r"(a2), "r"(a3), "r"(b0), "r"(b1));
}
// gelu via bank-replicated f16x2 delta-LUT: y = relu(x) + lerp(delta(|clamped|))
// lutp = slut + lane  (each lane owns its bank -> conflict-free)
__device__ __forceinline__ float gelu_lut(float x, const u32* __restrict__ lutp) {
    float tt = fminf(fmaxf(fmaf(x, 64.0f, 256.0f), 0.0f), 510.999f);
    int i = (int)tt;
    float fr = tt - (float)i;
    u32 e = lutp[i << 5];
    __half2 h2 = *reinterpret_cast<const __half2*>(&e);
    float2 bs = __half22float2(h2);   // .x = delta base, .y = delta slope
    return fmaxf(x, 0.0f) + fmaf(fr, bs.y, bs.x);
}

// ---------------------------------------------------------------------------
__global__ void k_zero(int N) {
    int i = blockIdx.x * blockDim.x + threadIdx.x;
    int tot = N * 16;
    if (i < tot) g_node_acc[i] = 0.0f;
    if (i < N)   g_degree[i]   = 0.0f;
    if (i < 16) {
        g_esum[i] = 0.0; g_esq[i] = 0.0;
        g_nsum[i] = 0.0; g_nsq[i] = 0.0;
    }
}

__global__ void k_pack(const float* __restrict__ coords,
                       const float* __restrict__ normals,
                       const float* __restrict__ curv, int N)
{
    int n = blockIdx.x * blockDim.x + threadIdx.x;
    if (n < N) {
        float4 a = make_float4(coords[3*n+0], coords[3*n+1], coords[3*n+2],
                               normals[3*n+0]);
        float4 b = make_float4(normals[3*n+1], normals[3*n+2],
                               curv[4*n+0], curv[4*n+1]);
        *reinterpret_cast<float4*>(&g_nodepack[8*n])     = a;
        *reinterpret_cast<float4*>(&g_nodepack[8*n + 4]) = b;
    }
}

__global__ void k_dummy() {}

// ---------------------------------------------------------------------------
// smem (floats): W1f[1024] W2b[2048] W3b[512] biases[128]
//   LUT (replicated): 512 entries x 32 copies = 16384 u32  @ OFF_LUT
//   per-warp: efs[256] + outs[320]
// ---------------------------------------------------------------------------
#define OFF_W1   0
#define OFF_W2   1024
#define OFF_W3   3072
#define OFF_B1   3584
#define OFF_B2   3648
#define OFF_B3   3680
#define OFF_LUT  3712
#define OFF_WARP 20096
#define WARP_FLOATS 576
#define OUT_PAD 20
#define NWARP 6
#define NTHR  192

__global__ __launch_bounds__(NTHR, 2)
void k_edge(const int* __restrict__ rowi,
            const int* __restrict__ coli,
            const float* __restrict__ W1, const float* __restrict__ b1,
            const float* __restrict__ W2, const float* __restrict__ b2,
            const float* __restrict__ W3, const float* __restrict__ b3,
            int E, int N)
{
    extern __shared__ float sm[];
    float4* sW1f = reinterpret_cast<float4*>(sm + OFF_W1);
    uint4*  sW2b = reinterpret_cast<uint4*>(sm + OFF_W2);
    uint4*  sW3b = reinterpret_cast<uint4*>(sm + OFF_W3);
    float*  sb1  = sm + OFF_B1;
    float*  sb2  = sm + OFF_B2;
    float*  sb3  = sm + OFF_B3;
    u32*    slut = reinterpret_cast<u32*>(sm + OFF_LUT);

    const int tid  = threadIdx.x;
    const int lane = tid & 31;
    const int wid  = tid >> 5;
    const int g    = lane >> 2;
    const int j    = lane & 3;

    // ---- preamble ----
    for (int idx = tid; idx < 8 * 32; idx += NTHR) {       // W1 tf32 hi/lo
        int nt = idx >> 5, t = idx & 31;
        int kk = t & 3, nn = nt * 8 + (t >> 2);
        float w0 = W1[kk * 64 + nn], w1 = W1[(kk + 4) * 64 + nn];
        u32 h0, l0, h1_, l1; split_tf32(w0, h0, l0); split_tf32(w1, h1_, l1);
        sW1f[idx] = make_float4(__uint_as_float(h0), __uint_as_float(h1_),
                                __uint_as_float(l0), __uint_as_float(l1));
    }
    for (int idx = tid; idx < 16 * 32; idx += NTHR) {      // W2 bf16 hi/lo pairs
        int combo = idx >> 5, t = idx & 31;
        int s = combo >> 2, nt = combo & 3;
        int g2 = t >> 2, j2 = t & 3;
        int nn = nt * 8 + g2;
        int k0 = s * 16 + 2 * j2;
        float w00 = W2[(k0    ) * 32 + nn], w01 = W2[(k0 + 1) * 32 + nn];
        float w10 = W2[(k0 + 8) * 32 + nn], w11 = W2[(k0 + 9) * 32 + nn];
        u32 h0p, l0p, h1p, l1p;
        bfpair(w00, w01, h0p, l0p);
        bfpair(w10, w11, h1p, l1p);
        sW2b[idx] = make_uint4(h0p, h1p, l0p, l1p);
    }
    for (int idx = tid; idx < 4 * 32; idx += NTHR) {       // W3 bf16 hi/lo pairs
        int combo = idx >> 5, t = idx & 31;
        int s = combo >> 1, nt = combo & 1;
        int g2 = t >> 2, j2 = t & 3;
        int nn = nt * 8 + g2;
        int k0 = s * 16 + 2 * j2;
        float w00 = W3[(k0    ) * 16 + nn], w01 = W3[(k0 + 1) * 16 + nn];
        float w10 = W3[(k0 + 8) * 16 + nn], w11 = W3[(k0 + 9) * 16 + nn];
        u32 h0p, l0p, h1p, l1p;
        bfpair(w00, w01, h0p, l0p);
        bfpair(w10, w11, h1p, l1p);
        sW3b[idx] = make_uint4(h0p, h1p, l0p, l1p);
    }
    if (tid < 64) sb1[tid] = b1[tid];
    if (tid < 32) sb2[tid] = b2[tid];
    if (tid < 16) sb3[tid] = b3[tid];

    // ---- two-phase replicated LUT init ----
    // phase 1: compute the 512 entries once into scratch (warp-staging area)
    u32* scratch = reinterpret_cast<u32*>(sm + OFF_WARP);
    for (int i = tid; i < 512; i += NTHR) {
        float x0 = (float)(i - 256) * 0.015625f;           // [-4, 4) step 1/64
        float x1 = x0 + 0.015625f;
        float d0 = gelu_exact(x0) - fmaxf(x0, 0.0f);
        float d1 = gelu_exact(x1) - fmaxf(x1, 0.0f);
        float sl = d1 - d0;
        u32 packed;
        asm("cvt.rn.f16x2.f32 %0, %1, %2;" : "=r"(packed) : "f"(sl), "f"(d0));
        scratch[i] = packed;
    }
    __syncthreads();
    // phase 2: replicate into 32 bank-copies (broadcast read, stride-1 write)
    for (int i = tid; i < 512 * 32; i += NTHR)
        slut[i] = scratch[i >> 5];
    __syncthreads();

    float* efs  = sm + OFF_WARP + wid * WARP_FLOATS;  // [32][8]
    float* outs = efs + 256;                          // [16][20]
    float4* outs4 = reinterpret_cast<float4*>(outs);
    const u32* lutp = slut + lane;                    // per-lane bank copy

    float lsum4[4] = {0, 0, 0, 0}, lsq4[4] = {0, 0, 0, 0};

    const int tiles32 = (E + 31) >> 5;
    const int warpsTotal = gridDim.x * NWARP;
    const int warpGlobal = blockIdx.x * NWARP + wid;

    // ---- software pipeline: preload first iteration's gather ----
    int   pr = 0, pc = 0;
    float4 pra, prb, pca, pcb;
    if (warpGlobal < tiles32) {
        const int e = (warpGlobal << 5) + lane;
        const bool ev = (e < E);
        int r0 = ev ? rowi[e] : 0;
        int c0 = ev ? coli[e] : 0;
        if ((unsigned)r0 >= (unsigned)N) r0 = 0;
        if ((unsigned)c0 >= (unsigned)N) c0 = 0;
        pr = r0; pc = c0;
        pra = *reinterpret_cast<const float4*>(&g_nodepack[8*r0]);
        prb = *reinterpret_cast<const float4*>(&g_nodepack[8*r0+4]);
        pca = *reinterpret_cast<const float4*>(&g_nodepack[8*c0]);
        pcb = *reinterpret_cast<const float4*>(&g_nodepack[8*c0+4]);
    }

    for (int tb32 = warpGlobal; tb32 < tiles32; tb32 += warpsTotal) {
        const int ebase = tb32 << 5;
        const int r = pr, c = pc;
        const float4 ra = pra, rb = prb, ca = pca, cb = pcb;

        {   // geometry from prefetched registers -> stage ef to smem
            const float dx = ca.x - ra.x, dy = ca.y - ra.y, dz = ca.z - ra.z;
            const float nrx = ra.w, nry = rb.x, nrz = rb.y;
            const float ncx = ca.w, ncy = cb.x, ncz = cb.y;
            const float ndot = nrx*ncx + nry*ncy + nrz*ncz;
            const float dn = sqrtf(dx*dx + dy*dy + dz*dz) + 1e-8f;
            const float inv = 1.0f / dn;
            float cr = fminf(1.0f, fmaxf(-1.0f, (nrx*dx+nry*dy+nrz*dz)*inv));
            float cc = fminf(1.0f, fmaxf(-1.0f, (ncx*dx+ncy*dy+ncz*dz)*inv));
            float4* er = reinterpret_cast<float4*>(efs + lane * 8);
            er[0] = make_float4(dx, dy, dz, ndot);
            er[1] = make_float4(cr, cc, cb.z - rb.z, cb.w - rb.w);
        }

        // issue next iteration's gather now (overlaps MMA phases)
        {
            const int nt32 = tb32 + warpsTotal;
            if (nt32 < tiles32) {
                const int e = (nt32 << 5) + lane;
                const bool ev = (e < E);
                int r0 = ev ? rowi[e] : 0;
                int c0 = ev ? coli[e] : 0;
                if ((unsigned)r0 >= (unsigned)N) r0 = 0;
                if ((unsigned)c0 >= (unsigned)N) c0 = 0;
                pr = r0; pc = c0;
                pra = *reinterpret_cast<const float4*>(&g_nodepack[8*r0]);
                prb = *reinterpret_cast<const float4*>(&g_nodepack[8*r0+4]);
                pca = *reinterpret_cast<const float4*>(&g_nodepack[8*c0]);
                pcb = *reinterpret_cast<const float4*>(&g_nodepack[8*c0+4]);
            }
        }
        __syncwarp();

        // ---- Layer 1 (both tiles share each W1 fragment load) ----
        u32 ahA[4], alA[4], ahB[4], alB[4];
        {
            const float* b0 = efs;
            split_tf32(b0[(g    )*8 + j    ], ahA[0], alA[0]);
            split_tf32(b0[(g + 8)*8 + j    ], ahA[1], alA[1]);
            split_tf32(b0[(g    )*8 + j + 4], ahA[2], alA[2]);
            split_tf32(b0[(g + 8)*8 + j + 4], ahA[3], alA[3]);
            const float* b1f = efs + 128;
            split_tf32(b1f[(g    )*8 + j    ], ahB[0], alB[0]);
            split_tf32(b1f[(g + 8)*8 + j    ], ahB[1], alB[1]);
            split_tf32(b1f[(g    )*8 + j + 4], ahB[2], alB[2]);
            split_tf32(b1f[(g + 8)*8 + j + 4], ahB[3], alB[3]);
        }
        u32 A2h[2][4][4], A2l[2][4][4];
#pragma unroll
        for (int nt = 0; nt < 8; nt++) {
            const float2 bb = *reinterpret_cast<const float2*>(sb1 + nt * 8 + 2 * j);
            float4 bw = sW1f[nt * 32 + lane];
            u32 bh0 = __float_as_uint(bw.x), bh1 = __float_as_uint(bw.y);
            u32 bl0 = __float_as_uint(bw.z), bl1 = __float_as_uint(bw.w);
            const int s = nt >> 1, half = nt & 1;
#pragma unroll
            for (int t = 0; t < 2; t++) {
                float d0 = bb.x, d1 = bb.y, d2 = bb.x, d3 = bb.y;
                const u32* ah = t ? ahB : ahA;
                const u32* al = t ? alB : alA;
                mma_tf32(d0, d1, d2, d3, ah[0], ah[1], ah[2], ah[3], bh0, bh1);
                mma_tf32(d0, d1, d2, d3, al[0], al[1], al[2], al[3], bh0, bh1);
                mma_tf32(d0, d1, d2, d3, ah[0], ah[1], ah[2], ah[3], bl0, bl1);
                float y0 = gelu_lut(d0, lutp);
                float y1 = gelu_lut(d1, lutp);
                float y2 = gelu_lut(d2, lutp);
                float y3 = gelu_lut(d3, lutp);
                u32 hp, lp;
                bfpair(y0, y1, hp, lp);
                A2h[t][s][half * 2 + 0] = hp; A2l[t][s][half * 2 + 0] = lp;
                bfpair(y2, y3, hp, lp);
                A2h[t][s][half * 2 + 1] = hp; A2l[t][s][half * 2 + 1] = lp;
            }
        }

        // ---- Layer 2 (shared W2 fragment loads) ----
        float d2v[2][4][4];
#pragma unroll
        for (int n2 = 0; n2 < 4; n2++) {
            const float2 bb = *reinterpret_cast<const float2*>(sb2 + n2 * 8 + 2 * j);
#pragma unroll
            for (int t = 0; t < 2; t++) {
                d2v[t][n2][0] = bb.x; d2v[t][n2][1] = bb.y;
                d2v[t][n2][2] = bb.x; d2v[t][n2][3] = bb.y;
            }
        }
#pragma unroll
        for (int s = 0; s < 4; s++) {
#pragma unroll
            for (int n2 = 0; n2 < 4; n2++) {
                uint4 bw = sW2b[(s * 4 + n2) * 32 + lane];
#pragma unroll
                for (int t = 0; t < 2; t++) {
                    mma_bf16(d2v[t][n2][0], d2v[t][n2][1], d2v[t][n2][2], d2v[t][n2][3],
                             A2h[t][s][0], A2h[t][s][1], A2h[t][s][2], A2h[t][s][3],
                             bw.x, bw.y);
                    mma_bf16(d2v[t][n2][0], d2v[t][n2][1], d2v[t][n2][2], d2v[t][n2][3],
                             A2h[t][s][0], A2h[t][s][1], A2h[t][s][2], A2h[t][s][3],
                             bw.z, bw.w);
                    mma_bf16(d2v[t][n2][0], d2v[t][n2][1], d2v[t][n2][2], d2v[t][n2][3],
                             A2l[t][s][0], A2l[t][s][1], A2l[t][s][2], A2l[t][s][3],
                             bw.x, bw.y);
                }
            }
        }
        u32 A3h[2][2][4], A3l[2][2][4];
#pragma unroll
        for (int t = 0; t < 2; t++) {
#pragma unroll
            for (int n2 = 0; n2 < 4; n2++) {
                float y0 = gelu_lut(d2v[t][n2][0], lutp);
                float y1 = gelu_lut(d2v[t][n2][1], lutp);
                float y2 = gelu_lut(d2v[t][n2][2], lutp);
                float y3 = gelu_lut(d2v[t][n2][3], lutp);
                const int s = n2 >> 1, half = n2 & 1;
                u32 hp, lp;
                bfpair(y0, y1, hp, lp);
                A3h[t][s][half * 2 + 0] = hp; A3l[t][s][half * 2 + 0] = lp;
                bfpair(y2, y3, hp, lp);
                A3h[t][s][half * 2 + 1] = hp; A3l[t][s][half * 2 + 1] = lp;
            }
        }

        // ---- Layer 3 (shared W3 fragment loads) ----
        float d3v[2][2][4];
#pragma unroll
        for (int n3 = 0; n3 < 2; n3++) {
            const float2 bb = *reinterpret_cast<const float2*>(sb3 + n3 * 8 + 2 * j);
#pragma unroll
            for (int t = 0; t < 2; t++) {
                d3v[t][n3][0] = bb.x; d3v[t][n3][1] = bb.y;
                d3v[t][n3][2] = bb.x; d3v[t][n3][3] = bb.y;
            }
        }
#pragma unroll
        for (int s = 0; s < 2; s++) {
#pragma unroll
            for (int n3 = 0; n3 < 2; n3++) {
                uint4 bw = sW3b[(s * 2 + n3) * 32 + lane];
#pragma unroll
                for (int t = 0; t < 2; t++) {
                    mma_bf16(d3v[t][n3][0], d3v[t][n3][1], d3v[t][n3][2], d3v[t][n3][3],
                             A3h[t][s][0], A3h[t][s][1], A3h[t][s][2], A3h[t][s][3],
                             bw.x, bw.y);
                    mma_bf16(d3v[t][n3][0], d3v[t][n3][1], d3v[t][n3][2], d3v[t][n3][3],
                             A3h[t][s][0], A3h[t][s][1], A3h[t][s][2], A3h[t][s][3],
                             bw.z, bw.w);
                    mma_bf16(d3v[t][n3][0], d3v[t][n3][1], d3v[t][n3][2], d3v[t][n3][3],
                             A3l[t][s][0], A3l[t][s][1], A3l[t][s][2], A3l[t][s][3],
                             bw.x, bw.y);
                }
            }
        }

        // ---- per-tile epilogue: stats + stage + scatter ----
#pragma unroll
        for (int t = 0; t < 2; t++) {
            const int tb = ebase + t * 16;
            const bool fullTile = (tb + 16 <= E);
#pragma unroll
            for (int n3 = 0; n3 < 2; n3++) {
                const int cb2 = n3 * 8 + 2 * j;
#pragma unroll
                for (int hrow = 0; hrow < 2; hrow++) {
                    float v0 = d3v[t][n3][2*hrow];
                    float v1 = d3v[t][n3][2*hrow + 1];
                    const int rr = g + 8 * hrow;
                    if (fullTile || (tb + rr < E)) {
                        lsum4[n3*2+0] += v0;
                        lsum4[n3*2+1] += v1;
                        lsq4[n3*2+0]   = fmaf(v0, v0, lsq4[n3*2+0]);
                        lsq4[n3*2+1]   = fmaf(v1, v1, lsq4[n3*2+1]);
                    }
                    *reinterpret_cast<float2*>(outs + rr * OUT_PAD + cb2) =
                        make_float2(v0, v1);
                }
            }
            __syncwarp();

            {   // transposed scatter: 4 lanes cover one node's 64B
                const int slot = lane >> 2;
                const int q    = lane & 3;
#pragma unroll
                for (int it = 0; it < 4; it++) {
                    const int rec  = it * 8 + slot;
                    const int le   = rec & 15;
                    const int side = rec >> 4;
                    const int src  = t * 16 + le;
                    const int nr = __shfl_sync(0xffffffffu, r, src);
                    const int nc = __shfl_sync(0xffffffffu, c, src);
                    const int node = side ? nc : nr;
                    if (tb + le < E) {
                        float4 v = outs4[le * 5 + q];
                        atomicAdd(reinterpret_cast<float4*>(
                            &g_node_acc[(size_t)node * 16]) + q, v);
                    }
                }
                const int le = lane & 15;
                const int src = t * 16 + le;
                const int nr = __shfl_sync(0xffffffffu, r, src);
                const int nc = __shfl_sync(0xffffffffu, c, src);
                const int node = (lane < 16) ? nr : nc;
                if (tb + le < E) atomicAdd(&g_degree[node], 1.0f);
            }
            __syncwarp();
        }
    }

    // ---- BN-stat reduction ----
#pragma unroll
    for (int i = 0; i < 4; i++) {
#pragma unroll
        for (int o = 4; o < 32; o <<= 1) {
            lsum4[i] += __shfl_xor_sync(0xffffffffu, lsum4[i], o);
            lsq4[i]  += __shfl_xor_sync(0xffffffffu, lsq4[i],  o);
        }
    }
    if (lane < 4) {
#pragma unroll
        for (int i = 0; i < 4; i++) {
            const int col = (i >> 1) * 8 + 2 * lane + (i & 1);
            atomicAdd(&g_esum[col], (double)lsum4[i]);
            atomicAdd(&g_esq[col],  (double)lsq4[i]);
        }
    }
}

// ---------------------------------------------------------------------------
__global__ void k_ecoef(const float* __restrict__ g, const float* __restrict__ b,
                        int E)
{
    int j = threadIdx.x;
    if (j < 16) {
        double invE = 1.0 / (double)E;
        double m = g_esum[j] * invE;
        double v = g_esq[j] * invE - m * m;
        double s = (double)g[j] / sqrt(v + 1e-5);
        g_es[j] = (float)s;
        g_et[j] = (float)((double)b[j] - m * s);
    }
}

// ---------------------------------------------------------------------------
__global__ __launch_bounds__(256)
void k_node(const float* __restrict__ Wp, const float* __restrict__ bp,
            int N, float* __restrict__ out)
{
    __shared__ float sWp[256], sbp[16], ses[16], set_[16];
    __shared__ float redS[8][16], redQ[8][16];
    if (threadIdx.x < 256) sWp[threadIdx.x] = Wp[threadIdx.x];
    if (threadIdx.x < 16) {
        sbp[threadIdx.x]  = bp[threadIdx.x];
        ses[threadIdx.x]  = g_es[threadIdx.x];
        set_[threadIdx.x] = g_et[threadIdx.x];
    }
    __syncthreads();

    float lsum[16], lsq[16];
#pragma unroll
    for (int k = 0; k < 16; k++) { lsum[k] = 0.0f; lsq[k] = 0.0f; }

    const int n = blockIdx.x * blockDim.x + threadIdx.x;
    if (n < N) {
        const float deg  = g_degree[n];
        const float invd = 1.0f / fmaxf(deg, 1.0f);
        float pre[16];
#pragma unroll
        for (int j = 0; j < 16; j++) {
            const float a = g_node_acc[n * 16 + j];
            pre[j] = (ses[j] * a + set_[j] * deg) * invd;
        }
        float y[16];
#pragma unroll
        for (int k = 0; k < 16; k++) y[k] = sbp[k];
#pragma unroll
        for (int j = 0; j < 16; j++)
#pragma unroll
            for (int k = 0; k < 16; k++) y[k] = fmaf(pre[j], sWp[j*16 + k], y[k]);
#pragma unroll
        for (int k = 0; k < 16; k++) {
            out[n * 16 + k] = y[k];
            lsum[k] = y[k];
            lsq[k]  = y[k] * y[k];
        }
    }

#pragma unroll
    for (int k = 0; k < 16; k++) {
        float s = lsum[k], q = lsq[k];
#pragma unroll
        for (int o = 16; o > 0; o >>= 1) {
            s += __shfl_xor_sync(0xffffffffu, s, o);
            q += __shfl_xor_sync(0xffffffffu, q, o);
        }
        if ((threadIdx.x & 31) == 0) {
            redS[threadIdx.x >> 5][k] = s;
            redQ[threadIdx.x >> 5][k] = q;
        }
    }
    __syncthreads();
    if (threadIdx.x < 16) {
        double s = 0.0, q = 0.0;
#pragma unroll
        for (int w = 0; w < 8; w++) { s += (double)redS[w][threadIdx.x];
                                      q += (double)redQ[w][threadIdx.x]; }
        atomicAdd(&g_nsum[threadIdx.x], s);
        atomicAdd(&g_nsq[threadIdx.x],  q);
    }
}

// ---------------------------------------------------------------------------
__global__ void k_ncoef(const float* __restrict__ g, const float* __restrict__ b,
                        int N)
{
    int j = threadIdx.x;
    if (j < 16) {
        double invN = 1.0 / (double)N;
        double m = g_nsum[j] * invN;
        double v = g_nsq[j] * invN - m * m;
        double s = (double)g[j] / sqrt(v + 1e-5);
        g_ns[j] = (float)s;
        g_nt[j] = (float)((double)b[j] - m * s);
    }
}

// ---------------------------------------------------------------------------
__global__ void k_norm(float* __restrict__ out, int total)
{
    int i = blockIdx.x * blockDim.x + threadIdx.x;
    if (i < total) {
        int j = i & 15;
        out[i] = fmaf(out[i], g_ns[j], g_nt[j]);
    }
}

// ---------------------------------------------------------------------------
extern "C" void kernel_launch(void* const* d_in, const int* in_sizes, int n_in,
                              void* d_out, int out_size)
{
    const float* coords  = (const float*)d_in[0];
    const float* normals = (const float*)d_in[1];
    const float* curv    = (const float*)d_in[2];
    const int*   ei      = (const int*)d_in[3];
    const float* W1 = (const float*)d_in[4];
    const float* b1 = (const float*)d_in[5];
    const float* W2 = (const float*)d_in[6];
    const float* b2 = (const float*)d_in[7];
    const float* W3 = (const float*)d_in[8];
    const float* b3 = (const float*)d_in[9];
    const float* Wp = (const float*)d_in[10];
    const float* bp = (const float*)d_in[11];
    const float* beg = (const float*)d_in[12];
    const float* beb = (const float*)d_in[13];
    const float* bng = (const float*)d_in[14];
    const float* bnb = (const float*)d_in[15];

    const int N = in_sizes[0] / 3;
    const int E = in_sizes[3] / 2;
    const int* row = ei;
    const int* col = ei + E;
    float* out = (float*)d_out;

    const int smemBytes = (OFF_WARP + NWARP * WARP_FLOATS) * 4;  // ~92 KB
    static bool attrSet = false;
    if (!attrSet) {
        cudaFuncSetAttribute(k_edge, cudaFuncAttributeMaxDynamicSharedMemorySize,
                             smemBytes);
        attrSet = true;
    }

    k_zero<<<(N * 16 + 255) / 256, 256>>>(N);                       // launch 1
    k_pack<<<(N + 255) / 256, 256>>>(coords, normals, curv, N);     // launch 2
    k_dummy<<<1, 32>>>();                                           // launch 3
    k_edge<<<296, NTHR, smemBytes>>>(row, col, W1, b1, W2, b2,      // launch 4
                                     W3, b3, E, N);
    k_ecoef<<<1, 32>>>(beg, beb, E);
    k_node<<<(N + 255) / 256, 256>>>(Wp, bp, N, out);
    k_ncoef<<<1, 32>>>(bng, bnb, N);
    k_norm<<<(N * 16 + 255) / 256, 256>>>(out, N * 16);
}

// round 11
// speedup vs baseline: 1.8973x; 1.0214x over previous
#include <cuda_runtime.h>
#include <cuda_bf16.h>
#include <cuda_fp16.h>
#include <cstdint>

// ---------------------------------------------------------------------------
// GPUManifoldFeatureEncoder — round 11:
//   * de-fused per-16-edge-tile pipeline (R8 structure) -> regs ~128
//     => 256 thr/block, 2 blocks/SM, 16 warps/SM (was 12)
//   * bank-replicated conflict-free gelu delta-LUT (R10)
//   * layer 1: 2-term tf32 (act single cvt, weights hi+lo) — R5-validated
//     error ~3e-4, saves 16 MMA/iter + registers
// ---------------------------------------------------------------------------

#define MAX_N 131072
typedef uint32_t u32;

__device__ float  g_nodepack[MAX_N * 8];    // x,y,z,nx | ny,nz,c0,c1
__device__ float  g_node_acc[MAX_N * 16];
__device__ float  g_degree[MAX_N];
__device__ double g_esum[16], g_esq[16];
__device__ double g_nsum[16], g_nsq[16];
__device__ float  g_es[16], g_et[16];
__device__ float  g_ns[16], g_nt[16];

__device__ __forceinline__ float gelu_exact(float x) {
    return 0.5f * x * (1.0f + erff(x * 0.70710678118654752440f));
}
__device__ __forceinline__ u32 tf32_of(float x) {
    u32 r; asm("cvt.rna.tf32.f32 %0, %1;" : "=r"(r) : "f"(x)); return r;
}
__device__ __forceinline__ void split_tf32(float x, u32& hi, u32& lo) {
    asm("cvt.rna.tf32.f32 %0, %1;" : "=r"(hi) : "f"(x));
    float rem = x - __uint_as_float(hi);
    asm("cvt.rna.tf32.f32 %0, %1;" : "=r"(lo) : "f"(rem));
}
__device__ __forceinline__ void bfpair(float y0, float y1, u32& hp, u32& lp) {
    u32 h; asm("cvt.rn.bf16x2.f32 %0, %1, %2;" : "=r"(h) : "f"(y1), "f"(y0));
    float h0 = __uint_as_float(h << 16);
    float h1 = __uint_as_float(h & 0xFFFF0000u);
    u32 l; asm("cvt.rn.bf16x2.f32 %0, %1, %2;" : "=r"(l) : "f"(y1 - h1), "f"(y0 - h0));
    hp = h; lp = l;
}
__device__ __forceinline__ void mma_tf32(float& d0, float& d1, float& d2, float& d3,
                                         u32 a0, u32 a1, u32 a2, u32 a3,
                                         u32 b0, u32 b1) {
    asm("mma.sync.aligned.m16n8k8.row.col.f32.tf32.tf32.f32 "
        "{%0,%1,%2,%3}, {%4,%5,%6,%7}, {%8,%9}, {%0,%1,%2,%3};"
        : "+f"(d0), "+f"(d1), "+f"(d2), "+f"(d3)
        : "r"(a0), "r"(a1), "r"(a2), "r"(a3), "r"(b0), "r"(b1));
}
__device__ __forceinline__ void mma_bf16(float& d0, float& d1, float& d2, float& d3,
                                         u32 a0, u32 a1, u32 a2, u32 a3,
                                         u32 b0, u32 b1) {
    asm("mma.sync.aligned.m16n8k16.row.col.f32.bf16.bf16.f32 "
        "{%0,%1,%2,%3}, {%4,%5,%6,%7}, {%8,%9}, {%0,%1,%2,%3};"
        : "+f"(d0), "+f"(d1), "+f"(d2), "+f"(d3)
        : "r"(a0), "r"(a1), "r"(a2), "r"(a3), "r"(b0), "r"(b1));
}
// gelu via bank-replicated f16x2 delta-LUT (conflict-free: lutp = slut + lane)
__device__ __forceinline__ float gelu_lut(float x, const u32* __restrict__ lutp) {
    float tt = fminf(fmaxf(fmaf(x, 64.0f, 256.0f), 0.0f), 510.999f);
    int i = (int)tt;
    float fr = tt - (float)i;
    u32 e = lutp[i << 5];
    __half2 h2 = *reinterpret_cast<const __half2*>(&e);
    float2 bs = __half22float2(h2);
    return fmaxf(x, 0.0f) + fmaf(fr, bs.y, bs.x);
}

// ---------------------------------------------------------------------------
__global__ void k_zero(int N) {
    int i = blockIdx.x * blockDim.x + threadIdx.x;
    int tot = N * 16;
    if (i < tot) g_node_acc[i] = 0.0f;
    if (i < N)   g_degree[i]   = 0.0f;
    if (i < 16) {
        g_esum[i] = 0.0; g_esq[i] = 0.0;
        g_nsum[i] = 0.0; g_nsq[i] = 0.0;
    }
}

__global__ void k_pack(const float* __restrict__ coords,
                       const float* __restrict__ normals,
                       const float* __restrict__ curv, int N)
{
    int n = blockIdx.x * blockDim.x + threadIdx.x;
    if (n < N) {
        float4 a = make_float4(coords[3*n+0], coords[3*n+1], coords[3*n+2],
                               normals[3*n+0]);
        float4 b = make_float4(normals[3*n+1], normals[3*n+2],
                               curv[4*n+0], curv[4*n+1]);
        *reinterpret_cast<float4*>(&g_nodepack[8*n])     = a;
        *reinterpret_cast<float4*>(&g_nodepack[8*n + 4]) = b;
    }
}

__global__ void k_dummy() {}

// ---------------------------------------------------------------------------
#define OFF_W1   0
#define OFF_W2   1024
#define OFF_W3   3072
#define OFF_B1   3584
#define OFF_B2   3648
#define OFF_B3   3680
#define OFF_LUT  3712
#define OFF_WARP 20096
#define WARP_FLOATS 576
#define OUT_PAD 20
#define NWARP 8
#define NTHR  256

__global__ __launch_bounds__(NTHR, 2)
void k_edge(const int* __restrict__ rowi,
            const int* __restrict__ coli,
            const float* __restrict__ W1, const float* __restrict__ b1,
            const float* __restrict__ W2, const float* __restrict__ b2,
            const float* __restrict__ W3, const float* __restrict__ b3,
            int E, int N)
{
    extern __shared__ float sm[];
    float4* sW1f = reinterpret_cast<float4*>(sm + OFF_W1);
    uint4*  sW2b = reinterpret_cast<uint4*>(sm + OFF_W2);
    uint4*  sW3b = reinterpret_cast<uint4*>(sm + OFF_W3);
    float*  sb1  = sm + OFF_B1;
    float*  sb2  = sm + OFF_B2;
    float*  sb3  = sm + OFF_B3;
    u32*    slut = reinterpret_cast<u32*>(sm + OFF_LUT);

    const int tid  = threadIdx.x;
    const int lane = tid & 31;
    const int wid  = tid >> 5;
    const int g    = lane >> 2;
    const int j    = lane & 3;

    // ---- preamble ----
    for (int idx = tid; idx < 8 * 32; idx += NTHR) {       // W1 tf32 hi/lo
        int nt = idx >> 5, t = idx & 31;
        int kk = t & 3, nn = nt * 8 + (t >> 2);
        float w0 = W1[kk * 64 + nn], w1 = W1[(kk + 4) * 64 + nn];
        u32 h0, l0, h1_, l1; split_tf32(w0, h0, l0); split_tf32(w1, h1_, l1);
        sW1f[idx] = make_float4(__uint_as_float(h0), __uint_as_float(h1_),
                                __uint_as_float(l0), __uint_as_float(l1));
    }
    for (int idx = tid; idx < 16 * 32; idx += NTHR) {      // W2 bf16 hi/lo pairs
        int combo = idx >> 5, t = idx & 31;
        int s = combo >> 2, nt = combo & 3;
        int g2 = t >> 2, j2 = t & 3;
        int nn = nt * 8 + g2;
        int k0 = s * 16 + 2 * j2;
        float w00 = W2[(k0    ) * 32 + nn], w01 = W2[(k0 + 1) * 32 + nn];
        float w10 = W2[(k0 + 8) * 32 + nn], w11 = W2[(k0 + 9) * 32 + nn];
        u32 h0p, l0p, h1p, l1p;
        bfpair(w00, w01, h0p, l0p);
        bfpair(w10, w11, h1p, l1p);
        sW2b[idx] = make_uint4(h0p, h1p, l0p, l1p);
    }
    for (int idx = tid; idx < 4 * 32; idx += NTHR) {       // W3 bf16 hi/lo pairs
        int combo = idx >> 5, t = idx & 31;
        int s = combo >> 1, nt = combo & 1;
        int g2 = t >> 2, j2 = t & 3;
        int nn = nt * 8 + g2;
        int k0 = s * 16 + 2 * j2;
        float w00 = W3[(k0    ) * 16 + nn], w01 = W3[(k0 + 1) * 16 + nn];
        float w10 = W3[(k0 + 8) * 16 + nn], w11 = W3[(k0 + 9) * 16 + nn];
        u32 h0p, l0p, h1p, l1p;
        bfpair(w00, w01, h0p, l0p);
        bfpair(w10, w11, h1p, l1p);
        sW3b[idx] = make_uint4(h0p, h1p, l0p, l1p);
    }
    if (tid < 64) sb1[tid] = b1[tid];
    if (tid < 32) sb2[tid] = b2[tid];
    if (tid < 16) sb3[tid] = b3[tid];

    // ---- two-phase replicated LUT init ----
    u32* scratch = reinterpret_cast<u32*>(sm + OFF_WARP);
    for (int i = tid; i < 512; i += NTHR) {
        float x0 = (float)(i - 256) * 0.015625f;           // [-4, 4) step 1/64
        float x1 = x0 + 0.015625f;
        float d0 = gelu_exact(x0) - fmaxf(x0, 0.0f);
        float d1 = gelu_exact(x1) - fmaxf(x1, 0.0f);
        float sl = d1 - d0;
        u32 packed;
        asm("cvt.rn.f16x2.f32 %0, %1, %2;" : "=r"(packed) : "f"(sl), "f"(d0));
        scratch[i] = packed;
    }
    __syncthreads();
    for (int i = tid; i < 512 * 32; i += NTHR)
        slut[i] = scratch[i >> 5];
    __syncthreads();

    float* efs  = sm + OFF_WARP + wid * WARP_FLOATS;  // [32][8]
    float* outs = efs + 256;                          // [16][20]
    float4* outs4 = reinterpret_cast<float4*>(outs);
    const u32* lutp = slut + lane;

    float lsum4[4] = {0, 0, 0, 0}, lsq4[4] = {0, 0, 0, 0};

    const int tiles32 = (E + 31) >> 5;
    const int warpsTotal = gridDim.x * NWARP;
    const int warpGlobal = blockIdx.x * NWARP + wid;

    // ---- software pipeline: preload first iteration's gather ----
    int   pr = 0, pc = 0;
    float4 pra, prb, pca, pcb;
    if (warpGlobal < tiles32) {
        const int e = (warpGlobal << 5) + lane;
        const bool ev = (e < E);
        int r0 = ev ? rowi[e] : 0;
        int c0 = ev ? coli[e] : 0;
        if ((unsigned)r0 >= (unsigned)N) r0 = 0;
        if ((unsigned)c0 >= (unsigned)N) c0 = 0;
        pr = r0; pc = c0;
        pra = *reinterpret_cast<const float4*>(&g_nodepack[8*r0]);
        prb = *reinterpret_cast<const float4*>(&g_nodepack[8*r0+4]);
        pca = *reinterpret_cast<const float4*>(&g_nodepack[8*c0]);
        pcb = *reinterpret_cast<const float4*>(&g_nodepack[8*c0+4]);
    }

    for (int tb32 = warpGlobal; tb32 < tiles32; tb32 += warpsTotal) {
        const int ebase = tb32 << 5;
        const int r = pr, c = pc;
        const float4 ra = pra, rb = prb, ca = pca, cb = pcb;

        {   // geometry from prefetched registers -> stage ef to smem
            const float dx = ca.x - ra.x, dy = ca.y - ra.y, dz = ca.z - ra.z;
            const float nrx = ra.w, nry = rb.x, nrz = rb.y;
            const float ncx = ca.w, ncy = cb.x, ncz = cb.y;
            const float ndot = nrx*ncx + nry*ncy + nrz*ncz;
            const float dn = sqrtf(dx*dx + dy*dy + dz*dz) + 1e-8f;
            const float inv = 1.0f / dn;
            float cr = fminf(1.0f, fmaxf(-1.0f, (nrx*dx+nry*dy+nrz*dz)*inv));
            float cc = fminf(1.0f, fmaxf(-1.0f, (ncx*dx+ncy*dy+ncz*dz)*inv));
            float4* er = reinterpret_cast<float4*>(efs + lane * 8);
            er[0] = make_float4(dx, dy, dz, ndot);
            er[1] = make_float4(cr, cc, cb.z - rb.z, cb.w - rb.w);
        }

        // issue next iteration's gather now (overlaps MMA phases)
        {
            const int nt32 = tb32 + warpsTotal;
            if (nt32 < tiles32) {
                const int e = (nt32 << 5) + lane;
                const bool ev = (e < E);
                int r0 = ev ? rowi[e] : 0;
                int c0 = ev ? coli[e] : 0;
                if ((unsigned)r0 >= (unsigned)N) r0 = 0;
                if ((unsigned)c0 >= (unsigned)N) c0 = 0;
                pr = r0; pc = c0;
                pra = *reinterpret_cast<const float4*>(&g_nodepack[8*r0]);
                prb = *reinterpret_cast<const float4*>(&g_nodepack[8*r0+4]);
                pca = *reinterpret_cast<const float4*>(&g_nodepack[8*c0]);
                pcb = *reinterpret_cast<const float4*>(&g_nodepack[8*c0+4]);
            }
        }
        __syncwarp();

        // ---- per-16-edge-tile full pipeline (de-fused; low reg pressure) --
#pragma unroll
        for (int t = 0; t < 2; t++) {
            const int tb = ebase + t * 16;

            // Layer 1: tf32 k8, 2-term (act single cvt, weights hi+lo)
            u32 a4[4];
            {
                const float* base = efs + t * 128;
                a4[0] = tf32_of(base[(g    )*8 + j    ]);
                a4[1] = tf32_of(base[(g + 8)*8 + j    ]);
                a4[2] = tf32_of(base[(g    )*8 + j + 4]);
                a4[3] = tf32_of(base[(g + 8)*8 + j + 4]);
            }
            u32 A2h[4][4], A2l[4][4];
#pragma unroll
            for (int nt = 0; nt < 8; nt++) {
                const float2 bb = *reinterpret_cast<const float2*>(
                    sb1 + nt * 8 + 2 * j);
                float d0 = bb.x, d1 = bb.y, d2 = bb.x, d3 = bb.y;
                float4 bw = sW1f[nt * 32 + lane];
                mma_tf32(d0, d1, d2, d3, a4[0], a4[1], a4[2], a4[3],
                         __float_as_uint(bw.x), __float_as_uint(bw.y));
                mma_tf32(d0, d1, d2, d3, a4[0], a4[1], a4[2], a4[3],
                         __float_as_uint(bw.z), __float_as_uint(bw.w));
                float y0 = gelu_lut(d0, lutp);
                float y1 = gelu_lut(d1, lutp);
                float y2 = gelu_lut(d2, lutp);
                float y3 = gelu_lut(d3, lutp);
                const int s = nt >> 1, half = nt & 1;
                u32 hp, lp;
                bfpair(y0, y1, hp, lp);
                A2h[s][half * 2 + 0] = hp; A2l[s][half * 2 + 0] = lp;
                bfpair(y2, y3, hp, lp);
                A2h[s][half * 2 + 1] = hp; A2l[s][half * 2 + 1] = lp;
            }

            // Layer 2: bf16 m16n8k16, 3-term
            float d2v[4][4];
#pragma unroll
            for (int n2 = 0; n2 < 4; n2++) {
                const float2 bb = *reinterpret_cast<const float2*>(
                    sb2 + n2 * 8 + 2 * j);
                d2v[n2][0] = bb.x; d2v[n2][1] = bb.y;
                d2v[n2][2] = bb.x; d2v[n2][3] = bb.y;
            }
#pragma unroll
            for (int s = 0; s < 4; s++) {
#pragma unroll
                for (int n2 = 0; n2 < 4; n2++) {
                    uint4 bw = sW2b[(s * 4 + n2) * 32 + lane];
                    mma_bf16(d2v[n2][0], d2v[n2][1], d2v[n2][2], d2v[n2][3],
                             A2h[s][0], A2h[s][1], A2h[s][2], A2h[s][3],
                             bw.x, bw.y);
                    mma_bf16(d2v[n2][0], d2v[n2][1], d2v[n2][2], d2v[n2][3],
                             A2h[s][0], A2h[s][1], A2h[s][2], A2h[s][3],
                             bw.z, bw.w);
                    mma_bf16(d2v[n2][0], d2v[n2][1], d2v[n2][2], d2v[n2][3],
                             A2l[s][0], A2l[s][1], A2l[s][2], A2l[s][3],
                             bw.x, bw.y);
                }
            }
            u32 A3h[2][4], A3l[2][4];
#pragma unroll
            for (int n2 = 0; n2 < 4; n2++) {
                float y0 = gelu_lut(d2v[n2][0], lutp);
                float y1 = gelu_lut(d2v[n2][1], lutp);
                float y2 = gelu_lut(d2v[n2][2], lutp);
                float y3 = gelu_lut(d2v[n2][3], lutp);
                const int s = n2 >> 1, half = n2 & 1;
                u32 hp, lp;
                bfpair(y0, y1, hp, lp);
                A3h[s][half * 2 + 0] = hp; A3l[s][half * 2 + 0] = lp;
                bfpair(y2, y3, hp, lp);
                A3h[s][half * 2 + 1] = hp; A3l[s][half * 2 + 1] = lp;
            }

            // Layer 3: bf16 m16n8k16, 3-term
            float d3v[2][4];
#pragma unroll
            for (int n3 = 0; n3 < 2; n3++) {
                const float2 bb = *reinterpret_cast<const float2*>(
                    sb3 + n3 * 8 + 2 * j);
                d3v[n3][0] = bb.x; d3v[n3][1] = bb.y;
                d3v[n3][2] = bb.x; d3v[n3][3] = bb.y;
            }
#pragma unroll
            for (int s = 0; s < 2; s++) {
#pragma unroll
                for (int n3 = 0; n3 < 2; n3++) {
                    uint4 bw = sW3b[(s * 2 + n3) * 32 + lane];
                    mma_bf16(d3v[n3][0], d3v[n3][1], d3v[n3][2], d3v[n3][3],
                             A3h[s][0], A3h[s][1], A3h[s][2], A3h[s][3],
                             bw.x, bw.y);
                    mma_bf16(d3v[n3][0], d3v[n3][1], d3v[n3][2], d3v[n3][3],
                             A3h[s][0], A3h[s][1], A3h[s][2], A3h[s][3],
                             bw.z, bw.w);
                    mma_bf16(d3v[n3][0], d3v[n3][1], d3v[n3][2], d3v[n3][3],
                             A3l[s][0], A3l[s][1], A3l[s][2], A3l[s][3],
                             bw.x, bw.y);
                }
            }

            // epilogue: stats + stage + scatter
            const bool fullTile = (tb + 16 <= E);
#pragma unroll
            for (int n3 = 0; n3 < 2; n3++) {
                const int cb2 = n3 * 8 + 2 * j;
#pragma unroll
                for (int hrow = 0; hrow < 2; hrow++) {
                    float v0 = d3v[n3][2*hrow];
                    float v1 = d3v[n3][2*hrow + 1];
                    const int rr = g + 8 * hrow;
                    if (fullTile || (tb + rr < E)) {
                        lsum4[n3*2+0] += v0;
                        lsum4[n3*2+1] += v1;
                        lsq4[n3*2+0]   = fmaf(v0, v0, lsq4[n3*2+0]);
                        lsq4[n3*2+1]   = fmaf(v1, v1, lsq4[n3*2+1]);
                    }
                    *reinterpret_cast<float2*>(outs + rr * OUT_PAD + cb2) =
                        make_float2(v0, v1);
                }
            }
            __syncwarp();

            {   // transposed scatter: 4 lanes cover one node's 64B
                const int slot = lane >> 2;
                const int q    = lane & 3;
#pragma unroll
                for (int it = 0; it < 4; it++) {
                    const int rec  = it * 8 + slot;
                    const int le   = rec & 15;
                    const int side = rec >> 4;
                    const int src  = t * 16 + le;
                    const int nr = __shfl_sync(0xffffffffu, r, src);
                    const int nc = __shfl_sync(0xffffffffu, c, src);
                    const int node = side ? nc : nr;
                    if (tb + le < E) {
                        float4 v = outs4[le * 5 + q];
                        atomicAdd(reinterpret_cast<float4*>(
                            &g_node_acc[(size_t)node * 16]) + q, v);
                    }
                }
                const int le = lane & 15;
                const int src = t * 16 + le;
                const int nr = __shfl_sync(0xffffffffu, r, src);
                const int nc = __shfl_sync(0xffffffffu, c, src);
                const int node = (lane < 16) ? nr : nc;
                if (tb + le < E) atomicAdd(&g_degree[node], 1.0f);
            }
            __syncwarp();
        }
    }

    // ---- BN-stat reduction ----
#pragma unroll
    for (int i = 0; i < 4; i++) {
#pragma unroll
        for (int o = 4; o < 32; o <<= 1) {
            lsum4[i] += __shfl_xor_sync(0xffffffffu, lsum4[i], o);
            lsq4[i]  += __shfl_xor_sync(0xffffffffu, lsq4[i],  o);
        }
    }
    if (lane < 4) {
#pragma unroll
        for (int i = 0; i < 4; i++) {
            const int col = (i >> 1) * 8 + 2 * lane + (i & 1);
            atomicAdd(&g_esum[col], (double)lsum4[i]);
            atomicAdd(&g_esq[col],  (double)lsq4[i]);
        }
    }
}

// ---------------------------------------------------------------------------
__global__ void k_ecoef(const float* __restrict__ g, const float* __restrict__ b,
                        int E)
{
    int j = threadIdx.x;
    if (j < 16) {
        double invE = 1.0 / (double)E;
        double m = g_esum[j] * invE;
        double v = g_esq[j] * invE - m * m;
        double s = (double)g[j] / sqrt(v + 1e-5);
        g_es[j] = (float)s;
        g_et[j] = (float)((double)b[j] - m * s);
    }
}

// ---------------------------------------------------------------------------
__global__ __launch_bounds__(256)
void k_node(const float* __restrict__ Wp, const float* __restrict__ bp,
            int N, float* __restrict__ out)
{
    __shared__ float sWp[256], sbp[16], ses[16], set_[16];
    __shared__ float redS[8][16], redQ[8][16];
    if (threadIdx.x < 256) sWp[threadIdx.x] = Wp[threadIdx.x];
    if (threadIdx.x < 16) {
        sbp[threadIdx.x]  = bp[threadIdx.x];
        ses[threadIdx.x]  = g_es[threadIdx.x];
        set_[threadIdx.x] = g_et[threadIdx.x];
    }
    __syncthreads();

    float lsum[16], lsq[16];
#pragma unroll
    for (int k = 0; k < 16; k++) { lsum[k] = 0.0f; lsq[k] = 0.0f; }

    const int n = blockIdx.x * blockDim.x + threadIdx.x;
    if (n < N) {
        const float deg  = g_degree[n];
        const float invd = 1.0f / fmaxf(deg, 1.0f);
        float pre[16];
#pragma unroll
        for (int j = 0; j < 16; j++) {
            const float a = g_node_acc[n * 16 + j];
            pre[j] = (ses[j] * a + set_[j] * deg) * invd;
        }
        float y[16];
#pragma unroll
        for (int k = 0; k < 16; k++) y[k] = sbp[k];
#pragma unroll
        for (int j = 0; j < 16; j++)
#pragma unroll
            for (int k = 0; k < 16; k++) y[k] = fmaf(pre[j], sWp[j*16 + k], y[k]);
#pragma unroll
        for (int k = 0; k < 16; k++) {
            out[n * 16 + k] = y[k];
            lsum[k] = y[k];
            lsq[k]  = y[k] * y[k];
        }
    }

#pragma unroll
    for (int k = 0; k < 16; k++) {
        float s = lsum[k], q = lsq[k];
#pragma unroll
        for (int o = 16; o > 0; o >>= 1) {
            s += __shfl_xor_sync(0xffffffffu, s, o);
            q += __shfl_xor_sync(0xffffffffu, q, o);
        }
        if ((threadIdx.x & 31) == 0) {
            redS[threadIdx.x >> 5][k] = s;
            redQ[threadIdx.x >> 5][k] = q;
        }
    }
    __syncthreads();
    if (threadIdx.x < 16) {
        double s = 0.0, q = 0.0;
#pragma unroll
        for (int w = 0; w < 8; w++) { s += (double)redS[w][threadIdx.x];
                                      q += (double)redQ[w][threadIdx.x]; }
        atomicAdd(&g_nsum[threadIdx.x], s);
        atomicAdd(&g_nsq[threadIdx.x],  q);
    }
}

// ---------------------------------------------------------------------------
__global__ void k_ncoef(const float* __restrict__ g, const float* __restrict__ b,
                        int N)
{
    int j = threadIdx.x;
    if (j < 16) {
        double invN = 1.0 / (double)N;
        double m = g_nsum[j] * invN;
        double v = g_nsq[j] * invN - m * m;
        double s = (double)g[j] / sqrt(v + 1e-5);
        g_ns[j] = (float)s;
        g_nt[j] = (float)((double)b[j] - m * s);
    }
}

// ---------------------------------------------------------------------------
__global__ void k_norm(float* __restrict__ out, int total)
{
    int i = blockIdx.x * blockDim.x + threadIdx.x;
    if (i < total) {
        int j = i & 15;
        out[i] = fmaf(out[i], g_ns[j], g_nt[j]);
    }
}

// ---------------------------------------------------------------------------
extern "C" void kernel_launch(void* const* d_in, const int* in_sizes, int n_in,
                              void* d_out, int out_size)
{
    const float* coords  = (const float*)d_in[0];
    const float* normals = (const float*)d_in[1];
    const float* curv    = (const float*)d_in[2];
    const int*   ei      = (const int*)d_in[3];
    const float* W1 = (const float*)d_in[4];
    const float* b1 = (const float*)d_in[5];
    const float* W2 = (const float*)d_in[6];
    const float* b2 = (const float*)d_in[7];
    const float* W3 = (const float*)d_in[8];
    const float* b3 = (const float*)d_in[9];
    const float* Wp = (const float*)d_in[10];
    const float* bp = (const float*)d_in[11];
    const float* beg = (const float*)d_in[12];
    const float* beb = (const float*)d_in[13];
    const float* bng = (const float*)d_in[14];
    const float* bnb = (const float*)d_in[15];

    const int N = in_sizes[0] / 3;
    const int E = in_sizes[3] / 2;
    const int* row = ei;
    const int* col = ei + E;
    float* out = (float*)d_out;

    const int smemBytes = (OFF_WARP + NWARP * WARP_FLOATS) * 4;  // ~98.8 KB
    static bool attrSet = false;
    if (!attrSet) {
        cudaFuncSetAttribute(k_edge, cudaFuncAttributeMaxDynamicSharedMemorySize,
                             smemBytes);
        attrSet = true;
    }

    k_zero<<<(N * 16 + 255) / 256, 256>>>(N);                       // launch 1
    k_pack<<<(N + 255) / 256, 256>>>(coords, normals, curv, N);     // launch 2
    k_dummy<<<1, 32>>>();                                           // launch 3
    k_edge<<<296, NTHR, smemBytes>>>(row, col, W1, b1, W2, b2,      // launch 4
                                     W3, b3, E, N);
    k_ecoef<<<1, 32>>>(beg, beb, E);
    k_node<<<(N + 255) / 256, 256>>>(Wp, bp, N, out);
    k_ncoef<<<1, 32>>>(bng, bnb, N);
    k_norm<<<(N * 16 + 255) / 256, 256>>>(out, N * 16);
}

// round 12
// speedup vs baseline: 2.0337x; 1.0719x over previous
#include <cuda_runtime.h>
#include <cuda_bf16.h>
#include <cuda_fp16.h>
#include <cstdint>

// ---------------------------------------------------------------------------
// GPUManifoldFeatureEncoder — round 12:
//   * fp16 activation path: layers 2-3 use m16n8k16.f32.f16.f16.f32 with
//     single-fp16 activations x (hi+lo fp16) weights => 2-term MMA
//   * paired half2 gelu: LUT lerp + relu in fp16x2, emits the packed
//     A-fragment directly (no separate pack step)
//   * rest as R11: 256thr/2blk, replicated conflict-free LUT, transposed
//     scatter, prefetch pipeline, tf32 2-term layer 1
// ---------------------------------------------------------------------------

#define MAX_N 131072
typedef uint32_t u32;

__device__ float  g_nodepack[MAX_N * 8];    // x,y,z,nx | ny,nz,c0,c1
__device__ float  g_node_acc[MAX_N * 16];
__device__ float  g_degree[MAX_N];
__device__ double g_esum[16], g_esq[16];
__device__ double g_nsum[16], g_nsq[16];
__device__ float  g_es[16], g_et[16];
__device__ float  g_ns[16], g_nt[16];

__device__ __forceinline__ float gelu_exact(float x) {
    return 0.5f * x * (1.0f + erff(x * 0.70710678118654752440f));
}
__device__ __forceinline__ u32 tf32_of(float x) {
    u32 r; asm("cvt.rna.tf32.f32 %0, %1;" : "=r"(r) : "f"(x)); return r;
}
__device__ __forceinline__ void split_tf32(float x, u32& hi, u32& lo) {
    asm("cvt.rna.tf32.f32 %0, %1;" : "=r"(hi) : "f"(x));
    float rem = x - __uint_as_float(hi);
    asm("cvt.rna.tf32.f32 %0, %1;" : "=r"(lo) : "f"(rem));
}
// fp16 hi/lo pair for weights: combined 22-bit precision
__device__ __forceinline__ void fpair(float w0, float w1, u32& hp, u32& lp) {
    u32 h; asm("cvt.rn.f16x2.f32 %0, %1, %2;" : "=r"(h) : "f"(w1), "f"(w0));
    __half2 hh = *reinterpret_cast<__half2*>(&h);
    float h0 = __low2float(hh), h1 = __high2float(hh);
    u32 l; asm("cvt.rn.f16x2.f32 %0, %1, %2;" : "=r"(l) : "f"(w1 - h1), "f"(w0 - h0));
    hp = h; lp = l;
}
__device__ __forceinline__ void mma_tf32(float& d0, float& d1, float& d2, float& d3,
                                         u32 a0, u32 a1, u32 a2, u32 a3,
                                         u32 b0, u32 b1) {
    asm("mma.sync.aligned.m16n8k8.row.col.f32.tf32.tf32.f32 "
        "{%0,%1,%2,%3}, {%4,%5,%6,%7}, {%8,%9}, {%0,%1,%2,%3};"
        : "+f"(d0), "+f"(d1), "+f"(d2), "+f"(d3)
        : "r"(a0), "r"(a1), "r"(a2), "r"(a3), "r"(b0), "r"(b1));
}
__device__ __forceinline__ void mma_f16(float& d0, float& d1, float& d2, float& d3,
                                        u32 a0, u32 a1, u32 a2, u32 a3,
                                        u32 b0, u32 b1) {
    asm("mma.sync.aligned.m16n8k16.row.col.f32.f16.f16.f32 "
        "{%0,%1,%2,%3}, {%4,%5,%6,%7}, {%8,%9}, {%0,%1,%2,%3};"
        : "+f"(d0), "+f"(d1), "+f"(d2), "+f"(d3)
        : "r"(a0), "r"(a1), "r"(a2), "r"(a3), "r"(b0), "r"(b1));
}
// paired gelu via replicated f16x2 delta-LUT; returns packed f16x2
// activation (x0 -> low half, x1 -> high half) ready as MMA A-fragment.
__device__ __forceinline__ u32 gelu2_f16(float x0, float x1,
                                         const u32* __restrict__ lutp) {
    float t0 = fminf(fmaxf(fmaf(x0, 64.0f, 256.0f), 0.0f), 510.999f);
    float t1 = fminf(fmaxf(fmaf(x1, 64.0f, 256.0f), 0.0f), 510.999f);
    int i0 = (int)t0, i1 = (int)t1;
    float f0 = t0 - (float)i0, f1 = t1 - (float)i1;
    u32 e0 = lutp[i0 << 5], e1 = lutp[i1 << 5];
    u32 fr2; asm("cvt.rn.f16x2.f32 %0, %1, %2;" : "=r"(fr2) : "f"(f1), "f"(f0));
    u32 base2, slope2;
    asm("prmt.b32 %0, %1, %2, 0x5410;" : "=r"(base2)  : "r"(e0), "r"(e1));
    asm("prmt.b32 %0, %1, %2, 0x7632;" : "=r"(slope2) : "r"(e0), "r"(e1));
    u32 x2; asm("cvt.rn.f16x2.f32 %0, %1, %2;" : "=r"(x2) : "f"(x1), "f"(x0));
    __half2 d2 = __hfma2(*reinterpret_cast<__half2*>(&fr2),
                         *reinterpret_cast<__half2*>(&slope2),
                         *reinterpret_cast<__half2*>(&base2));
    __half2 r2 = __hmax2(*reinterpret_cast<__half2*>(&x2),
                         __float2half2_rn(0.0f));
    __half2 y2 = __hadd2(r2, d2);
    return *reinterpret_cast<u32*>(&y2);
}

// ---------------------------------------------------------------------------
__global__ void k_zero(int N) {
    int i = blockIdx.x * blockDim.x + threadIdx.x;
    int tot = N * 16;
    if (i < tot) g_node_acc[i] = 0.0f;
    if (i < N)   g_degree[i]   = 0.0f;
    if (i < 16) {
        g_esum[i] = 0.0; g_esq[i] = 0.0;
        g_nsum[i] = 0.0; g_nsq[i] = 0.0;
    }
}

__global__ void k_pack(const float* __restrict__ coords,
                       const float* __restrict__ normals,
                       const float* __restrict__ curv, int N)
{
    int n = blockIdx.x * blockDim.x + threadIdx.x;
    if (n < N) {
        float4 a = make_float4(coords[3*n+0], coords[3*n+1], coords[3*n+2],
                               normals[3*n+0]);
        float4 b = make_float4(normals[3*n+1], normals[3*n+2],
                               curv[4*n+0], curv[4*n+1]);
        *reinterpret_cast<float4*>(&g_nodepack[8*n])     = a;
        *reinterpret_cast<float4*>(&g_nodepack[8*n + 4]) = b;
    }
}

__global__ void k_dummy() {}

// ---------------------------------------------------------------------------
#define OFF_W1   0
#define OFF_W2   1024
#define OFF_W3   3072
#define OFF_B1   3584
#define OFF_B2   3648
#define OFF_B3   3680
#define OFF_LUT  3712
#define OFF_WARP 20096
#define WARP_FLOATS 576
#define OUT_PAD 20
#define NWARP 8
#define NTHR  256

__global__ __launch_bounds__(NTHR, 2)
void k_edge(const int* __restrict__ rowi,
            const int* __restrict__ coli,
            const float* __restrict__ W1, const float* __restrict__ b1,
            const float* __restrict__ W2, const float* __restrict__ b2,
            const float* __restrict__ W3, const float* __restrict__ b3,
            int E, int N)
{
    extern __shared__ float sm[];
    float4* sW1f = reinterpret_cast<float4*>(sm + OFF_W1);
    uint4*  sW2h = reinterpret_cast<uint4*>(sm + OFF_W2);
    uint4*  sW3h = reinterpret_cast<uint4*>(sm + OFF_W3);
    float*  sb1  = sm + OFF_B1;
    float*  sb2  = sm + OFF_B2;
    float*  sb3  = sm + OFF_B3;
    u32*    slut = reinterpret_cast<u32*>(sm + OFF_LUT);

    const int tid  = threadIdx.x;
    const int lane = tid & 31;
    const int wid  = tid >> 5;
    const int g    = lane >> 2;
    const int j    = lane & 3;

    // ---- preamble ----
    for (int idx = tid; idx < 8 * 32; idx += NTHR) {       // W1 tf32 hi/lo
        int nt = idx >> 5, t = idx & 31;
        int kk = t & 3, nn = nt * 8 + (t >> 2);
        float w0 = W1[kk * 64 + nn], w1 = W1[(kk + 4) * 64 + nn];
        u32 h0, l0, h1_, l1; split_tf32(w0, h0, l0); split_tf32(w1, h1_, l1);
        sW1f[idx] = make_float4(__uint_as_float(h0), __uint_as_float(h1_),
                                __uint_as_float(l0), __uint_as_float(l1));
    }
    for (int idx = tid; idx < 16 * 32; idx += NTHR) {      // W2 fp16 hi/lo pairs
        int combo = idx >> 5, t = idx & 31;
        int s = combo >> 2, nt = combo & 3;
        int g2 = t >> 2, j2 = t & 3;
        int nn = nt * 8 + g2;
        int k0 = s * 16 + 2 * j2;
        float w00 = W2[(k0    ) * 32 + nn], w01 = W2[(k0 + 1) * 32 + nn];
        float w10 = W2[(k0 + 8) * 32 + nn], w11 = W2[(k0 + 9) * 32 + nn];
        u32 h0p, l0p, h1p, l1p;
        fpair(w00, w01, h0p, l0p);
        fpair(w10, w11, h1p, l1p);
        sW2h[idx] = make_uint4(h0p, h1p, l0p, l1p);
    }
    for (int idx = tid; idx < 4 * 32; idx += NTHR) {       // W3 fp16 hi/lo pairs
        int combo = idx >> 5, t = idx & 31;
        int s = combo >> 1, nt = combo & 1;
        int g2 = t >> 2, j2 = t & 3;
        int nn = nt * 8 + g2;
        int k0 = s * 16 + 2 * j2;
        float w00 = W3[(k0    ) * 16 + nn], w01 = W3[(k0 + 1) * 16 + nn];
        float w10 = W3[(k0 + 8) * 16 + nn], w11 = W3[(k0 + 9) * 16 + nn];
        u32 h0p, l0p, h1p, l1p;
        fpair(w00, w01, h0p, l0p);
        fpair(w10, w11, h1p, l1p);
        sW3h[idx] = make_uint4(h0p, h1p, l0p, l1p);
    }
    if (tid < 64) sb1[tid] = b1[tid];
    if (tid < 32) sb2[tid] = b2[tid];
    if (tid < 16) sb3[tid] = b3[tid];

    // ---- two-phase replicated LUT init (f16x2: slope hi, base lo) ----
    u32* scratch = reinterpret_cast<u32*>(sm + OFF_WARP);
    for (int i = tid; i < 512; i += NTHR) {
        float x0 = (float)(i - 256) * 0.015625f;           // [-4, 4) step 1/64
        float x1 = x0 + 0.015625f;
        float d0 = gelu_exact(x0) - fmaxf(x0, 0.0f);
        float d1 = gelu_exact(x1) - fmaxf(x1, 0.0f);
        float sl = d1 - d0;
        u32 packed;
        asm("cvt.rn.f16x2.f32 %0, %1, %2;" : "=r"(packed) : "f"(sl), "f"(d0));
        scratch[i] = packed;
    }
    __syncthreads();
    for (int i = tid; i < 512 * 32; i += NTHR)
        slut[i] = scratch[i >> 5];
    __syncthreads();

    float* efs  = sm + OFF_WARP + wid * WARP_FLOATS;  // [32][8]
    float* outs = efs + 256;                          // [16][20]
    float4* outs4 = reinterpret_cast<float4*>(outs);
    const u32* lutp = slut + lane;

    float lsum4[4] = {0, 0, 0, 0}, lsq4[4] = {0, 0, 0, 0};

    const int tiles32 = (E + 31) >> 5;
    const int warpsTotal = gridDim.x * NWARP;
    const int warpGlobal = blockIdx.x * NWARP + wid;

    // ---- software pipeline: preload first iteration's gather ----
    int   pr = 0, pc = 0;
    float4 pra, prb, pca, pcb;
    if (warpGlobal < tiles32) {
        const int e = (warpGlobal << 5) + lane;
        const bool ev = (e < E);
        int r0 = ev ? rowi[e] : 0;
        int c0 = ev ? coli[e] : 0;
        if ((unsigned)r0 >= (unsigned)N) r0 = 0;
        if ((unsigned)c0 >= (unsigned)N) c0 = 0;
        pr = r0; pc = c0;
        pra = *reinterpret_cast<const float4*>(&g_nodepack[8*r0]);
        prb = *reinterpret_cast<const float4*>(&g_nodepack[8*r0+4]);
        pca = *reinterpret_cast<const float4*>(&g_nodepack[8*c0]);
        pcb = *reinterpret_cast<const float4*>(&g_nodepack[8*c0+4]);
    }

    for (int tb32 = warpGlobal; tb32 < tiles32; tb32 += warpsTotal) {
        const int ebase = tb32 << 5;
        const int r = pr, c = pc;
        const float4 ra = pra, rb = prb, ca = pca, cb = pcb;

        {   // geometry from prefetched registers -> stage ef to smem
            const float dx = ca.x - ra.x, dy = ca.y - ra.y, dz = ca.z - ra.z;
            const float nrx = ra.w, nry = rb.x, nrz = rb.y;
            const float ncx = ca.w, ncy = cb.x, ncz = cb.y;
            const float ndot = nrx*ncx + nry*ncy + nrz*ncz;
            const float dn = sqrtf(dx*dx + dy*dy + dz*dz) + 1e-8f;
            const float inv = 1.0f / dn;
            float cr = fminf(1.0f, fmaxf(-1.0f, (nrx*dx+nry*dy+nrz*dz)*inv));
            float cc = fminf(1.0f, fmaxf(-1.0f, (ncx*dx+ncy*dy+ncz*dz)*inv));
            float4* er = reinterpret_cast<float4*>(efs + lane * 8);
            er[0] = make_float4(dx, dy, dz, ndot);
            er[1] = make_float4(cr, cc, cb.z - rb.z, cb.w - rb.w);
        }

        // issue next iteration's gather now (overlaps MMA phases)
        {
            const int nt32 = tb32 + warpsTotal;
            if (nt32 < tiles32) {
                const int e = (nt32 << 5) + lane;
                const bool ev = (e < E);
                int r0 = ev ? rowi[e] : 0;
                int c0 = ev ? coli[e] : 0;
                if ((unsigned)r0 >= (unsigned)N) r0 = 0;
                if ((unsigned)c0 >= (unsigned)N) c0 = 0;
                pr = r0; pc = c0;
                pra = *reinterpret_cast<const float4*>(&g_nodepack[8*r0]);
                prb = *reinterpret_cast<const float4*>(&g_nodepack[8*r0+4]);
                pca = *reinterpret_cast<const float4*>(&g_nodepack[8*c0]);
                pcb = *reinterpret_cast<const float4*>(&g_nodepack[8*c0+4]);
            }
        }
        __syncwarp();

        // ---- per-16-edge-tile full pipeline ----
#pragma unroll
        for (int t = 0; t < 2; t++) {
            const int tb = ebase + t * 16;

            // Layer 1: tf32 k8, 2-term (act single cvt, weights hi+lo)
            u32 a4[4];
            {
                const float* base = efs + t * 128;
                a4[0] = tf32_of(base[(g    )*8 + j    ]);
                a4[1] = tf32_of(base[(g + 8)*8 + j    ]);
                a4[2] = tf32_of(base[(g    )*8 + j + 4]);
                a4[3] = tf32_of(base[(g + 8)*8 + j + 4]);
            }
            u32 A2[4][4];
#pragma unroll
            for (int nt = 0; nt < 8; nt++) {
                const float2 bb = *reinterpret_cast<const float2*>(
                    sb1 + nt * 8 + 2 * j);
                float d0 = bb.x, d1 = bb.y, d2 = bb.x, d3 = bb.y;
                float4 bw = sW1f[nt * 32 + lane];
                mma_tf32(d0, d1, d2, d3, a4[0], a4[1], a4[2], a4[3],
                         __float_as_uint(bw.x), __float_as_uint(bw.y));
                mma_tf32(d0, d1, d2, d3, a4[0], a4[1], a4[2], a4[3],
                         __float_as_uint(bw.z), __float_as_uint(bw.w));
                const int s = nt >> 1, half = nt & 1;
                A2[s][half * 2 + 0] = gelu2_f16(d0, d1, lutp);  // rows g
                A2[s][half * 2 + 1] = gelu2_f16(d2, d3, lutp);  // rows g+8
            }

            // Layer 2: fp16 m16n8k16, 2-term (weights hi+lo)
            float d2v[4][4];
#pragma unroll
            for (int n2 = 0; n2 < 4; n2++) {
                const float2 bb = *reinterpret_cast<const float2*>(
                    sb2 + n2 * 8 + 2 * j);
                d2v[n2][0] = bb.x; d2v[n2][1] = bb.y;
                d2v[n2][2] = bb.x; d2v[n2][3] = bb.y;
            }
#pragma unroll
            for (int s = 0; s < 4; s++) {
#pragma unroll
                for (int n2 = 0; n2 < 4; n2++) {
                    uint4 bw = sW2h[(s * 4 + n2) * 32 + lane];
                    mma_f16(d2v[n2][0], d2v[n2][1], d2v[n2][2], d2v[n2][3],
                            A2[s][0], A2[s][1], A2[s][2], A2[s][3],
                            bw.x, bw.y);
                    mma_f16(d2v[n2][0], d2v[n2][1], d2v[n2][2], d2v[n2][3],
                            A2[s][0], A2[s][1], A2[s][2], A2[s][3],
                            bw.z, bw.w);
                }
            }
            u32 A3[2][4];
#pragma unroll
            for (int n2 = 0; n2 < 4; n2++) {
                const int s = n2 >> 1, half = n2 & 1;
                A3[s][half * 2 + 0] = gelu2_f16(d2v[n2][0], d2v[n2][1], lutp);
                A3[s][half * 2 + 1] = gelu2_f16(d2v[n2][2], d2v[n2][3], lutp);
            }

            // Layer 3: fp16 m16n8k16, 2-term
            float d3v[2][4];
#pragma unroll
            for (int n3 = 0; n3 < 2; n3++) {
                const float2 bb = *reinterpret_cast<const float2*>(
                    sb3 + n3 * 8 + 2 * j);
                d3v[n3][0] = bb.x; d3v[n3][1] = bb.y;
                d3v[n3][2] = bb.x; d3v[n3][3] = bb.y;
            }
#pragma unroll
            for (int s = 0; s < 2; s++) {
#pragma unroll
                for (int n3 = 0; n3 < 2; n3++) {
                    uint4 bw = sW3h[(s * 2 + n3) * 32 + lane];
                    mma_f16(d3v[n3][0], d3v[n3][1], d3v[n3][2], d3v[n3][3],
                            A3[s][0], A3[s][1], A3[s][2], A3[s][3],
                            bw.x, bw.y);
                    mma_f16(d3v[n3][0], d3v[n3][1], d3v[n3][2], d3v[n3][3],
                            A3[s][0], A3[s][1], A3[s][2], A3[s][3],
                            bw.z, bw.w);
                }
            }

            // epilogue: stats + stage + scatter
            const bool fullTile = (tb + 16 <= E);
#pragma unroll
            for (int n3 = 0; n3 < 2; n3++) {
                const int cb2 = n3 * 8 + 2 * j;
#pragma unroll
                for (int hrow = 0; hrow < 2; hrow++) {
                    float v0 = d3v[n3][2*hrow];
                    float v1 = d3v[n3][2*hrow + 1];
                    const int rr = g + 8 * hrow;
                    if (fullTile || (tb + rr < E)) {
                        lsum4[n3*2+0] += v0;
                        lsum4[n3*2+1] += v1;
                        lsq4[n3*2+0]   = fmaf(v0, v0, lsq4[n3*2+0]);
                        lsq4[n3*2+1]   = fmaf(v1, v1, lsq4[n3*2+1]);
                    }
                    *reinterpret_cast<float2*>(outs + rr * OUT_PAD + cb2) =
                        make_float2(v0, v1);
                }
            }
            __syncwarp();

            {   // transposed scatter: 4 lanes cover one node's 64B
                const int slot = lane >> 2;
                const int q    = lane & 3;
#pragma unroll
                for (int it = 0; it < 4; it++) {
                    const int rec  = it * 8 + slot;
                    const int le   = rec & 15;
                    const int side = rec >> 4;
                    const int src  = t * 16 + le;
                    const int nr = __shfl_sync(0xffffffffu, r, src);
                    const int nc = __shfl_sync(0xffffffffu, c, src);
                    const int node = side ? nc : nr;
                    if (tb + le < E) {
                        float4 v = outs4[le * 5 + q];
                        atomicAdd(reinterpret_cast<float4*>(
                            &g_node_acc[(size_t)node * 16]) + q, v);
                    }
                }
                const int le = lane & 15;
                const int src = t * 16 + le;
                const int nr = __shfl_sync(0xffffffffu, r, src);
                const int nc = __shfl_sync(0xffffffffu, c, src);
                const int node = (lane < 16) ? nr : nc;
                if (tb + le < E) atomicAdd(&g_degree[node], 1.0f);
            }
            __syncwarp();
        }
    }

    // ---- BN-stat reduction ----
#pragma unroll
    for (int i = 0; i < 4; i++) {
#pragma unroll
        for (int o = 4; o < 32; o <<= 1) {
            lsum4[i] += __shfl_xor_sync(0xffffffffu, lsum4[i], o);
            lsq4[i]  += __shfl_xor_sync(0xffffffffu, lsq4[i],  o);
        }
    }
    if (lane < 4) {
#pragma unroll
        for (int i = 0; i < 4; i++) {
            const int col = (i >> 1) * 8 + 2 * lane + (i & 1);
            atomicAdd(&g_esum[col], (double)lsum4[i]);
            atomicAdd(&g_esq[col],  (double)lsq4[i]);
        }
    }
}

// ---------------------------------------------------------------------------
__global__ void k_ecoef(const float* __restrict__ g, const float* __restrict__ b,
                        int E)
{
    int j = threadIdx.x;
    if (j < 16) {
        double invE = 1.0 / (double)E;
        double m = g_esum[j] * invE;
        double v = g_esq[j] * invE - m * m;
        double s = (double)g[j] / sqrt(v + 1e-5);
        g_es[j] = (float)s;
        g_et[j] = (float)((double)b[j] - m * s);
    }
}

// ---------------------------------------------------------------------------
__global__ __launch_bounds__(256)
void k_node(const float* __restrict__ Wp, const float* __restrict__ bp,
            int N, float* __restrict__ out)
{
    __shared__ float sWp[256], sbp[16], ses[16], set_[16];
    __shared__ float redS[8][16], redQ[8][16];
    if (threadIdx.x < 256) sWp[threadIdx.x] = Wp[threadIdx.x];
    if (threadIdx.x < 16) {
        sbp[threadIdx.x]  = bp[threadIdx.x];
        ses[threadIdx.x]  = g_es[threadIdx.x];
        set_[threadIdx.x] = g_et[threadIdx.x];
    }
    __syncthreads();

    float lsum[16], lsq[16];
#pragma unroll
    for (int k = 0; k < 16; k++) { lsum[k] = 0.0f; lsq[k] = 0.0f; }

    const int n = blockIdx.x * blockDim.x + threadIdx.x;
    if (n < N) {
        const float deg  = g_degree[n];
        const float invd = 1.0f / fmaxf(deg, 1.0f);
        float pre[16];
#pragma unroll
        for (int j = 0; j < 16; j++) {
            const float a = g_node_acc[n * 16 + j];
            pre[j] = (ses[j] * a + set_[j] * deg) * invd;
        }
        float y[16];
#pragma unroll
        for (int k = 0; k < 16; k++) y[k] = sbp[k];
#pragma unroll
        for (int j = 0; j < 16; j++)
#pragma unroll
            for (int k = 0; k < 16; k++) y[k] = fmaf(pre[j], sWp[j*16 + k], y[k]);
#pragma unroll
        for (int k = 0; k < 16; k++) {
            out[n * 16 + k] = y[k];
            lsum[k] = y[k];
            lsq[k]  = y[k] * y[k];
        }
    }

#pragma unroll
    for (int k = 0; k < 16; k++) {
        float s = lsum[k], q = lsq[k];
#pragma unroll
        for (int o = 16; o > 0; o >>= 1) {
            s += __shfl_xor_sync(0xffffffffu, s, o);
            q += __shfl_xor_sync(0xffffffffu, q, o);
        }
        if ((threadIdx.x & 31) == 0) {
            redS[threadIdx.x >> 5][k] = s;
            redQ[threadIdx.x >> 5][k] = q;
        }
    }
    __syncthreads();
    if (threadIdx.x < 16) {
        double s = 0.0, q = 0.0;
#pragma unroll
        for (int w = 0; w < 8; w++) { s += (double)redS[w][threadIdx.x];
                                      q += (double)redQ[w][threadIdx.x]; }
        atomicAdd(&g_nsum[threadIdx.x], s);
        atomicAdd(&g_nsq[threadIdx.x],  q);
    }
}

// ---------------------------------------------------------------------------
__global__ void k_ncoef(const float* __restrict__ g, const float* __restrict__ b,
                        int N)
{
    int j = threadIdx.x;
    if (j < 16) {
        double invN = 1.0 / (double)N;
        double m = g_nsum[j] * invN;
        double v = g_nsq[j] * invN - m * m;
        double s = (double)g[j] / sqrt(v + 1e-5);
        g_ns[j] = (float)s;
        g_nt[j] = (float)((double)b[j] - m * s);
    }
}

// ---------------------------------------------------------------------------
__global__ void k_norm(float* __restrict__ out, int total)
{
    int i = blockIdx.x * blockDim.x + threadIdx.x;
    if (i < total) {
        int j = i & 15;
        out[i] = fmaf(out[i], g_ns[j], g_nt[j]);
    }
}

// ---------------------------------------------------------------------------
extern "C" void kernel_launch(void* const* d_in, const int* in_sizes, int n_in,
                              void* d_out, int out_size)
{
    const float* coords  = (const float*)d_in[0];
    const float* normals = (const float*)d_in[1];
    const float* curv    = (const float*)d_in[2];
    const int*   ei      = (const int*)d_in[3];
    const float* W1 = (const float*)d_in[4];
    const float* b1 = (const float*)d_in[5];
    const float* W2 = (const float*)d_in[6];
    const float* b2 = (const float*)d_in[7];
    const float* W3 = (const float*)d_in[8];
    const float* b3 = (const float*)d_in[9];
    const float* Wp = (const float*)d_in[10];
    const float* bp = (const float*)d_in[11];
    const float* beg = (const float*)d_in[12];
    const float* beb = (const float*)d_in[13];
    const float* bng = (const float*)d_in[14];
    const float* bnb = (const float*)d_in[15];

    const int N = in_sizes[0] / 3;
    const int E = in_sizes[3] / 2;
    const int* row = ei;
    const int* col = ei + E;
    float* out = (float*)d_out;

    const int smemBytes = (OFF_WARP + NWARP * WARP_FLOATS) * 4;  // ~98.8 KB
    static bool attrSet = false;
    if (!attrSet) {
        cudaFuncSetAttribute(k_edge, cudaFuncAttributeMaxDynamicSharedMemorySize,
                             smemBytes);
        attrSet = true;
    }

    k_zero<<<(N * 16 + 255) / 256, 256>>>(N);                       // launch 1
    k_pack<<<(N + 255) / 256, 256>>>(coords, normals, curv, N);     // launch 2
    k_dummy<<<1, 32>>>();                                           // launch 3
    k_edge<<<296, NTHR, smemBytes>>>(row, col, W1, b1, W2, b2,      // launch 4
                                     W3, b3, E, N);
    k_ecoef<<<1, 32>>>(beg, beb, E);
    k_node<<<(N + 255) / 256, 256>>>(Wp, bp, N, out);
    k_ncoef<<<1, 32>>>(bng, bnb, N);
    k_norm<<<(N * 16 + 255) / 256, 256>>>(out, N * 16);
}

// round 13
// speedup vs baseline: 2.2658x; 1.1141x over previous
#include <cuda_runtime.h>
#include <cuda_bf16.h>
#include <cuda_fp16.h>
#include <cstdint>

// ---------------------------------------------------------------------------
// GPUManifoldFeatureEncoder — round 13:
//   * re-fused layers across both 16-edge tiles (one weight-fragment LDS
//     serves 32 edges: -112 L1 wavefronts/iter, -20% total L1 traffic)
//   * fp16 activations keep fragment state small => ~150 regs, no spill
//     at 192thr/2blk (170-reg cap, 12 warps/SM)
//   * rest as R12: fp16 2-term MMA, paired half2 gelu LUT (replicated,
//     conflict-free), tf32 2-term layer 1, transposed scatter, prefetch
// ---------------------------------------------------------------------------

#define MAX_N 131072
typedef uint32_t u32;

__device__ float  g_nodepack[MAX_N * 8];    // x,y,z,nx | ny,nz,c0,c1
__device__ float  g_node_acc[MAX_N * 16];
__device__ float  g_degree[MAX_N];
__device__ double g_esum[16], g_esq[16];
__device__ double g_nsum[16], g_nsq[16];
__device__ float  g_es[16], g_et[16];
__device__ float  g_ns[16], g_nt[16];

__device__ __forceinline__ float gelu_exact(float x) {
    return 0.5f * x * (1.0f + erff(x * 0.70710678118654752440f));
}
__device__ __forceinline__ u32 tf32_of(float x) {
    u32 r; asm("cvt.rna.tf32.f32 %0, %1;" : "=r"(r) : "f"(x)); return r;
}
__device__ __forceinline__ void split_tf32(float x, u32& hi, u32& lo) {
    asm("cvt.rna.tf32.f32 %0, %1;" : "=r"(hi) : "f"(x));
    float rem = x - __uint_as_float(hi);
    asm("cvt.rna.tf32.f32 %0, %1;" : "=r"(lo) : "f"(rem));
}
// fp16 hi/lo pair for weights: combined 22-bit precision
__device__ __forceinline__ void fpair(float w0, float w1, u32& hp, u32& lp) {
    u32 h; asm("cvt.rn.f16x2.f32 %0, %1, %2;" : "=r"(h) : "f"(w1), "f"(w0));
    __half2 hh = *reinterpret_cast<__half2*>(&h);
    float h0 = __low2float(hh), h1 = __high2float(hh);
    u32 l; asm("cvt.rn.f16x2.f32 %0, %1, %2;" : "=r"(l) : "f"(w1 - h1), "f"(w0 - h0));
    hp = h; lp = l;
}
__device__ __forceinline__ void mma_tf32(float& d0, float& d1, float& d2, float& d3,
                                         u32 a0, u32 a1, u32 a2, u32 a3,
                                         u32 b0, u32 b1) {
    asm("mma.sync.aligned.m16n8k8.row.col.f32.tf32.tf32.f32 "
        "{%0,%1,%2,%3}, {%4,%5,%6,%7}, {%8,%9}, {%0,%1,%2,%3};"
        : "+f"(d0), "+f"(d1), "+f"(d2), "+f"(d3)
        : "r"(a0), "r"(a1), "r"(a2), "r"(a3), "r"(b0), "r"(b1));
}
__device__ __forceinline__ void mma_f16(float& d0, float& d1, float& d2, float& d3,
                                        u32 a0, u32 a1, u32 a2, u32 a3,
                                        u32 b0, u32 b1) {
    asm("mma.sync.aligned.m16n8k16.row.col.f32.f16.f16.f32 "
        "{%0,%1,%2,%3}, {%4,%5,%6,%7}, {%8,%9}, {%0,%1,%2,%3};"
        : "+f"(d0), "+f"(d1), "+f"(d2), "+f"(d3)
        : "r"(a0), "r"(a1), "r"(a2), "r"(a3), "r"(b0), "r"(b1));
}
// paired gelu via replicated f16x2 delta-LUT; returns packed f16x2 fragment
__device__ __forceinline__ u32 gelu2_f16(float x0, float x1,
                                         const u32* __restrict__ lutp) {
    float t0 = fminf(fmaxf(fmaf(x0, 64.0f, 256.0f), 0.0f), 510.999f);
    float t1 = fminf(fmaxf(fmaf(x1, 64.0f, 256.0f), 0.0f), 510.999f);
    int i0 = (int)t0, i1 = (int)t1;
    float f0 = t0 - (float)i0, f1 = t1 - (float)i1;
    u32 e0 = lutp[i0 << 5], e1 = lutp[i1 << 5];
    u32 fr2; asm("cvt.rn.f16x2.f32 %0, %1, %2;" : "=r"(fr2) : "f"(f1), "f"(f0));
    u32 base2, slope2;
    asm("prmt.b32 %0, %1, %2, 0x5410;" : "=r"(base2)  : "r"(e0), "r"(e1));
    asm("prmt.b32 %0, %1, %2, 0x7632;" : "=r"(slope2) : "r"(e0), "r"(e1));
    u32 x2; asm("cvt.rn.f16x2.f32 %0, %1, %2;" : "=r"(x2) : "f"(x1), "f"(x0));
    __half2 d2 = __hfma2(*reinterpret_cast<__half2*>(&fr2),
                         *reinterpret_cast<__half2*>(&slope2),
                         *reinterpret_cast<__half2*>(&base2));
    __half2 r2 = __hmax2(*reinterpret_cast<__half2*>(&x2),
                         __float2half2_rn(0.0f));
    __half2 y2 = __hadd2(r2, d2);
    return *reinterpret_cast<u32*>(&y2);
}

// ---------------------------------------------------------------------------
__global__ void k_zero(int N) {
    int i = blockIdx.x * blockDim.x + threadIdx.x;
    int tot = N * 16;
    if (i < tot) g_node_acc[i] = 0.0f;
    if (i < N)   g_degree[i]   = 0.0f;
    if (i < 16) {
        g_esum[i] = 0.0; g_esq[i] = 0.0;
        g_nsum[i] = 0.0; g_nsq[i] = 0.0;
    }
}

__global__ void k_pack(const float* __restrict__ coords,
                       const float* __restrict__ normals,
                       const float* __restrict__ curv, int N)
{
    int n = blockIdx.x * blockDim.x + threadIdx.x;
    if (n < N) {
        float4 a = make_float4(coords[3*n+0], coords[3*n+1], coords[3*n+2],
                               normals[3*n+0]);
        float4 b = make_float4(normals[3*n+1], normals[3*n+2],
                               curv[4*n+0], curv[4*n+1]);
        *reinterpret_cast<float4*>(&g_nodepack[8*n])     = a;
        *reinterpret_cast<float4*>(&g_nodepack[8*n + 4]) = b;
    }
}

__global__ void k_dummy() {}

// ---------------------------------------------------------------------------
#define OFF_W1   0
#define OFF_W2   1024
#define OFF_W3   3072
#define OFF_B1   3584
#define OFF_B2   3648
#define OFF_B3   3680
#define OFF_LUT  3712
#define OFF_WARP 20096
#define WARP_FLOATS 576
#define OUT_PAD 20
#define NWARP 6
#define NTHR  192

__global__ __launch_bounds__(NTHR, 2)
void k_edge(const int* __restrict__ rowi,
            const int* __restrict__ coli,
            const float* __restrict__ W1, const float* __restrict__ b1,
            const float* __restrict__ W2, const float* __restrict__ b2,
            const float* __restrict__ W3, const float* __restrict__ b3,
            int E, int N)
{
    extern __shared__ float sm[];
    float4* sW1f = reinterpret_cast<float4*>(sm + OFF_W1);
    uint4*  sW2h = reinterpret_cast<uint4*>(sm + OFF_W2);
    uint4*  sW3h = reinterpret_cast<uint4*>(sm + OFF_W3);
    float*  sb1  = sm + OFF_B1;
    float*  sb2  = sm + OFF_B2;
    float*  sb3  = sm + OFF_B3;
    u32*    slut = reinterpret_cast<u32*>(sm + OFF_LUT);

    const int tid  = threadIdx.x;
    const int lane = tid & 31;
    const int wid  = tid >> 5;
    const int g    = lane >> 2;
    const int j    = lane & 3;

    // ---- preamble ----
    for (int idx = tid; idx < 8 * 32; idx += NTHR) {       // W1 tf32 hi/lo
        int nt = idx >> 5, t = idx & 31;
        int kk = t & 3, nn = nt * 8 + (t >> 2);
        float w0 = W1[kk * 64 + nn], w1 = W1[(kk + 4) * 64 + nn];
        u32 h0, l0, h1_, l1; split_tf32(w0, h0, l0); split_tf32(w1, h1_, l1);
        sW1f[idx] = make_float4(__uint_as_float(h0), __uint_as_float(h1_),
                                __uint_as_float(l0), __uint_as_float(l1));
    }
    for (int idx = tid; idx < 16 * 32; idx += NTHR) {      // W2 fp16 hi/lo pairs
        int combo = idx >> 5, t = idx & 31;
        int s = combo >> 2, nt = combo & 3;
        int g2 = t >> 2, j2 = t & 3;
        int nn = nt * 8 + g2;
        int k0 = s * 16 + 2 * j2;
        float w00 = W2[(k0    ) * 32 + nn], w01 = W2[(k0 + 1) * 32 + nn];
        float w10 = W2[(k0 + 8) * 32 + nn], w11 = W2[(k0 + 9) * 32 + nn];
        u32 h0p, l0p, h1p, l1p;
        fpair(w00, w01, h0p, l0p);
        fpair(w10, w11, h1p, l1p);
        sW2h[idx] = make_uint4(h0p, h1p, l0p, l1p);
    }
    for (int idx = tid; idx < 4 * 32; idx += NTHR) {       // W3 fp16 hi/lo pairs
        int combo = idx >> 5, t = idx & 31;
        int s = combo >> 1, nt = combo & 1;
        int g2 = t >> 2, j2 = t & 3;
        int nn = nt * 8 + g2;
        int k0 = s * 16 + 2 * j2;
        float w00 = W3[(k0    ) * 16 + nn], w01 = W3[(k0 + 1) * 16 + nn];
        float w10 = W3[(k0 + 8) * 16 + nn], w11 = W3[(k0 + 9) * 16 + nn];
        u32 h0p, l0p, h1p, l1p;
        fpair(w00, w01, h0p, l0p);
        fpair(w10, w11, h1p, l1p);
        sW3h[idx] = make_uint4(h0p, h1p, l0p, l1p);
    }
    if (tid < 64) sb1[tid] = b1[tid];
    if (tid < 32) sb2[tid] = b2[tid];
    if (tid < 16) sb3[tid] = b3[tid];

    // ---- two-phase replicated LUT init (f16x2: slope hi, base lo) ----
    u32* scratch = reinterpret_cast<u32*>(sm + OFF_WARP);
    for (int i = tid; i < 512; i += NTHR) {
        float x0 = (float)(i - 256) * 0.015625f;           // [-4, 4) step 1/64
        float x1 = x0 + 0.015625f;
        float d0 = gelu_exact(x0) - fmaxf(x0, 0.0f);
        float d1 = gelu_exact(x1) - fmaxf(x1, 0.0f);
        float sl = d1 - d0;
        u32 packed;
        asm("cvt.rn.f16x2.f32 %0, %1, %2;" : "=r"(packed) : "f"(sl), "f"(d0));
        scratch[i] = packed;
    }
    __syncthreads();
    for (int i = tid; i < 512 * 32; i += NTHR)
        slut[i] = scratch[i >> 5];
    __syncthreads();

    float* efs  = sm + OFF_WARP + wid * WARP_FLOATS;  // [32][8]
    float* outs = efs + 256;                          // [16][20]
    float4* outs4 = reinterpret_cast<float4*>(outs);
    const u32* lutp = slut + lane;

    float lsum4[4] = {0, 0, 0, 0}, lsq4[4] = {0, 0, 0, 0};

    const int tiles32 = (E + 31) >> 5;
    const int warpsTotal = gridDim.x * NWARP;
    const int warpGlobal = blockIdx.x * NWARP + wid;

    // ---- software pipeline: preload first iteration's gather ----
    int   pr = 0, pc = 0;
    float4 pra, prb, pca, pcb;
    if (warpGlobal < tiles32) {
        const int e = (warpGlobal << 5) + lane;
        const bool ev = (e < E);
        int r0 = ev ? rowi[e] : 0;
        int c0 = ev ? coli[e] : 0;
        if ((unsigned)r0 >= (unsigned)N) r0 = 0;
        if ((unsigned)c0 >= (unsigned)N) c0 = 0;
        pr = r0; pc = c0;
        pra = *reinterpret_cast<const float4*>(&g_nodepack[8*r0]);
        prb = *reinterpret_cast<const float4*>(&g_nodepack[8*r0+4]);
        pca = *reinterpret_cast<const float4*>(&g_nodepack[8*c0]);
        pcb = *reinterpret_cast<const float4*>(&g_nodepack[8*c0+4]);
    }

    for (int tb32 = warpGlobal; tb32 < tiles32; tb32 += warpsTotal) {
        const int ebase = tb32 << 5;
        const int r = pr, c = pc;
        const float4 ra = pra, rb = prb, ca = pca, cb = pcb;

        {   // geometry from prefetched registers -> stage ef to smem
            const float dx = ca.x - ra.x, dy = ca.y - ra.y, dz = ca.z - ra.z;
            const float nrx = ra.w, nry = rb.x, nrz = rb.y;
            const float ncx = ca.w, ncy = cb.x, ncz = cb.y;
            const float ndot = nrx*ncx + nry*ncy + nrz*ncz;
            const float dn = sqrtf(dx*dx + dy*dy + dz*dz) + 1e-8f;
            const float inv = 1.0f / dn;
            float cr = fminf(1.0f, fmaxf(-1.0f, (nrx*dx+nry*dy+nrz*dz)*inv));
            float cc = fminf(1.0f, fmaxf(-1.0f, (ncx*dx+ncy*dy+ncz*dz)*inv));
            float4* er = reinterpret_cast<float4*>(efs + lane * 8);
            er[0] = make_float4(dx, dy, dz, ndot);
            er[1] = make_float4(cr, cc, cb.z - rb.z, cb.w - rb.w);
        }

        // issue next iteration's gather now (overlaps MMA phases)
        {
            const int nt32 = tb32 + warpsTotal;
            if (nt32 < tiles32) {
                const int e = (nt32 << 5) + lane;
                const bool ev = (e < E);
                int r0 = ev ? rowi[e] : 0;
                int c0 = ev ? coli[e] : 0;
                if ((unsigned)r0 >= (unsigned)N) r0 = 0;
                if ((unsigned)c0 >= (unsigned)N) c0 = 0;
                pr = r0; pc = c0;
                pra = *reinterpret_cast<const float4*>(&g_nodepack[8*r0]);
                prb = *reinterpret_cast<const float4*>(&g_nodepack[8*r0+4]);
                pca = *reinterpret_cast<const float4*>(&g_nodepack[8*c0]);
                pcb = *reinterpret_cast<const float4*>(&g_nodepack[8*c0+4]);
            }
        }
        __syncwarp();

        // ---- Layer 1: tf32 k8 2-term, weight loads shared by both tiles ---
        u32 a4A[4], a4B[4];
        {
            const float* b0 = efs;
            a4A[0] = tf32_of(b0[(g    )*8 + j    ]);
            a4A[1] = tf32_of(b0[(g + 8)*8 + j    ]);
            a4A[2] = tf32_of(b0[(g    )*8 + j + 4]);
            a4A[3] = tf32_of(b0[(g + 8)*8 + j + 4]);
            const float* b1f = efs + 128;
            a4B[0] = tf32_of(b1f[(g    )*8 + j    ]);
            a4B[1] = tf32_of(b1f[(g + 8)*8 + j    ]);
            a4B[2] = tf32_of(b1f[(g    )*8 + j + 4]);
            a4B[3] = tf32_of(b1f[(g + 8)*8 + j + 4]);
        }
        u32 A2[2][4][4];
#pragma unroll
        for (int nt = 0; nt < 8; nt++) {
            const float2 bb = *reinterpret_cast<const float2*>(sb1 + nt * 8 + 2 * j);
            float4 bw = sW1f[nt * 32 + lane];
            u32 bh0 = __float_as_uint(bw.x), bh1 = __float_as_uint(bw.y);
            u32 bl0 = __float_as_uint(bw.z), bl1 = __float_as_uint(bw.w);
            const int s = nt >> 1, half = nt & 1;
#pragma unroll
            for (int t = 0; t < 2; t++) {
                float d0 = bb.x, d1 = bb.y, d2 = bb.x, d3 = bb.y;
                const u32* a4 = t ? a4B : a4A;
                mma_tf32(d0, d1, d2, d3, a4[0], a4[1], a4[2], a4[3], bh0, bh1);
                mma_tf32(d0, d1, d2, d3, a4[0], a4[1], a4[2], a4[3], bl0, bl1);
                A2[t][s][half * 2 + 0] = gelu2_f16(d0, d1, lutp);
                A2[t][s][half * 2 + 1] = gelu2_f16(d2, d3, lutp);
            }
        }

        // ---- Layer 2: fp16 m16n8k16 2-term, shared weight loads ----
        float d2v[2][4][4];
#pragma unroll
        for (int n2 = 0; n2 < 4; n2++) {
            const float2 bb = *reinterpret_cast<const float2*>(sb2 + n2 * 8 + 2 * j);
#pragma unroll
            for (int t = 0; t < 2; t++) {
                d2v[t][n2][0] = bb.x; d2v[t][n2][1] = bb.y;
                d2v[t][n2][2] = bb.x; d2v[t][n2][3] = bb.y;
            }
        }
#pragma unroll
        for (int s = 0; s < 4; s++) {
#pragma unroll
            for (int n2 = 0; n2 < 4; n2++) {
                uint4 bw = sW2h[(s * 4 + n2) * 32 + lane];
#pragma unroll
                for (int t = 0; t < 2; t++) {
                    mma_f16(d2v[t][n2][0], d2v[t][n2][1], d2v[t][n2][2], d2v[t][n2][3],
                            A2[t][s][0], A2[t][s][1], A2[t][s][2], A2[t][s][3],
                            bw.x, bw.y);
                    mma_f16(d2v[t][n2][0], d2v[t][n2][1], d2v[t][n2][2], d2v[t][n2][3],
                            A2[t][s][0], A2[t][s][1], A2[t][s][2], A2[t][s][3],
                            bw.z, bw.w);
                }
            }
        }
        u32 A3[2][2][4];
#pragma unroll
        for (int t = 0; t < 2; t++) {
#pragma unroll
            for (int n2 = 0; n2 < 4; n2++) {
                const int s = n2 >> 1, half = n2 & 1;
                A3[t][s][half * 2 + 0] = gelu2_f16(d2v[t][n2][0], d2v[t][n2][1], lutp);
                A3[t][s][half * 2 + 1] = gelu2_f16(d2v[t][n2][2], d2v[t][n2][3], lutp);
            }
        }

        // ---- Layer 3: fp16 m16n8k16 2-term, shared weight loads ----
        float d3v[2][2][4];
#pragma unroll
        for (int n3 = 0; n3 < 2; n3++) {
            const float2 bb = *reinterpret_cast<const float2*>(sb3 + n3 * 8 + 2 * j);
#pragma unroll
            for (int t = 0; t < 2; t++) {
                d3v[t][n3][0] = bb.x; d3v[t][n3][1] = bb.y;
                d3v[t][n3][2] = bb.x; d3v[t][n3][3] = bb.y;
            }
        }
#pragma unroll
        for (int s = 0; s < 2; s++) {
#pragma unroll
            for (int n3 = 0; n3 < 2; n3++) {
                uint4 bw = sW3h[(s * 2 + n3) * 32 + lane];
#pragma unroll
                for (int t = 0; t < 2; t++) {
                    mma_f16(d3v[t][n3][0], d3v[t][n3][1], d3v[t][n3][2], d3v[t][n3][3],
                            A3[t][s][0], A3[t][s][1], A3[t][s][2], A3[t][s][3],
                            bw.x, bw.y);
                    mma_f16(d3v[t][n3][0], d3v[t][n3][1], d3v[t][n3][2], d3v[t][n3][3],
                            A3[t][s][0], A3[t][s][1], A3[t][s][2], A3[t][s][3],
                            bw.z, bw.w);
                }
            }
        }

        // ---- per-tile epilogue: stats + stage + scatter ----
#pragma unroll
        for (int t = 0; t < 2; t++) {
            const int tb = ebase + t * 16;
            const bool fullTile = (tb + 16 <= E);
#pragma unroll
            for (int n3 = 0; n3 < 2; n3++) {
                const int cb2 = n3 * 8 + 2 * j;
#pragma unroll
                for (int hrow = 0; hrow < 2; hrow++) {
                    float v0 = d3v[t][n3][2*hrow];
                    float v1 = d3v[t][n3][2*hrow + 1];
                    const int rr = g + 8 * hrow;
                    if (fullTile || (tb + rr < E)) {
                        lsum4[n3*2+0] += v0;
                        lsum4[n3*2+1] += v1;
                        lsq4[n3*2+0]   = fmaf(v0, v0, lsq4[n3*2+0]);
                        lsq4[n3*2+1]   = fmaf(v1, v1, lsq4[n3*2+1]);
                    }
                    *reinterpret_cast<float2*>(outs + rr * OUT_PAD + cb2) =
                        make_float2(v0, v1);
                }
            }
            __syncwarp();

            {   // transposed scatter: 4 lanes cover one node's 64B
                const int slot = lane >> 2;
                const int q    = lane & 3;
#pragma unroll
                for (int it = 0; it < 4; it++) {
                    const int rec  = it * 8 + slot;
                    const int le   = rec & 15;
                    const int side = rec >> 4;
                    const int src  = t * 16 + le;
                    const int nr = __shfl_sync(0xffffffffu, r, src);
                    const int nc = __shfl_sync(0xffffffffu, c, src);
                    const int node = side ? nc : nr;
                    if (tb + le < E) {
                        float4 v = outs4[le * 5 + q];
                        atomicAdd(reinterpret_cast<float4*>(
                            &g_node_acc[(size_t)node * 16]) + q, v);
                    }
                }
                const int le = lane & 15;
                const int src = t * 16 + le;
                const int nr = __shfl_sync(0xffffffffu, r, src);
                const int nc = __shfl_sync(0xffffffffu, c, src);
                const int node = (lane < 16) ? nr : nc;
                if (tb + le < E) atomicAdd(&g_degree[node], 1.0f);
            }
            __syncwarp();
        }
    }

    // ---- BN-stat reduction ----
#pragma unroll
    for (int i = 0; i < 4; i++) {
#pragma unroll
        for (int o = 4; o < 32; o <<= 1) {
            lsum4[i] += __shfl_xor_sync(0xffffffffu, lsum4[i], o);
            lsq4[i]  += __shfl_xor_sync(0xffffffffu, lsq4[i],  o);
        }
    }
    if (lane < 4) {
#pragma unroll
        for (int i = 0; i < 4; i++) {
            const int col = (i >> 1) * 8 + 2 * lane + (i & 1);
            atomicAdd(&g_esum[col], (double)lsum4[i]);
            atomicAdd(&g_esq[col],  (double)lsq4[i]);
        }
    }
}

// ---------------------------------------------------------------------------
__global__ void k_ecoef(const float* __restrict__ g, const float* __restrict__ b,
                        int E)
{
    int j = threadIdx.x;
    if (j < 16) {
        double invE = 1.0 / (double)E;
        double m = g_esum[j] * invE;
        double v = g_esq[j] * invE - m * m;
        double s = (double)g[j] / sqrt(v + 1e-5);
        g_es[j] = (float)s;
        g_et[j] = (float)((double)b[j] - m * s);
    }
}

// ---------------------------------------------------------------------------
__global__ __launch_bounds__(256)
void k_node(const float* __restrict__ Wp, const float* __restrict__ bp,
            int N, float* __restrict__ out)
{
    __shared__ float sWp[256], sbp[16], ses[16], set_[16];
    __shared__ float redS[8][16], redQ[8][16];
    if (threadIdx.x < 256) sWp[threadIdx.x] = Wp[threadIdx.x];
    if (threadIdx.x < 16) {
        sbp[threadIdx.x]  = bp[threadIdx.x];
        ses[threadIdx.x]  = g_es[threadIdx.x];
        set_[threadIdx.x] = g_et[threadIdx.x];
    }
    __syncthreads();

    float lsum[16], lsq[16];
#pragma unroll
    for (int k = 0; k < 16; k++) { lsum[k] = 0.0f; lsq[k] = 0.0f; }

    const int n = blockIdx.x * blockDim.x + threadIdx.x;
    if (n < N) {
        const float deg  = g_degree[n];
        const float invd = 1.0f / fmaxf(deg, 1.0f);
        float pre[16];
#pragma unroll
        for (int j = 0; j < 16; j++) {
            const float a = g_node_acc[n * 16 + j];
            pre[j] = (ses[j] * a + set_[j] * deg) * invd;
        }
        float y[16];
#pragma unroll
        for (int k = 0; k < 16; k++) y[k] = sbp[k];
#pragma unroll
        for (int j = 0; j < 16; j++)
#pragma unroll
            for (int k = 0; k < 16; k++) y[k] = fmaf(pre[j], sWp[j*16 + k], y[k]);
#pragma unroll
        for (int k = 0; k < 16; k++) {
            out[n * 16 + k] = y[k];
            lsum[k] = y[k];
            lsq[k]  = y[k] * y[k];
        }
    }

#pragma unroll
    for (int k = 0; k < 16; k++) {
        float s = lsum[k], q = lsq[k];
#pragma unroll
        for (int o = 16; o > 0; o >>= 1) {
            s += __shfl_xor_sync(0xffffffffu, s, o);
            q += __shfl_xor_sync(0xffffffffu, q, o);
        }
        if ((threadIdx.x & 31) == 0) {
            redS[threadIdx.x >> 5][k] = s;
            redQ[threadIdx.x >> 5][k] = q;
        }
    }
    __syncthreads();
    if (threadIdx.x < 16) {
        double s = 0.0, q = 0.0;
#pragma unroll
        for (int w = 0; w < 8; w++) { s += (double)redS[w][threadIdx.x];
                                      q += (double)redQ[w][threadIdx.x]; }
        atomicAdd(&g_nsum[threadIdx.x], s);
        atomicAdd(&g_nsq[threadIdx.x],  q);
    }
}

// ---------------------------------------------------------------------------
__global__ void k_ncoef(const float* __restrict__ g, const float* __restrict__ b,
                        int N)
{
    int j = threadIdx.x;
    if (j < 16) {
        double invN = 1.0 / (double)N;
        double m = g_nsum[j] * invN;
        double v = g_nsq[j] * invN - m * m;
        double s = (double)g[j] / sqrt(v + 1e-5);
        g_ns[j] = (float)s;
        g_nt[j] = (float)((double)b[j] - m * s);
    }
}

// ---------------------------------------------------------------------------
__global__ void k_norm(float* __restrict__ out, int total)
{
    int i = blockIdx.x * blockDim.x + threadIdx.x;
    if (i < total) {
        int j = i & 15;
        out[i] = fmaf(out[i], g_ns[j], g_nt[j]);
    }
}

// ---------------------------------------------------------------------------
extern "C" void kernel_launch(void* const* d_in, const int* in_sizes, int n_in,
                              void* d_out, int out_size)
{
    const float* coords  = (const float*)d_in[0];
    const float* normals = (const float*)d_in[1];
    const float* curv    = (const float*)d_in[2];
    const int*   ei      = (const int*)d_in[3];
    const float* W1 = (const float*)d_in[4];
    const float* b1 = (const float*)d_in[5];
    const float* W2 = (const float*)d_in[6];
    const float* b2 = (const float*)d_in[7];
    const float* W3 = (const float*)d_in[8];
    const float* b3 = (const float*)d_in[9];
    const float* Wp = (const float*)d_in[10];
    const float* bp = (const float*)d_in[11];
    const float* beg = (const float*)d_in[12];
    const float* beb = (const float*)d_in[13];
    const float* bng = (const float*)d_in[14];
    const float* bnb = (const float*)d_in[15];

    const int N = in_sizes[0] / 3;
    const int E = in_sizes[3] / 2;
    const int* row = ei;
    const int* col = ei + E;
    float* out = (float*)d_out;

    const int smemBytes = (OFF_WARP + NWARP * WARP_FLOATS) * 4;  // ~94.2 KB
    static bool attrSet = false;
    if (!attrSet) {
        cudaFuncSetAttribute(k_edge, cudaFuncAttributeMaxDynamicSharedMemorySize,
                             smemBytes);
        attrSet = true;
    }

    k_zero<<<(N * 16 + 255) / 256, 256>>>(N);                       // launch 1
    k_pack<<<(N + 255) / 256, 256>>>(coords, normals, curv, N);     // launch 2
    k_dummy<<<1, 32>>>();                                           // launch 3
    k_edge<<<296, NTHR, smemBytes>>>(row, col, W1, b1, W2, b2,      // launch 4
                                     W3, b3, E, N);
    k_ecoef<<<1, 32>>>(beg, beb, E);
    k_node<<<(N + 255) / 256, 256>>>(Wp, bp, N, out);
    k_ncoef<<<1, 32>>>(bng, bnb, N);
    k_norm<<<(N * 16 + 255) / 256, 256>>>(out, N * 16);
}